// round 1
// baseline (speedup 1.0000x reference)
#include <cuda_runtime.h>
#include <math.h>

#define BATCH 256
#define NTOK 197
#define CDIM 768
#define HEADS 12
#define DH 64
#define GRID14 14
#define M_ROWS (BATCH * NTOK)   /* 50432, divisible by 128 */
#define QKV_N (3 * CDIM)        /* 2304 */
#define KSTRIDE 68              /* 16B-aligned, conflict-free padded row stride */

/* Scratch (allocation-free rule: __device__ globals) */
__device__ float g_qkv[(size_t)M_ROWS * QKV_N];   /* ~465 MB: (B*N, 3C) as (s,h,d) cols */
__device__ float g_att[(size_t)M_ROWS * CDIM];    /* ~155 MB: attention + conv result   */

/* ------------------------------------------------------------------ */
/* Classic 128x128x8 fp32 GEMM, C = A*B + bias.  M%128==N%128==K%8==0 */
/* ------------------------------------------------------------------ */
__global__ __launch_bounds__(256) void sgemm_bias(
    const float* __restrict__ A, const float* __restrict__ B,
    const float* __restrict__ bias, float* __restrict__ C,
    int M, int N, int K)
{
    __shared__ float As[8][128];
    __shared__ float Bs[8][128];
    const int tid = threadIdx.x;
    const int bm = blockIdx.y * 128;
    const int bn = blockIdx.x * 128;
    const int arow = tid >> 1;
    const int acol = (tid & 1) * 4;
    const int brow = tid >> 5;
    const int bcol = (tid & 31) * 4;
    const int tx = (tid & 15) * 8;
    const int ty = (tid >> 4) * 8;

    const float* Ap = A + (size_t)(bm + arow) * K + acol;
    const float* Bp = B + (size_t)brow * N + bn + bcol;

    float acc[8][8];
#pragma unroll
    for (int i = 0; i < 8; i++)
#pragma unroll
        for (int j = 0; j < 8; j++) acc[i][j] = 0.f;

    for (int k0 = 0; k0 < K; k0 += 8) {
        float4 a = *(const float4*)Ap;
        float4 b = *(const float4*)Bp;
        As[acol + 0][arow] = a.x;
        As[acol + 1][arow] = a.y;
        As[acol + 2][arow] = a.z;
        As[acol + 3][arow] = a.w;
        *(float4*)&Bs[brow][bcol] = b;
        __syncthreads();
#pragma unroll
        for (int kk = 0; kk < 8; kk++) {
            float ar[8], br[8];
            *(float4*)&ar[0] = *(const float4*)&As[kk][ty];
            *(float4*)&ar[4] = *(const float4*)&As[kk][ty + 4];
            *(float4*)&br[0] = *(const float4*)&Bs[kk][tx];
            *(float4*)&br[4] = *(const float4*)&Bs[kk][tx + 4];
#pragma unroll
            for (int i = 0; i < 8; i++)
#pragma unroll
                for (int j = 0; j < 8; j++)
                    acc[i][j] = fmaf(ar[i], br[j], acc[i][j]);
        }
        __syncthreads();
        Ap += 8;
        Bp += (size_t)8 * N;
    }
#pragma unroll
    for (int i = 0; i < 8; i++) {
        float* Cp = C + (size_t)(bm + ty + i) * N + bn + tx;
#pragma unroll
        for (int j = 0; j < 8; j++)
            Cp[j] = acc[i][j] + bias[bn + tx + j];
    }
}

/* ------------------------------------------------------------------ */
/* Attention: one block per (b,h). K,V staged in smem; warp-per-row.  */
/* qkv layout: row r=(b*197+n), col = s*768 + h*64 + d                */
/* ------------------------------------------------------------------ */
#define SMEM_ATTN ((2 * NTOK * KSTRIDE + 8 * 200) * (int)sizeof(float))

__global__ __launch_bounds__(256) void attn_kernel(const float* __restrict__ qkv,
                                                   float* __restrict__ out)
{
    const int bh = blockIdx.x;
    const int b = bh / HEADS;
    const int h = bh % HEADS;
    extern __shared__ float sm[];
    float* Ks = sm;                        /* 197 x 68 */
    float* Vs = Ks + NTOK * KSTRIDE;       /* 197 x 68 */
    float* Ps = Vs + NTOK * KSTRIDE;       /* 8 warps x 200 */
    const int tid = threadIdx.x;
    const float* base = qkv + (size_t)b * NTOK * QKV_N + h * DH;

    for (int idx = tid; idx < NTOK * DH; idx += 256) {
        int j = idx >> 6;
        int d = idx & 63;
        const float* src = base + (size_t)j * QKV_N + d;
        Ks[j * KSTRIDE + d] = src[CDIM];
        Vs[j * KSTRIDE + d] = src[2 * CDIM];
    }
    __syncthreads();

    const int warp = tid >> 5, lane = tid & 31;
    float* pw = Ps + warp * 200;

    for (int row = warp; row < NTOK; row += 8) {
        float4 q[16];
        const float* qr = base + (size_t)row * QKV_N;
#pragma unroll
        for (int i = 0; i < 16; i++) q[i] = *(const float4*)(qr + i * 4);

        float s[7];
        float mx = -1e30f;
#pragma unroll
        for (int it = 0; it < 7; it++) {
            int j = lane + it * 32;
            float acc = -1e30f;
            if (j < NTOK) {
                const float* kr = Ks + j * KSTRIDE;
                float a = 0.f;
#pragma unroll
                for (int i = 0; i < 16; i++) {
                    float4 k4 = *(const float4*)(kr + i * 4);
                    a = fmaf(q[i].x, k4.x, a);
                    a = fmaf(q[i].y, k4.y, a);
                    a = fmaf(q[i].z, k4.z, a);
                    a = fmaf(q[i].w, k4.w, a);
                }
                acc = a * 0.125f;
            }
            s[it] = acc;
            mx = fmaxf(mx, acc);
        }
#pragma unroll
        for (int o = 16; o > 0; o >>= 1)
            mx = fmaxf(mx, __shfl_xor_sync(0xffffffffu, mx, o));
        float sum = 0.f;
#pragma unroll
        for (int it = 0; it < 7; it++) {
            int j = lane + it * 32;
            float e = (j < NTOK) ? __expf(s[it] - mx) : 0.f;
            s[it] = e;
            sum += e;
        }
#pragma unroll
        for (int o = 16; o > 0; o >>= 1)
            sum += __shfl_xor_sync(0xffffffffu, sum, o);
        float inv = __frcp_rn(sum);
#pragma unroll
        for (int it = 0; it < 7; it++) {
            int j = lane + it * 32;
            if (j < NTOK) pw[j] = s[it] * inv;
        }
        __syncwarp();

        float o0 = 0.f, o1 = 0.f;
        for (int j = 0; j < NTOK; j++) {
            float p = pw[j];
            o0 = fmaf(p, Vs[j * KSTRIDE + lane], o0);
            o1 = fmaf(p, Vs[j * KSTRIDE + lane + 32], o1);
        }
        float* op = out + (size_t)(b * NTOK + row) * CDIM + h * DH + lane;
        op[0] = o0;
        op[32] = o1;
        __syncwarp();   /* all lanes done reading pw before next row rewrites it */
    }
}

/* ------------------------------------------------------------------ */
/* Depthwise 3x3 conv on V (tokens 1..196 as 14x14), += into out.     */
/* One thread per (b, y, x, c); total 256*196*768 = 150528*256.       */
/* ------------------------------------------------------------------ */
__global__ __launch_bounds__(256) void dwconv_add(const float* __restrict__ qkv,
                                                  const float* __restrict__ w,
                                                  const float* __restrict__ bias,
                                                  float* __restrict__ out)
{
    int idx = blockIdx.x * 256 + threadIdx.x;
    int c = idx % CDIM;
    int r = idx / CDIM;
    int x = r % GRID14; r /= GRID14;
    int y = r % GRID14;
    int b = r / GRID14;

    const float* vbase = qkv + (size_t)b * NTOK * QKV_N + 2 * CDIM + c;
    const float* wc = w + c * 9;
    float acc = bias[c];
#pragma unroll
    for (int ky = 0; ky < 3; ky++) {
        int yy = y + ky - 1;
        if (yy < 0 || yy >= GRID14) continue;
#pragma unroll
        for (int kx = 0; kx < 3; kx++) {
            int xx = x + kx - 1;
            if (xx < 0 || xx >= GRID14) continue;
            acc = fmaf(vbase[(size_t)(1 + yy * GRID14 + xx) * QKV_N], wc[ky * 3 + kx], acc);
        }
    }
    out[(size_t)(b * NTOK + 1 + y * GRID14 + x) * CDIM + c] += acc;
}

/* ------------------------------------------------------------------ */
extern "C" void kernel_launch(void* const* d_in, const int* in_sizes, int n_in,
                              void* d_out, int out_size)
{
    const float* x      = (const float*)d_in[0];
    const float* W_qkv  = (const float*)d_in[1];
    const float* b_qkv  = (const float*)d_in[2];
    const float* W_proj = (const float*)d_in[3];
    const float* b_proj = (const float*)d_in[4];
    const float* dwc_w  = (const float*)d_in[5];
    const float* dwc_b  = (const float*)d_in[6];
    float* out = (float*)d_out;

    float* qkv = nullptr;
    float* att = nullptr;
    cudaGetSymbolAddress((void**)&qkv, g_qkv);
    cudaGetSymbolAddress((void**)&att, g_att);

    cudaFuncSetAttribute(attn_kernel, cudaFuncAttributeMaxDynamicSharedMemorySize, SMEM_ATTN);

    /* 1) qkv = x @ W_qkv + b_qkv */
    dim3 g1(QKV_N / 128, M_ROWS / 128);
    sgemm_bias<<<g1, 256>>>(x, W_qkv, b_qkv, qkv, M_ROWS, QKV_N, CDIM);

    /* 2) attention -> g_att */
    attn_kernel<<<BATCH * HEADS, 256, SMEM_ATTN>>>(qkv, att);

    /* 3) depthwise conv on V, += into g_att rows 1..196 */
    dwconv_add<<<(BATCH * (NTOK - 1) * CDIM) / 256, 256>>>(qkv, dwc_w, dwc_b, att);

    /* 4) out = g_att @ W_proj + b_proj */
    dim3 g2(CDIM / 128, M_ROWS / 128);
    sgemm_bias<<<g2, 256>>>(att, W_proj, b_proj, out, M_ROWS, CDIM, CDIM);
}

// round 3
// speedup vs baseline: 1.7493x; 1.7493x over previous
#include <cuda_runtime.h>
#include <cuda_bf16.h>
#include <cstdint>
#include <math.h>

#define BATCH 256
#define NTOK 197
#define CDIM 768
#define HEADS 12
#define DH 64
#define GRID14 14
#define M_ROWS (BATCH * NTOK)   /* 50432 = 394*128 */
#define QKV_N (3 * CDIM)        /* 2304 */
#define KSTRIDE 68
#define KTOT 768
#define KSPLIT (2 * KTOT)       /* 1536 bf16 per row, per-32-chunk [hi|lo] packing */
#define ROWB (KSPLIT * 2)       /* 3072 bytes per packed row */

/* ---------------- scratch (__device__ globals; no allocs allowed) -------- */
__device__ float g_qkv[(size_t)M_ROWS * QKV_N];
__device__ float g_att[(size_t)M_ROWS * CDIM];
__device__ __nv_bfloat16 g_xs[(size_t)M_ROWS * KSPLIT];
__device__ __nv_bfloat16 g_atts[(size_t)M_ROWS * KSPLIT];
__device__ __nv_bfloat16 g_wqkvs[(size_t)QKV_N * KSPLIT];
__device__ __nv_bfloat16 g_wprojs[(size_t)CDIM * KSPLIT];

/* ---------------- helpers ------------------------------------------------- */
__device__ __forceinline__ uint32_t smem_u32(const void* p) {
    uint32_t a;
    asm("{ .reg .u64 t; cvta.to.shared.u64 t, %1; cvt.u32.u64 %0, t; }" : "=r"(a) : "l"(p));
    return a;
}
__device__ __forceinline__ uint32_t sw128(uint32_t o) { return o ^ ((o >> 3) & 0x70); }

__device__ __forceinline__ void cp16(uint32_t s, const void* g) {
    asm volatile("cp.async.cg.shared.global [%0], [%1], 16;" :: "r"(s), "l"(g));
}
__device__ __forceinline__ void ldm_x4(uint32_t* r, uint32_t a) {
    asm volatile("ldmatrix.sync.aligned.m8n8.x4.shared.b16 {%0,%1,%2,%3}, [%4];"
                 : "=r"(r[0]), "=r"(r[1]), "=r"(r[2]), "=r"(r[3]) : "r"(a));
}
__device__ __forceinline__ void mma16816(float* c, const uint32_t* a, const uint32_t* b) {
    asm volatile(
        "mma.sync.aligned.m16n8k16.row.col.f32.bf16.bf16.f32 "
        "{%0,%1,%2,%3}, {%4,%5,%6,%7}, {%8,%9}, {%0,%1,%2,%3};"
        : "+f"(c[0]), "+f"(c[1]), "+f"(c[2]), "+f"(c[3])
        : "r"(a[0]), "r"(a[1]), "r"(a[2]), "r"(a[3]), "r"(b[0]), "r"(b[1]));
}

/* ---------------- hi/lo split prep ---------------------------------------- */
__global__ __launch_bounds__(256) void split_rows(const float* __restrict__ in,
                                                  __nv_bfloat16* __restrict__ out, int total)
{
    int idx = blockIdx.x * 256 + threadIdx.x;
    if (idx >= total) return;
    int r = idx / KTOT, k = idx % KTOT;
    float a = in[idx];
    __nv_bfloat16 hi = __float2bfloat16(a);
    __nv_bfloat16 lo = __float2bfloat16(a - __bfloat162float(hi));
    size_t o = (size_t)r * KSPLIT + ((k >> 5) << 6) + (k & 31);
    out[o] = hi;
    out[o + 32] = lo;
}

__global__ __launch_bounds__(256) void wsplit(const float* __restrict__ W,
                                              __nv_bfloat16* __restrict__ out,
                                              int N, int total)
{
    int idx = blockIdx.x * 256 + threadIdx.x;
    if (idx >= total) return;
    int n = idx / KTOT, k = idx % KTOT;
    float a = W[(size_t)k * N + n];
    __nv_bfloat16 hi = __float2bfloat16(a);
    __nv_bfloat16 lo = __float2bfloat16(a - __bfloat162float(hi));
    size_t o = (size_t)n * KSPLIT + ((k >> 5) << 6) + (k & 31);
    out[o] = hi;
    out[o + 32] = lo;
}

/* ---------------- mma.sync bf16x3 GEMM ------------------------------------ */
/* C[M, Nd] = A*B^T + bias.  A split [M,1536] bf16, B split [Nd,1536] bf16.  */
/* CTA tile 128x256, 8 warps (2x4), warp tile 64x64, 2-stage cp.async.      */
#define TM 128
#define TN 256
#define NSTG 24
#define CH_A 16384                /* 128 rows * 128B */
#define CH_B 32768                /* 256 rows * 128B */
#define STG (CH_A + CH_B)         /* 49152 */
#define GSMEM (2 * STG)           /* 98304 */

__device__ __forceinline__ void load_stage(uint32_t sb, int buf, int st,
                                           const char* Ag, const char* Bg, int tid)
{
    uint32_t ab = sb + buf * STG;
    const char* a0 = Ag + (size_t)st * 128;
#pragma unroll
    for (int c = tid; c < 1024; c += 256) {
        int r = c >> 3, j = c & 7;
        cp16(ab + sw128(r * 128 + j * 16), a0 + (size_t)r * ROWB + j * 16);
    }
    uint32_t bb = ab + CH_A;
    const char* b0 = Bg + (size_t)st * 128;
#pragma unroll
    for (int c = tid; c < 2048; c += 256) {
        int r = c >> 3, j = c & 7;
        cp16(bb + sw128(r * 128 + j * 16), b0 + (size_t)r * ROWB + j * 16);
    }
    asm volatile("cp.async.commit_group;" ::: "memory");
}

__global__ __launch_bounds__(256, 1) void gemm_mma(
    const __nv_bfloat16* __restrict__ As, const __nv_bfloat16* __restrict__ Bs,
    const float* __restrict__ bias, float* __restrict__ C, int Nd)
{
    extern __shared__ __align__(1024) char smc[];
    uint32_t sb = smem_u32(smc);
    const int tid = threadIdx.x;
    const size_t bm = (size_t)blockIdx.y * TM;
    const size_t bn = (size_t)blockIdx.x * TN;
    const char* Ag = (const char*)As + bm * ROWB;
    const char* Bg = (const char*)Bs + bn * ROWB;

    load_stage(sb, 0, 0, Ag, Bg, tid);
    load_stage(sb, 1, 1, Ag, Bg, tid);

    const int warp = tid >> 5, lane = tid & 31;
    const int wm = (warp >> 2) * 64;    /* warp row origin in tile   */
    const int wn = (warp & 3) * 64;     /* warp col origin in tile   */

    float acc[4][8][4];
#pragma unroll
    for (int i = 0; i < 4; i++)
#pragma unroll
        for (int j = 0; j < 8; j++)
#pragma unroll
            for (int q = 0; q < 4; q++) acc[i][j][q] = 0.f;

    /* A-lane addressing: row = (lane&15), kbyte += (lane>>4)*16           */
    const int a_r = lane & 15;
    const int a_c = (lane >> 4) << 4;
    /* B-lane (x4 over n16): nrow = (lane&7)+((lane>>4)<<3), kb += ((lane>>3)&1)*16 */
    const int b_r = (lane & 7) + ((lane >> 4) << 3);
    const int b_c = ((lane >> 3) & 1) << 4;

    /* 3-term product schedule inside each 128B [hi(64B)|lo(64B)] chunk     */
    const int akb[6] = {0, 32, 0, 32, 64, 96};
    const int bkb[6] = {0, 32, 64, 96, 0, 32};

    for (int s = 0; s < NSTG; s++) {
        const int buf = s & 1;
        if (s + 2 < NSTG) asm volatile("cp.async.wait_group 1;" ::: "memory");
        else              asm volatile("cp.async.wait_group 0;" ::: "memory");
        __syncthreads();

        uint32_t ab = sb + buf * STG;
        uint32_t bb = ab + CH_A;

#pragma unroll
        for (int ks = 0; ks < 6; ks++) {
            uint32_t ar[4][4];
#pragma unroll
            for (int i = 0; i < 4; i++) {
                int row = wm + i * 16 + a_r;
                ldm_x4(ar[i], ab + sw128(row * 128 + akb[ks] + a_c));
            }
            uint32_t br[4][4];
#pragma unroll
            for (int j = 0; j < 4; j++) {
                int row = wn + j * 16 + b_r;
                ldm_x4(br[j], bb + sw128(row * 128 + bkb[ks] + b_c));
            }
#pragma unroll
            for (int i = 0; i < 4; i++)
#pragma unroll
                for (int j = 0; j < 4; j++) {
                    mma16816(acc[i][2 * j + 0], ar[i], &br[j][0]);
                    mma16816(acc[i][2 * j + 1], ar[i], &br[j][2]);
                }
        }
        __syncthreads();
        if (s + 2 < NSTG) load_stage(sb, buf, s + 2, Ag, Bg, tid);
    }

    /* epilogue: lane l -> rows r0=l/4 (+8), cols c0=(l%3..)*2 per ntile    */
    const int r0 = lane >> 2;
    const int c0 = (lane & 3) * 2;
    const size_t grow = bm + wm + r0;
    const int gcol = (int)bn + wn + c0;

    float2 bv[8];
#pragma unroll
    for (int j = 0; j < 8; j++)
        bv[j] = *(const float2*)(bias + gcol + j * 8);

#pragma unroll
    for (int i = 0; i < 4; i++) {
        float* cp0 = C + (grow + i * 16) * Nd + gcol;
        float* cp1 = cp0 + (size_t)8 * Nd;
#pragma unroll
        for (int j = 0; j < 8; j++) {
            float2 v0 = make_float2(acc[i][j][0] + bv[j].x, acc[i][j][1] + bv[j].y);
            float2 v1 = make_float2(acc[i][j][2] + bv[j].x, acc[i][j][3] + bv[j].y);
            *(float2*)(cp0 + j * 8) = v0;
            *(float2*)(cp1 + j * 8) = v1;
        }
    }
}

/* ---------------- attention (unchanged, passing, fp32) --------------------- */
#define SMEM_ATTN ((2 * NTOK * KSTRIDE + 8 * 200) * (int)sizeof(float))

__global__ __launch_bounds__(256) void attn_kernel(const float* __restrict__ qkv,
                                                   float* __restrict__ out)
{
    const int bh = blockIdx.x;
    const int b = bh / HEADS;
    const int h = bh % HEADS;
    extern __shared__ float sm[];
    float* Ks = sm;
    float* Vs = Ks + NTOK * KSTRIDE;
    float* Ps = Vs + NTOK * KSTRIDE;
    const int tid = threadIdx.x;
    const float* base = qkv + (size_t)b * NTOK * QKV_N + h * DH;

    for (int idx = tid; idx < NTOK * DH; idx += 256) {
        int j = idx >> 6;
        int d = idx & 63;
        const float* src = base + (size_t)j * QKV_N + d;
        Ks[j * KSTRIDE + d] = src[CDIM];
        Vs[j * KSTRIDE + d] = src[2 * CDIM];
    }
    __syncthreads();

    const int warp = tid >> 5, lane = tid & 31;
    float* pw = Ps + warp * 200;

    for (int row = warp; row < NTOK; row += 8) {
        float4 q[16];
        const float* qr = base + (size_t)row * QKV_N;
#pragma unroll
        for (int i = 0; i < 16; i++) q[i] = *(const float4*)(qr + i * 4);

        float s[7];
        float mx = -1e30f;
#pragma unroll
        for (int it = 0; it < 7; it++) {
            int j = lane + it * 32;
            float a2 = -1e30f;
            if (j < NTOK) {
                const float* kr = Ks + j * KSTRIDE;
                float a = 0.f;
#pragma unroll
                for (int i = 0; i < 16; i++) {
                    float4 k4 = *(const float4*)(kr + i * 4);
                    a = fmaf(q[i].x, k4.x, a);
                    a = fmaf(q[i].y, k4.y, a);
                    a = fmaf(q[i].z, k4.z, a);
                    a = fmaf(q[i].w, k4.w, a);
                }
                a2 = a * 0.125f;
            }
            s[it] = a2;
            mx = fmaxf(mx, a2);
        }
#pragma unroll
        for (int o = 16; o > 0; o >>= 1)
            mx = fmaxf(mx, __shfl_xor_sync(0xffffffffu, mx, o));
        float sum = 0.f;
#pragma unroll
        for (int it = 0; it < 7; it++) {
            int j = lane + it * 32;
            float e = (j < NTOK) ? __expf(s[it] - mx) : 0.f;
            s[it] = e;
            sum += e;
        }
#pragma unroll
        for (int o = 16; o > 0; o >>= 1)
            sum += __shfl_xor_sync(0xffffffffu, sum, o);
        float inv = __frcp_rn(sum);
#pragma unroll
        for (int it = 0; it < 7; it++) {
            int j = lane + it * 32;
            if (j < NTOK) pw[j] = s[it] * inv;
        }
        __syncwarp();

        float o0 = 0.f, o1 = 0.f;
        for (int j = 0; j < NTOK; j++) {
            float p = pw[j];
            o0 = fmaf(p, Vs[j * KSTRIDE + lane], o0);
            o1 = fmaf(p, Vs[j * KSTRIDE + lane + 32], o1);
        }
        float* op = out + (size_t)(b * NTOK + row) * CDIM + h * DH + lane;
        op[0] = o0;
        op[32] = o1;
        __syncwarp();
    }
}

/* ---------------- depthwise 3x3 conv (unchanged) -------------------------- */
__global__ __launch_bounds__(256) void dwconv_add(const float* __restrict__ qkv,
                                                  const float* __restrict__ w,
                                                  const float* __restrict__ bias,
                                                  float* __restrict__ out)
{
    int idx = blockIdx.x * 256 + threadIdx.x;
    int c = idx % CDIM;
    int r = idx / CDIM;
    int x = r % GRID14; r /= GRID14;
    int y = r % GRID14;
    int b = r / GRID14;

    const float* vbase = qkv + (size_t)b * NTOK * QKV_N + 2 * CDIM + c;
    const float* wc = w + c * 9;
    float acc = bias[c];
#pragma unroll
    for (int ky = 0; ky < 3; ky++) {
        int yy = y + ky - 1;
        if (yy < 0 || yy >= GRID14) continue;
#pragma unroll
        for (int kx = 0; kx < 3; kx++) {
            int xx = x + kx - 1;
            if (xx < 0 || xx >= GRID14) continue;
            acc = fmaf(vbase[(size_t)(1 + yy * GRID14 + xx) * QKV_N], wc[ky * 3 + kx], acc);
        }
    }
    out[(size_t)(b * NTOK + 1 + y * GRID14 + x) * CDIM + c] += acc;
}

/* ---------------- launch --------------------------------------------------- */
extern "C" void kernel_launch(void* const* d_in, const int* in_sizes, int n_in,
                              void* d_out, int out_size)
{
    const float* x      = (const float*)d_in[0];
    const float* W_qkv  = (const float*)d_in[1];
    const float* b_qkv  = (const float*)d_in[2];
    const float* W_proj = (const float*)d_in[3];
    const float* b_proj = (const float*)d_in[4];
    const float* dwc_w  = (const float*)d_in[5];
    const float* dwc_b  = (const float*)d_in[6];
    float* out = (float*)d_out;

    float *qkv = nullptr, *att = nullptr;
    __nv_bfloat16 *xs = nullptr, *atts = nullptr, *wqkvs = nullptr, *wprojs = nullptr;
    cudaGetSymbolAddress((void**)&qkv, g_qkv);
    cudaGetSymbolAddress((void**)&att, g_att);
    cudaGetSymbolAddress((void**)&xs, g_xs);
    cudaGetSymbolAddress((void**)&atts, g_atts);
    cudaGetSymbolAddress((void**)&wqkvs, g_wqkvs);
    cudaGetSymbolAddress((void**)&wprojs, g_wprojs);

    cudaFuncSetAttribute(attn_kernel, cudaFuncAttributeMaxDynamicSharedMemorySize, SMEM_ATTN);
    cudaFuncSetAttribute(gemm_mma, cudaFuncAttributeMaxDynamicSharedMemorySize, GSMEM);

    /* prep: hi/lo splits */
    split_rows<<<(M_ROWS * KTOT) / 256, 256>>>(x, xs, M_ROWS * KTOT);
    wsplit<<<(QKV_N * KTOT) / 256, 256>>>(W_qkv, wqkvs, QKV_N, QKV_N * KTOT);
    wsplit<<<(CDIM * KTOT) / 256, 256>>>(W_proj, wprojs, CDIM, CDIM * KTOT);

    /* 1) qkv = x @ W_qkv + b_qkv */
    gemm_mma<<<dim3(QKV_N / TN, M_ROWS / TM), 256, GSMEM>>>(xs, wqkvs, b_qkv, qkv, QKV_N);

    /* 2) attention -> g_att */
    attn_kernel<<<BATCH * HEADS, 256, SMEM_ATTN>>>(qkv, att);

    /* 3) depthwise conv on V, += into g_att rows 1..196 */
    dwconv_add<<<(BATCH * (NTOK - 1) * CDIM) / 256, 256>>>(qkv, dwc_w, dwc_b, att);

    /* 4) split attention output, then out = g_att @ W_proj + b_proj */
    split_rows<<<(M_ROWS * KTOT) / 256, 256>>>(att, atts, M_ROWS * KTOT);
    gemm_mma<<<dim3(CDIM / TN, M_ROWS / TM), 256, GSMEM>>>(atts, wprojs, b_proj, out, CDIM);
}

// round 4
// speedup vs baseline: 3.0361x; 1.7356x over previous
#include <cuda_runtime.h>
#include <cuda_bf16.h>
#include <cstdint>
#include <math.h>

#define BATCH 256
#define NTOK 197
#define CDIM 768
#define HEADS 12
#define DH 64
#define GRID14 14
#define M_ROWS (BATCH * NTOK)   /* 50432 = 394*128 */
#define QKV_N (3 * CDIM)        /* 2304 */
#define KTOT 768
#define KSPLIT (2 * KTOT)       /* 1536 bf16 per row, per-32-chunk [hi|lo] packing */
#define ROWB (KSPLIT * 2)       /* 3072 bytes per packed row */

/* ---------------- scratch (__device__ globals; no allocs allowed) -------- */
__device__ float g_qkv[(size_t)M_ROWS * QKV_N];
__device__ float g_att[(size_t)M_ROWS * CDIM];
__device__ __nv_bfloat16 g_xs[(size_t)M_ROWS * KSPLIT];
__device__ __nv_bfloat16 g_atts[(size_t)M_ROWS * KSPLIT];
__device__ __nv_bfloat16 g_wqkvs[(size_t)QKV_N * KSPLIT];
__device__ __nv_bfloat16 g_wprojs[(size_t)CDIM * KSPLIT];

/* ---------------- helpers ------------------------------------------------- */
__device__ __forceinline__ uint32_t smem_u32(const void* p) {
    uint32_t a;
    asm("{ .reg .u64 t; cvta.to.shared.u64 t, %1; cvt.u32.u64 %0, t; }" : "=r"(a) : "l"(p));
    return a;
}
__device__ __forceinline__ uint32_t sw128(uint32_t o) { return o ^ ((o >> 3) & 0x70); }

__device__ __forceinline__ void cp16(uint32_t s, const void* g) {
    asm volatile("cp.async.cg.shared.global [%0], [%1], 16;" :: "r"(s), "l"(g));
}
__device__ __forceinline__ void ldm_x4(uint32_t* r, uint32_t a) {
    asm volatile("ldmatrix.sync.aligned.m8n8.x4.shared.b16 {%0,%1,%2,%3}, [%4];"
                 : "=r"(r[0]), "=r"(r[1]), "=r"(r[2]), "=r"(r[3]) : "r"(a));
}
__device__ __forceinline__ void ldm_x4t(uint32_t* r, uint32_t a) {
    asm volatile("ldmatrix.sync.aligned.m8n8.x4.trans.shared.b16 {%0,%1,%2,%3}, [%4];"
                 : "=r"(r[0]), "=r"(r[1]), "=r"(r[2]), "=r"(r[3]) : "r"(a));
}
__device__ __forceinline__ void mma16816(float* c, const uint32_t* a, const uint32_t* b) {
    asm volatile(
        "mma.sync.aligned.m16n8k16.row.col.f32.bf16.bf16.f32 "
        "{%0,%1,%2,%3}, {%4,%5,%6,%7}, {%8,%9}, {%0,%1,%2,%3};"
        : "+f"(c[0]), "+f"(c[1]), "+f"(c[2]), "+f"(c[3])
        : "r"(a[0]), "r"(a[1]), "r"(a[2]), "r"(a[3]), "r"(b[0]), "r"(b[1]));
}
/* split two floats into packed bf16 hi-pair and lo-pair (low half = first) */
__device__ __forceinline__ void fsplit2(float x, float y, uint32_t& hi, uint32_t& lo) {
    __nv_bfloat16 hx = __float2bfloat16_rn(x), hy = __float2bfloat16_rn(y);
    __nv_bfloat16 lx = __float2bfloat16_rn(x - __bfloat162float(hx));
    __nv_bfloat16 ly = __float2bfloat16_rn(y - __bfloat162float(hy));
    __nv_bfloat162 th; th.x = hx; th.y = hy;
    __nv_bfloat162 tl; tl.x = lx; tl.y = ly;
    hi = *reinterpret_cast<uint32_t*>(&th);
    lo = *reinterpret_cast<uint32_t*>(&tl);
}

/* ---------------- hi/lo split prep ---------------------------------------- */
__global__ __launch_bounds__(256) void split_rows(const float* __restrict__ in,
                                                  __nv_bfloat16* __restrict__ out, int total)
{
    int idx = blockIdx.x * 256 + threadIdx.x;
    if (idx >= total) return;
    int r = idx / KTOT, k = idx % KTOT;
    float a = in[idx];
    __nv_bfloat16 hi = __float2bfloat16(a);
    __nv_bfloat16 lo = __float2bfloat16(a - __bfloat162float(hi));
    size_t o = (size_t)r * KSPLIT + ((k >> 5) << 6) + (k & 31);
    out[o] = hi;
    out[o + 32] = lo;
}

__global__ __launch_bounds__(256) void wsplit(const float* __restrict__ W,
                                              __nv_bfloat16* __restrict__ out,
                                              int N, int total)
{
    int idx = blockIdx.x * 256 + threadIdx.x;
    if (idx >= total) return;
    int n = idx / KTOT, k = idx % KTOT;
    float a = W[(size_t)k * N + n];
    __nv_bfloat16 hi = __float2bfloat16(a);
    __nv_bfloat16 lo = __float2bfloat16(a - __bfloat162float(hi));
    size_t o = (size_t)n * KSPLIT + ((k >> 5) << 6) + (k & 31);
    out[o] = hi;
    out[o + 32] = lo;
}

/* ---------------- mma.sync bf16x3 GEMM, 4-stage pipeline ------------------ */
#define TM 128
#define TN 256
#define NSTG 24
#define CH_A 16384
#define CH_B 32768
#define STG (CH_A + CH_B)         /* 49152 */
#define GSMEM (4 * STG)           /* 196608 */

__device__ __forceinline__ void load_stage(uint32_t sb, int buf, int st,
                                           const char* Ag, const char* Bg, int tid)
{
    uint32_t ab = sb + buf * STG;
    const char* a0 = Ag + (size_t)st * 128;
#pragma unroll
    for (int c = tid; c < 1024; c += 256) {
        int r = c >> 3, j = c & 7;
        cp16(ab + sw128(r * 128 + j * 16), a0 + (size_t)r * ROWB + j * 16);
    }
    uint32_t bb = ab + CH_A;
    const char* b0 = Bg + (size_t)st * 128;
#pragma unroll
    for (int c = tid; c < 2048; c += 256) {
        int r = c >> 3, j = c & 7;
        cp16(bb + sw128(r * 128 + j * 16), b0 + (size_t)r * ROWB + j * 16);
    }
    asm volatile("cp.async.commit_group;" ::: "memory");
}

__global__ __launch_bounds__(256, 1) void gemm_mma(
    const __nv_bfloat16* __restrict__ As, const __nv_bfloat16* __restrict__ Bs,
    const float* __restrict__ bias, float* __restrict__ C, int Nd)
{
    extern __shared__ __align__(1024) char smc[];
    uint32_t sb = smem_u32(smc);
    const int tid = threadIdx.x;
    const size_t bm = (size_t)blockIdx.y * TM;
    const size_t bn = (size_t)blockIdx.x * TN;
    const char* Ag = (const char*)As + bm * ROWB;
    const char* Bg = (const char*)Bs + bn * ROWB;

    load_stage(sb, 0, 0, Ag, Bg, tid);
    load_stage(sb, 1, 1, Ag, Bg, tid);
    load_stage(sb, 2, 2, Ag, Bg, tid);

    const int warp = tid >> 5, lane = tid & 31;
    const int wm = (warp >> 2) * 64;
    const int wn = (warp & 3) * 64;

    float acc[4][8][4];
#pragma unroll
    for (int i = 0; i < 4; i++)
#pragma unroll
        for (int j = 0; j < 8; j++)
#pragma unroll
            for (int q = 0; q < 4; q++) acc[i][j][q] = 0.f;

    const int a_r = lane & 15;
    const int a_c = (lane >> 4) << 4;
    const int b_r = (lane & 7) + ((lane >> 4) << 3);
    const int b_c = ((lane >> 3) & 1) << 4;

    const int akb[6] = {0, 32, 0, 32, 64, 96};
    const int bkb[6] = {0, 32, 64, 96, 0, 32};

    for (int s = 0; s < NSTG; s++) {
        const int buf = s & 3;
        if (s <= NSTG - 3)      asm volatile("cp.async.wait_group 2;" ::: "memory");
        else if (s == NSTG - 2) asm volatile("cp.async.wait_group 1;" ::: "memory");
        else                    asm volatile("cp.async.wait_group 0;" ::: "memory");
        __syncthreads();
        if (s + 3 < NSTG) load_stage(sb, (s + 3) & 3, s + 3, Ag, Bg, tid);

        uint32_t ab = sb + buf * STG;
        uint32_t bb = ab + CH_A;

#pragma unroll
        for (int ks = 0; ks < 6; ks++) {
            uint32_t ar[4][4];
#pragma unroll
            for (int i = 0; i < 4; i++) {
                int row = wm + i * 16 + a_r;
                ldm_x4(ar[i], ab + sw128(row * 128 + akb[ks] + a_c));
            }
            uint32_t br[4][4];
#pragma unroll
            for (int j = 0; j < 4; j++) {
                int row = wn + j * 16 + b_r;
                ldm_x4(br[j], bb + sw128(row * 128 + bkb[ks] + b_c));
            }
#pragma unroll
            for (int i = 0; i < 4; i++)
#pragma unroll
                for (int j = 0; j < 4; j++) {
                    mma16816(acc[i][2 * j + 0], ar[i], &br[j][0]);
                    mma16816(acc[i][2 * j + 1], ar[i], &br[j][2]);
                }
        }
    }

    const int r0 = lane >> 2;
    const int c0 = (lane & 3) * 2;
    const size_t grow = bm + wm + r0;
    const int gcol = (int)bn + wn + c0;

    float2 bv[8];
#pragma unroll
    for (int j = 0; j < 8; j++)
        bv[j] = *(const float2*)(bias + gcol + j * 8);

#pragma unroll
    for (int i = 0; i < 4; i++) {
        float* cp0 = C + (grow + i * 16) * Nd + gcol;
        float* cp1 = cp0 + (size_t)8 * Nd;
#pragma unroll
        for (int j = 0; j < 8; j++) {
            *(float2*)(cp0 + j * 8) = make_float2(acc[i][j][0] + bv[j].x, acc[i][j][1] + bv[j].y);
            *(float2*)(cp1 + j * 8) = make_float2(acc[i][j][2] + bv[j].x, acc[i][j][3] + bv[j].y);
        }
    }
}

/* ---------------- tensor-core attention ------------------------------------ */
/* One CTA per (b,h), 4 warps.  K/V -> bf16 hi/lo in SW128 smem (208x64 each).*/
/* Warp handles 16-row Q strips: QK^T (3-term), softmax in frags, P*V (3-term)*/
#define NPAD 208
#define CHB (NPAD * 128)            /* 26624 per array */
#define ASMEM (4 * CHB)             /* 106496 */

__global__ __launch_bounds__(128) void attn_mma(const float* __restrict__ qkv,
                                                float* __restrict__ out)
{
    extern __shared__ __align__(1024) char smem[];
    uint32_t sbase = smem_u32(smem);
    const uint32_t Khi = sbase, Klo = sbase + CHB, Vhi = sbase + 2 * CHB, Vlo = sbase + 3 * CHB;
    const int b = blockIdx.x / HEADS, h = blockIdx.x % HEADS;
    const int tid = threadIdx.x;
    const float* base = qkv + (size_t)b * NTOK * QKV_N + h * DH;

    /* stage K,V as bf16 hi/lo (rows >= NTOK zeroed) */
    for (int idx = tid; idx < NPAD * 32; idx += 128) {
        int j = idx >> 5, dp = idx & 31;
        float2 kv = make_float2(0.f, 0.f), vv = make_float2(0.f, 0.f);
        if (j < NTOK) {
            const float* p = base + (size_t)j * QKV_N + dp * 2;
            kv = *(const float2*)(p + CDIM);
            vv = *(const float2*)(p + 2 * CDIM);
        }
        uint32_t off = sw128((uint32_t)(j * 128 + dp * 4));
        uint32_t khu, klu, vhu, vlu;
        fsplit2(kv.x, kv.y, khu, klu);
        fsplit2(vv.x, vv.y, vhu, vlu);
        asm volatile("st.shared.b32 [%0], %1;" :: "r"(Khi + off), "r"(khu) : "memory");
        asm volatile("st.shared.b32 [%0], %1;" :: "r"(Klo + off), "r"(klu) : "memory");
        asm volatile("st.shared.b32 [%0], %1;" :: "r"(Vhi + off), "r"(vhu) : "memory");
        asm volatile("st.shared.b32 [%0], %1;" :: "r"(Vlo + off), "r"(vlu) : "memory");
    }
    __syncthreads();

    const int lane = tid & 31, warp = tid >> 5;
    const int qr = lane >> 2;          /* quad row 0..7 */
    const int qc = (lane & 3) * 2;     /* quad col pair */
    const int b_r = (lane & 7) + ((lane >> 4) << 3);
    const int b_c = ((lane >> 3) & 1) << 4;
    const int a_r = lane & 15;
    const int a_c = (lane >> 4) << 4;

    for (int s = warp; s < 13; s += 4) {
        const int m0 = s * 16 + qr;
        const int m1 = m0 + 8;
        const int rm0 = m0 < NTOK ? m0 : NTOK - 1;
        const int rm1 = m1 < NTOK ? m1 : NTOK - 1;

        /* Q fragments straight from global, hi/lo split in regs */
        uint32_t qh[4][4], ql[4][4];
        const float* q0 = base + (size_t)rm0 * QKV_N;
        const float* q1 = base + (size_t)rm1 * QKV_N;
#pragma unroll
        for (int kt = 0; kt < 4; kt++) {
            int c = kt * 16 + qc;
            float2 p00 = *(const float2*)(q0 + c);
            float2 p10 = *(const float2*)(q1 + c);
            float2 p01 = *(const float2*)(q0 + c + 8);
            float2 p11 = *(const float2*)(q1 + c + 8);
            fsplit2(p00.x, p00.y, qh[kt][0], ql[kt][0]);
            fsplit2(p10.x, p10.y, qh[kt][1], ql[kt][1]);
            fsplit2(p01.x, p01.y, qh[kt][2], ql[kt][2]);
            fsplit2(p11.x, p11.y, qh[kt][3], ql[kt][3]);
        }

        /* S = Q K^T, 3-term bf16x3, accum 16x208 */
        float S[26][4];
#pragma unroll
        for (int t = 0; t < 26; t++)
#pragma unroll
            for (int q = 0; q < 4; q++) S[t][q] = 0.f;

#pragma unroll
        for (int nc = 0; nc < 13; nc++) {
#pragma unroll
            for (int kt = 0; kt < 4; kt++) {
                uint32_t kbh[4], kbl[4];
                uint32_t rb = (uint32_t)((nc * 16 + b_r) * 128 + kt * 32 + b_c);
                ldm_x4(kbh, Khi + sw128(rb));
                ldm_x4(kbl, Klo + sw128(rb));
                mma16816(S[2 * nc],     qh[kt], &kbh[0]);
                mma16816(S[2 * nc + 1], qh[kt], &kbh[2]);
                mma16816(S[2 * nc],     qh[kt], &kbl[0]);
                mma16816(S[2 * nc + 1], qh[kt], &kbl[2]);
                mma16816(S[2 * nc],     ql[kt], &kbh[0]);
                mma16816(S[2 * nc + 1], ql[kt], &kbh[2]);
            }
        }

        /* mask padded cols (only tiles 24,25 can touch j>=197) */
#pragma unroll
        for (int t = 24; t < 26; t++) {
            int j0 = t * 8 + qc;
            if (j0 >= NTOK)     S[t][0] = S[t][2] = -1e30f;
            if (j0 + 1 >= NTOK) S[t][1] = S[t][3] = -1e30f;
        }

        /* softmax (rows m0 -> S[.][0,1], m1 -> S[.][2,3]) */
        float mx0 = -1e30f, mx1 = -1e30f;
#pragma unroll
        for (int t = 0; t < 26; t++) {
            mx0 = fmaxf(mx0, fmaxf(S[t][0], S[t][1]));
            mx1 = fmaxf(mx1, fmaxf(S[t][2], S[t][3]));
        }
        mx0 = fmaxf(mx0, __shfl_xor_sync(0xffffffffu, mx0, 1));
        mx0 = fmaxf(mx0, __shfl_xor_sync(0xffffffffu, mx0, 2));
        mx1 = fmaxf(mx1, __shfl_xor_sync(0xffffffffu, mx1, 1));
        mx1 = fmaxf(mx1, __shfl_xor_sync(0xffffffffu, mx1, 2));
        float sum0 = 0.f, sum1 = 0.f;
#pragma unroll
        for (int t = 0; t < 26; t++) {
            S[t][0] = __expf((S[t][0] - mx0) * 0.125f);
            S[t][1] = __expf((S[t][1] - mx0) * 0.125f);
            S[t][2] = __expf((S[t][2] - mx1) * 0.125f);
            S[t][3] = __expf((S[t][3] - mx1) * 0.125f);
            sum0 += S[t][0] + S[t][1];
            sum1 += S[t][2] + S[t][3];
        }
        sum0 += __shfl_xor_sync(0xffffffffu, sum0, 1);
        sum0 += __shfl_xor_sync(0xffffffffu, sum0, 2);
        sum1 += __shfl_xor_sync(0xffffffffu, sum1, 1);
        sum1 += __shfl_xor_sync(0xffffffffu, sum1, 2);
        float inv0 = __frcp_rn(sum0), inv1 = __frcp_rn(sum1);

        /* O = P V (unnormalized P, 3-term) */
        float O[8][4];
#pragma unroll
        for (int t = 0; t < 8; t++)
#pragma unroll
            for (int q = 0; q < 4; q++) O[t][q] = 0.f;

#pragma unroll
        for (int jt = 0; jt < 13; jt++) {
            uint32_t ph[4], pl[4];
            fsplit2(S[2 * jt][0],     S[2 * jt][1],     ph[0], pl[0]);
            fsplit2(S[2 * jt][2],     S[2 * jt][3],     ph[1], pl[1]);
            fsplit2(S[2 * jt + 1][0], S[2 * jt + 1][1], ph[2], pl[2]);
            fsplit2(S[2 * jt + 1][2], S[2 * jt + 1][3], ph[3], pl[3]);
#pragma unroll
            for (int dc = 0; dc < 4; dc++) {
                uint32_t vbh[4], vbl[4];
                uint32_t rb = (uint32_t)((jt * 16 + a_r) * 128 + dc * 32 + a_c);
                ldm_x4t(vbh, Vhi + sw128(rb));
                ldm_x4t(vbl, Vlo + sw128(rb));
                mma16816(O[2 * dc],     ph, &vbh[0]);
                mma16816(O[2 * dc + 1], ph, &vbh[2]);
                mma16816(O[2 * dc],     ph, &vbl[0]);
                mma16816(O[2 * dc + 1], ph, &vbl[2]);
                mma16816(O[2 * dc],     pl, &vbh[0]);
                mma16816(O[2 * dc + 1], pl, &vbh[2]);
            }
        }

        /* store (normalize by inv) */
        if (m0 < NTOK) {
            float* op = out + (size_t)(b * NTOK + m0) * CDIM + h * DH + qc;
#pragma unroll
            for (int t = 0; t < 8; t++)
                *(float2*)(op + t * 8) = make_float2(O[t][0] * inv0, O[t][1] * inv0);
        }
        if (m1 < NTOK) {
            float* op = out + (size_t)(b * NTOK + m1) * CDIM + h * DH + qc;
#pragma unroll
            for (int t = 0; t < 8; t++)
                *(float2*)(op + t * 8) = make_float2(O[t][2] * inv1, O[t][3] * inv1);
        }
    }
}

/* ---------------- depthwise 3x3 conv (unchanged) -------------------------- */
__global__ __launch_bounds__(256) void dwconv_add(const float* __restrict__ qkv,
                                                  const float* __restrict__ w,
                                                  const float* __restrict__ bias,
                                                  float* __restrict__ out)
{
    int idx = blockIdx.x * 256 + threadIdx.x;
    int c = idx % CDIM;
    int r = idx / CDIM;
    int x = r % GRID14; r /= GRID14;
    int y = r % GRID14;
    int b = r / GRID14;

    const float* vbase = qkv + (size_t)b * NTOK * QKV_N + 2 * CDIM + c;
    const float* wc = w + c * 9;
    float acc = bias[c];
#pragma unroll
    for (int ky = 0; ky < 3; ky++) {
        int yy = y + ky - 1;
        if (yy < 0 || yy >= GRID14) continue;
#pragma unroll
        for (int kx = 0; kx < 3; kx++) {
            int xx = x + kx - 1;
            if (xx < 0 || xx >= GRID14) continue;
            acc = fmaf(vbase[(size_t)(1 + yy * GRID14 + xx) * QKV_N], wc[ky * 3 + kx], acc);
        }
    }
    out[(size_t)(b * NTOK + 1 + y * GRID14 + x) * CDIM + c] += acc;
}

/* ---------------- launch --------------------------------------------------- */
extern "C" void kernel_launch(void* const* d_in, const int* in_sizes, int n_in,
                              void* d_out, int out_size)
{
    const float* x      = (const float*)d_in[0];
    const float* W_qkv  = (const float*)d_in[1];
    const float* b_qkv  = (const float*)d_in[2];
    const float* W_proj = (const float*)d_in[3];
    const float* b_proj = (const float*)d_in[4];
    const float* dwc_w  = (const float*)d_in[5];
    const float* dwc_b  = (const float*)d_in[6];
    float* out = (float*)d_out;

    float *qkv = nullptr, *att = nullptr;
    __nv_bfloat16 *xs = nullptr, *atts = nullptr, *wqkvs = nullptr, *wprojs = nullptr;
    cudaGetSymbolAddress((void**)&qkv, g_qkv);
    cudaGetSymbolAddress((void**)&att, g_att);
    cudaGetSymbolAddress((void**)&xs, g_xs);
    cudaGetSymbolAddress((void**)&atts, g_atts);
    cudaGetSymbolAddress((void**)&wqkvs, g_wqkvs);
    cudaGetSymbolAddress((void**)&wprojs, g_wprojs);

    cudaFuncSetAttribute(attn_mma, cudaFuncAttributeMaxDynamicSharedMemorySize, ASMEM);
    cudaFuncSetAttribute(gemm_mma, cudaFuncAttributeMaxDynamicSharedMemorySize, GSMEM);

    /* prep: hi/lo splits */
    split_rows<<<(M_ROWS * KTOT) / 256, 256>>>(x, xs, M_ROWS * KTOT);
    wsplit<<<(QKV_N * KTOT) / 256, 256>>>(W_qkv, wqkvs, QKV_N, QKV_N * KTOT);
    wsplit<<<(CDIM * KTOT) / 256, 256>>>(W_proj, wprojs, CDIM, CDIM * KTOT);

    /* 1) qkv = x @ W_qkv + b_qkv */
    gemm_mma<<<dim3(QKV_N / TN, M_ROWS / TM), 256, GSMEM>>>(xs, wqkvs, b_qkv, qkv, QKV_N);

    /* 2) attention -> g_att (tensor cores) */
    attn_mma<<<BATCH * HEADS, 128, ASMEM>>>(qkv, att);

    /* 3) depthwise conv on V, += into g_att rows 1..196 */
    dwconv_add<<<(BATCH * (NTOK - 1) * CDIM) / 256, 256>>>(qkv, dwc_w, dwc_b, att);

    /* 4) split attention output, then out = g_att @ W_proj + b_proj */
    split_rows<<<(M_ROWS * KTOT) / 256, 256>>>(att, atts, M_ROWS * KTOT);
    gemm_mma<<<dim3(CDIM / TN, M_ROWS / TM), 256, GSMEM>>>(atts, wprojs, b_proj, out, CDIM);
}

// round 5
// speedup vs baseline: 3.9168x; 1.2901x over previous
#include <cuda_runtime.h>
#include <cuda_fp16.h>
#include <cstdint>
#include <math.h>

#define BATCH 256
#define NTOK 197
#define CDIM 768
#define HEADS 12
#define DH 64
#define GRID14 14
#define M_ROWS (BATCH * NTOK)   /* 50432 = 394*128 */
#define QKV_N (3 * CDIM)        /* 2304 */
#define KTOT 768
#define KSPLIT (2 * KTOT)       /* 1536 fp16 per split row */
#define ROWB (KSPLIT * 2)       /* 3072 bytes per split row */
#define BROWB (KTOT * 2)        /* 1536 bytes per single-fp16 B row */

/* ---------------- scratch (__device__ globals; no allocs allowed) -------- */
__device__ float g_qkv[(size_t)M_ROWS * QKV_N];
__device__ __half g_xs[(size_t)M_ROWS * KSPLIT];     /* x split hi/lo fp16 */
__device__ __half g_atts[(size_t)M_ROWS * KSPLIT];   /* attn+conv split    */
__device__ __half g_wqkvs[(size_t)QKV_N * KTOT];     /* W_qkv^T fp16       */
__device__ __half g_wprojs[(size_t)CDIM * KTOT];     /* W_proj^T fp16      */

/* ---------------- helpers ------------------------------------------------- */
__device__ __forceinline__ uint32_t smem_u32(const void* p) {
    uint32_t a;
    asm("{ .reg .u64 t; cvta.to.shared.u64 t, %1; cvt.u32.u64 %0, t; }" : "=r"(a) : "l"(p));
    return a;
}
__device__ __forceinline__ uint32_t sw128(uint32_t o) { return o ^ ((o >> 3) & 0x70); }

__device__ __forceinline__ void cp16(uint32_t s, const void* g) {
    asm volatile("cp.async.cg.shared.global [%0], [%1], 16;" :: "r"(s), "l"(g));
}
__device__ __forceinline__ void ldm_x4(uint32_t* r, uint32_t a) {
    asm volatile("ldmatrix.sync.aligned.m8n8.x4.shared.b16 {%0,%1,%2,%3}, [%4];"
                 : "=r"(r[0]), "=r"(r[1]), "=r"(r[2]), "=r"(r[3]) : "r"(a));
}
__device__ __forceinline__ void ldm_x4t(uint32_t* r, uint32_t a) {
    asm volatile("ldmatrix.sync.aligned.m8n8.x4.trans.shared.b16 {%0,%1,%2,%3}, [%4];"
                 : "=r"(r[0]), "=r"(r[1]), "=r"(r[2]), "=r"(r[3]) : "r"(a));
}
__device__ __forceinline__ void mma16816(float* c, const uint32_t* a, const uint32_t* b) {
    asm volatile(
        "mma.sync.aligned.m16n8k16.row.col.f32.f16.f16.f32 "
        "{%0,%1,%2,%3}, {%4,%5,%6,%7}, {%8,%9}, {%0,%1,%2,%3};"
        : "+f"(c[0]), "+f"(c[1]), "+f"(c[2]), "+f"(c[3])
        : "r"(a[0]), "r"(a[1]), "r"(a[2]), "r"(a[3]), "r"(b[0]), "r"(b[1]));
}
/* split two floats into packed fp16 hi-pair and lo-pair (x in low half) */
__device__ __forceinline__ void fsplit2h(float x, float y, uint32_t& hi, uint32_t& lo) {
    __half hx = __float2half_rn(x), hy = __float2half_rn(y);
    __half lx = __float2half_rn(x - __half2float(hx));
    __half ly = __float2half_rn(y - __half2float(hy));
    __half2 th = __halves2half2(hx, hy);
    __half2 tl = __halves2half2(lx, ly);
    hi = *reinterpret_cast<uint32_t*>(&th);
    lo = *reinterpret_cast<uint32_t*>(&tl);
}

/* ---------------- prep kernels -------------------------------------------- */
/* x [R,768] fp32 -> split fp16 [R,1536], per-32 chunk [hi32|lo32] */
__global__ __launch_bounds__(256) void split_rows(const float* __restrict__ in,
                                                  __half* __restrict__ out, int total)
{
    int idx = blockIdx.x * 256 + threadIdx.x;
    if (idx >= total) return;
    int r = idx / KTOT, k = idx % KTOT;
    float a = in[idx];
    __half hi = __float2half_rn(a);
    __half lo = __float2half_rn(a - __half2float(hi));
    size_t o = (size_t)r * KSPLIT + ((k >> 5) << 6) + (k & 31);
    out[o] = hi;
    out[o + 32] = lo;
}

/* W [768,N] -> fp16 [N,768] transpose */
__global__ __launch_bounds__(256) void wpack(const float* __restrict__ W,
                                             __half* __restrict__ out,
                                             int N, int total)
{
    int idx = blockIdx.x * 256 + threadIdx.x;
    if (idx >= total) return;
    int n = idx / KTOT, k = idx % KTOT;
    out[(size_t)n * KTOT + k] = __float2half_rn(W[(size_t)k * N + n]);
}

/* ---------------- fp16 2-term GEMM, 6-stage pipeline ----------------------- */
/* C[M,Nd] = A*B^T + bias.  A split fp16 [M,1536], B single fp16 [Nd,768].   */
#define TM 128
#define TN 256
#define NSTG 24
#define RING 6
#define PF 5
#define STG_A 16384               /* 128 rows * 128B (hi32|lo32) */
#define STG_B 16384               /* 256 rows * 64B, two rows packed per 128B */
#define STG (STG_A + STG_B)
#define GSMEM (RING * STG)        /* 196608 */

__device__ __forceinline__ void load_stage(uint32_t sb, int buf, int st,
                                           const char* Ag, const char* Bg, int tid)
{
    uint32_t ab = sb + buf * STG;
    const char* a0 = Ag + (size_t)st * 128;
#pragma unroll
    for (int c = tid; c < 1024; c += 256) {
        int r = c >> 3, j = c & 7;
        cp16(ab + sw128(r * 128 + j * 16), a0 + (size_t)r * ROWB + j * 16);
    }
    uint32_t bb = ab + STG_A;
    const char* b0 = Bg + (size_t)st * 64;
#pragma unroll
    for (int c = tid; c < 1024; c += 256) {
        int j = c >> 2, o = c & 3;
        cp16(bb + sw128((j >> 1) * 128 + (j & 1) * 64 + o * 16),
             b0 + (size_t)j * BROWB + o * 16);
    }
    asm volatile("cp.async.commit_group;" ::: "memory");
}

__global__ __launch_bounds__(256, 1) void gemm_mma(
    const __half* __restrict__ As, const __half* __restrict__ Bs,
    const float* __restrict__ bias, float* __restrict__ C, int Nd)
{
    extern __shared__ __align__(1024) char smc[];
    uint32_t sb = smem_u32(smc);
    const int tid = threadIdx.x;
    const size_t bm = (size_t)blockIdx.y * TM;
    const size_t bn = (size_t)blockIdx.x * TN;
    const char* Ag = (const char*)As + bm * ROWB;
    const char* Bg = (const char*)Bs + bn * BROWB;

#pragma unroll
    for (int st = 0; st < PF; st++) load_stage(sb, st, st, Ag, Bg, tid);

    const int warp = tid >> 5, lane = tid & 31;
    const int wm = (warp >> 2) * 64;
    const int wn = (warp & 3) * 64;

    float acc[4][8][4];
#pragma unroll
    for (int i = 0; i < 4; i++)
#pragma unroll
        for (int j = 0; j < 8; j++)
#pragma unroll
            for (int q = 0; q < 4; q++) acc[i][j][q] = 0.f;

    const int a_r = lane & 15;
    const int a_c = (lane >> 4) << 4;
    const int b_r = (lane & 7) + ((lane >> 4) << 3);
    const int b_c = ((lane >> 3) & 1) << 4;

    for (int s = 0; s < NSTG; s++) {
        const int buf = s % RING;
        if (s <= NSTG - PF)      asm volatile("cp.async.wait_group 4;" ::: "memory");
        else if (s == NSTG - 4)  asm volatile("cp.async.wait_group 3;" ::: "memory");
        else if (s == NSTG - 3)  asm volatile("cp.async.wait_group 2;" ::: "memory");
        else if (s == NSTG - 2)  asm volatile("cp.async.wait_group 1;" ::: "memory");
        else                     asm volatile("cp.async.wait_group 0;" ::: "memory");
        __syncthreads();
        if (s + PF < NSTG) load_stage(sb, (s + PF) % RING, s + PF, Ag, Bg, tid);

        uint32_t ab = sb + buf * STG;
        uint32_t bb = ab + STG_A;

#pragma unroll
        for (int t = 0; t < 2; t++) {       /* k16 halves of the 32-K stage */
            uint32_t br[4][4];
#pragma unroll
            for (int j = 0; j < 4; j++) {
                int row = wn + j * 16 + b_r;
                ldm_x4(br[j], bb + sw128((row >> 1) * 128 + (row & 1) * 64 + t * 32 + b_c));
            }
#pragma unroll
            for (int half = 0; half < 2; half++) {  /* A hi then A lo */
                uint32_t ar[4][4];
                int off = half * 64 + t * 32;
#pragma unroll
                for (int i = 0; i < 4; i++) {
                    int row = wm + i * 16 + a_r;
                    ldm_x4(ar[i], ab + sw128(row * 128 + off + a_c));
                }
#pragma unroll
                for (int i = 0; i < 4; i++)
#pragma unroll
                    for (int j = 0; j < 4; j++) {
                        mma16816(acc[i][2 * j + 0], ar[i], &br[j][0]);
                        mma16816(acc[i][2 * j + 1], ar[i], &br[j][2]);
                    }
            }
        }
    }

    const int r0 = lane >> 2;
    const int c0 = (lane & 3) * 2;
    const size_t grow = bm + wm + r0;
    const int gcol = (int)bn + wn + c0;

    float2 bv[8];
#pragma unroll
    for (int j = 0; j < 8; j++)
        bv[j] = *(const float2*)(bias + gcol + j * 8);

#pragma unroll
    for (int i = 0; i < 4; i++) {
        float* cp0 = C + (grow + i * 16) * Nd + gcol;
        float* cp1 = cp0 + (size_t)8 * Nd;
#pragma unroll
        for (int j = 0; j < 8; j++) {
            *(float2*)(cp0 + j * 8) = make_float2(acc[i][j][0] + bv[j].x, acc[i][j][1] + bv[j].y);
            *(float2*)(cp1 + j * 8) = make_float2(acc[i][j][2] + bv[j].x, acc[i][j][3] + bv[j].y);
        }
    }
}

/* ---------------- tensor-core attention, writes split atts directly -------- */
/* One CTA per (b,h).  K single fp16, V hi/lo fp16, SW128 smem.              */
/* QK^T 2-term (Q split), PV 3-term (P split x V split).                     */
#define NPAD 208
#define ACHB (NPAD * 128)           /* 26624 */
#define ASMEM (3 * ACHB)            /* 79872 */

__global__ __launch_bounds__(128) void attn_mma(const float* __restrict__ qkv,
                                                __half* __restrict__ atts)
{
    extern __shared__ __align__(1024) char smem[];
    uint32_t sbase = smem_u32(smem);
    const uint32_t Ksm = sbase, Vhi = sbase + ACHB, Vlo = sbase + 2 * ACHB;
    const int b = blockIdx.x / HEADS, h = blockIdx.x % HEADS;
    const int tid = threadIdx.x;
    const float* base = qkv + (size_t)b * NTOK * QKV_N + h * DH;

    for (int idx = tid; idx < NPAD * 32; idx += 128) {
        int j = idx >> 5, dp = idx & 31;
        float2 kv = make_float2(0.f, 0.f), vv = make_float2(0.f, 0.f);
        if (j < NTOK) {
            const float* p = base + (size_t)j * QKV_N + dp * 2;
            kv = *(const float2*)(p + CDIM);
            vv = *(const float2*)(p + 2 * CDIM);
        }
        uint32_t off = sw128((uint32_t)(j * 128 + dp * 4));
        __half2 k2 = __floats2half2_rn(kv.x, kv.y);
        uint32_t ku = *reinterpret_cast<uint32_t*>(&k2);
        uint32_t vhu, vlu;
        fsplit2h(vv.x, vv.y, vhu, vlu);
        asm volatile("st.shared.b32 [%0], %1;" :: "r"(Ksm + off), "r"(ku) : "memory");
        asm volatile("st.shared.b32 [%0], %1;" :: "r"(Vhi + off), "r"(vhu) : "memory");
        asm volatile("st.shared.b32 [%0], %1;" :: "r"(Vlo + off), "r"(vlu) : "memory");
    }
    __syncthreads();

    const int lane = tid & 31, warp = tid >> 5;
    const int qr = lane >> 2;
    const int qc = (lane & 3) * 2;
    const int b_r = (lane & 7) + ((lane >> 4) << 3);
    const int b_c = ((lane >> 3) & 1) << 4;
    const int a_r = lane & 15;
    const int a_c = (lane >> 4) << 4;

    for (int s = warp; s < 13; s += 4) {
        const int m0 = s * 16 + qr;
        const int m1 = m0 + 8;
        const int rm0 = m0 < NTOK ? m0 : NTOK - 1;
        const int rm1 = m1 < NTOK ? m1 : NTOK - 1;

        uint32_t qh[4][4], ql[4][4];
        const float* q0 = base + (size_t)rm0 * QKV_N;
        const float* q1 = base + (size_t)rm1 * QKV_N;
#pragma unroll
        for (int kt = 0; kt < 4; kt++) {
            int c = kt * 16 + qc;
            float2 p00 = *(const float2*)(q0 + c);
            float2 p10 = *(const float2*)(q1 + c);
            float2 p01 = *(const float2*)(q0 + c + 8);
            float2 p11 = *(const float2*)(q1 + c + 8);
            fsplit2h(p00.x, p00.y, qh[kt][0], ql[kt][0]);
            fsplit2h(p10.x, p10.y, qh[kt][1], ql[kt][1]);
            fsplit2h(p01.x, p01.y, qh[kt][2], ql[kt][2]);
            fsplit2h(p11.x, p11.y, qh[kt][3], ql[kt][3]);
        }

        float S[26][4];
#pragma unroll
        for (int t = 0; t < 26; t++)
#pragma unroll
            for (int q = 0; q < 4; q++) S[t][q] = 0.f;

#pragma unroll
        for (int nc = 0; nc < 13; nc++) {
#pragma unroll
            for (int kt = 0; kt < 4; kt++) {
                uint32_t kb[4];
                ldm_x4(kb, Ksm + sw128((uint32_t)((nc * 16 + b_r) * 128 + kt * 32 + b_c)));
                mma16816(S[2 * nc],     qh[kt], &kb[0]);
                mma16816(S[2 * nc + 1], qh[kt], &kb[2]);
                mma16816(S[2 * nc],     ql[kt], &kb[0]);
                mma16816(S[2 * nc + 1], ql[kt], &kb[2]);
            }
        }

#pragma unroll
        for (int t = 24; t < 26; t++) {
            int j0 = t * 8 + qc;
            if (j0 >= NTOK)     S[t][0] = S[t][2] = -1e30f;
            if (j0 + 1 >= NTOK) S[t][1] = S[t][3] = -1e30f;
        }

        float mx0 = -1e30f, mx1 = -1e30f;
#pragma unroll
        for (int t = 0; t < 26; t++) {
            mx0 = fmaxf(mx0, fmaxf(S[t][0], S[t][1]));
            mx1 = fmaxf(mx1, fmaxf(S[t][2], S[t][3]));
        }
        mx0 = fmaxf(mx0, __shfl_xor_sync(0xffffffffu, mx0, 1));
        mx0 = fmaxf(mx0, __shfl_xor_sync(0xffffffffu, mx0, 2));
        mx1 = fmaxf(mx1, __shfl_xor_sync(0xffffffffu, mx1, 1));
        mx1 = fmaxf(mx1, __shfl_xor_sync(0xffffffffu, mx1, 2));
        float sum0 = 0.f, sum1 = 0.f;
#pragma unroll
        for (int t = 0; t < 26; t++) {
            S[t][0] = __expf((S[t][0] - mx0) * 0.125f);
            S[t][1] = __expf((S[t][1] - mx0) * 0.125f);
            S[t][2] = __expf((S[t][2] - mx1) * 0.125f);
            S[t][3] = __expf((S[t][3] - mx1) * 0.125f);
            sum0 += S[t][0] + S[t][1];
            sum1 += S[t][2] + S[t][3];
        }
        sum0 += __shfl_xor_sync(0xffffffffu, sum0, 1);
        sum0 += __shfl_xor_sync(0xffffffffu, sum0, 2);
        sum1 += __shfl_xor_sync(0xffffffffu, sum1, 1);
        sum1 += __shfl_xor_sync(0xffffffffu, sum1, 2);
        float inv0 = __frcp_rn(sum0), inv1 = __frcp_rn(sum1);

        float O[8][4];
#pragma unroll
        for (int t = 0; t < 8; t++)
#pragma unroll
            for (int q = 0; q < 4; q++) O[t][q] = 0.f;

#pragma unroll
        for (int jt = 0; jt < 13; jt++) {
            uint32_t ph[4], pl[4];
            fsplit2h(S[2 * jt][0],     S[2 * jt][1],     ph[0], pl[0]);
            fsplit2h(S[2 * jt][2],     S[2 * jt][3],     ph[1], pl[1]);
            fsplit2h(S[2 * jt + 1][0], S[2 * jt + 1][1], ph[2], pl[2]);
            fsplit2h(S[2 * jt + 1][2], S[2 * jt + 1][3], ph[3], pl[3]);
#pragma unroll
            for (int dc = 0; dc < 4; dc++) {
                uint32_t vbh[4], vbl[4];
                uint32_t rb = (uint32_t)((jt * 16 + a_r) * 128 + dc * 32 + a_c);
                ldm_x4t(vbh, Vhi + sw128(rb));
                ldm_x4t(vbl, Vlo + sw128(rb));
                mma16816(O[2 * dc],     ph, &vbh[0]);
                mma16816(O[2 * dc + 1], ph, &vbh[2]);
                mma16816(O[2 * dc],     ph, &vbl[0]);
                mma16816(O[2 * dc + 1], ph, &vbl[2]);
                mma16816(O[2 * dc],     pl, &vbh[0]);
                mma16816(O[2 * dc + 1], pl, &vbh[2]);
            }
        }

        /* write split fp16 directly into atts */
        if (m0 < NTOK) {
            __half* rp = atts + (size_t)(b * NTOK + m0) * KSPLIT + h * 128;
#pragma unroll
            for (int t = 0; t < 8; t++) {
                int off = (t >> 2) * 64 + (t & 3) * 8 + qc;
                uint32_t hi, lo;
                fsplit2h(O[t][0] * inv0, O[t][1] * inv0, hi, lo);
                *(uint32_t*)(rp + off) = hi;
                *(uint32_t*)(rp + off + 32) = lo;
            }
        }
        if (m1 < NTOK) {
            __half* rp = atts + (size_t)(b * NTOK + m1) * KSPLIT + h * 128;
#pragma unroll
            for (int t = 0; t < 8; t++) {
                int off = (t >> 2) * 64 + (t & 3) * 8 + qc;
                uint32_t hi, lo;
                fsplit2h(O[t][2] * inv1, O[t][3] * inv1, hi, lo);
                *(uint32_t*)(rp + off) = hi;
                *(uint32_t*)(rp + off + 32) = lo;
            }
        }
    }
}

/* ---------------- depthwise 3x3 conv, += into split atts ------------------- */
__global__ __launch_bounds__(256) void dwconv_split(const float* __restrict__ qkv,
                                                    const float* __restrict__ w,
                                                    const float* __restrict__ bias,
                                                    __half* __restrict__ atts)
{
    int idx = blockIdx.x * 256 + threadIdx.x;
    int c = idx % CDIM;
    int r = idx / CDIM;
    int x = r % GRID14; r /= GRID14;
    int y = r % GRID14;
    int b = r / GRID14;

    const float* vbase = qkv + (size_t)b * NTOK * QKV_N + 2 * CDIM + c;
    const float* wc = w + c * 9;
    float acc = bias[c];
#pragma unroll
    for (int ky = 0; ky < 3; ky++) {
        int yy = y + ky - 1;
        if (yy < 0 || yy >= GRID14) continue;
#pragma unroll
        for (int kx = 0; kx < 3; kx++) {
            int xx = x + kx - 1;
            if (xx < 0 || xx >= GRID14) continue;
            acc = fmaf(vbase[(size_t)(1 + yy * GRID14 + xx) * QKV_N], wc[ky * 3 + kx], acc);
        }
    }
    size_t row = (size_t)(b * NTOK + 1 + y * GRID14 + x);
    size_t o = row * KSPLIT + ((c >> 5) << 6) + (c & 31);
    float v = __half2float(atts[o]) + __half2float(atts[o + 32]) + acc;
    __half hi = __float2half_rn(v);
    __half lo = __float2half_rn(v - __half2float(hi));
    atts[o] = hi;
    atts[o + 32] = lo;
}

/* ---------------- launch --------------------------------------------------- */
extern "C" void kernel_launch(void* const* d_in, const int* in_sizes, int n_in,
                              void* d_out, int out_size)
{
    const float* x      = (const float*)d_in[0];
    const float* W_qkv  = (const float*)d_in[1];
    const float* b_qkv  = (const float*)d_in[2];
    const float* W_proj = (const float*)d_in[3];
    const float* b_proj = (const float*)d_in[4];
    const float* dwc_w  = (const float*)d_in[5];
    const float* dwc_b  = (const float*)d_in[6];
    float* out = (float*)d_out;

    float* qkv = nullptr;
    __half *xs = nullptr, *atts = nullptr, *wqkvs = nullptr, *wprojs = nullptr;
    cudaGetSymbolAddress((void**)&qkv, g_qkv);
    cudaGetSymbolAddress((void**)&xs, g_xs);
    cudaGetSymbolAddress((void**)&atts, g_atts);
    cudaGetSymbolAddress((void**)&wqkvs, g_wqkvs);
    cudaGetSymbolAddress((void**)&wprojs, g_wprojs);

    cudaFuncSetAttribute(attn_mma, cudaFuncAttributeMaxDynamicSharedMemorySize, ASMEM);
    cudaFuncSetAttribute(gemm_mma, cudaFuncAttributeMaxDynamicSharedMemorySize, GSMEM);

    split_rows<<<(M_ROWS * KTOT) / 256, 256>>>(x, xs, M_ROWS * KTOT);
    wpack<<<(QKV_N * KTOT) / 256, 256>>>(W_qkv, wqkvs, QKV_N, QKV_N * KTOT);
    wpack<<<(CDIM * KTOT) / 256, 256>>>(W_proj, wprojs, CDIM, CDIM * KTOT);

    /* 1) qkv = x @ W_qkv + b_qkv */
    gemm_mma<<<dim3(QKV_N / TN, M_ROWS / TM), 256, GSMEM>>>(xs, wqkvs, b_qkv, qkv, QKV_N);

    /* 2) attention -> atts (split fp16, direct) */
    attn_mma<<<BATCH * HEADS, 128, ASMEM>>>(qkv, atts);

    /* 3) depthwise conv on V, += into atts rows 1.. (read-modify-write split) */
    dwconv_split<<<(BATCH * (NTOK - 1) * CDIM) / 256, 256>>>(qkv, dwc_w, dwc_b, atts);

    /* 4) out = (attn+conv) @ W_proj + b_proj */
    gemm_mma<<<dim3(CDIM / TN, M_ROWS / TM), 256, GSMEM>>>(atts, wprojs, b_proj, out, CDIM);
}

// round 6
// speedup vs baseline: 3.9603x; 1.0111x over previous
#include <cuda_runtime.h>
#include <cuda_fp16.h>
#include <cstdint>
#include <math.h>

#define BATCH 256
#define NTOK 197
#define CDIM 768
#define HEADS 12
#define DH 64
#define GRID14 14
#define M_ROWS (BATCH * NTOK)   /* 50432 = 394*128 */
#define QKV_N (3 * CDIM)        /* 2304 */
#define KTOT 768
#define KSPLIT (2 * KTOT)       /* 1536 fp16 per split row */
#define ROWB (KSPLIT * 2)       /* 3072 bytes per split row */
#define BROWB (KTOT * 2)        /* 1536 bytes per single-fp16 B row */

/* ---------------- scratch (__device__ globals; no allocs allowed) -------- */
__device__ float g_qkv[(size_t)M_ROWS * QKV_N];
__device__ __half g_xs[(size_t)M_ROWS * KSPLIT];     /* x split hi/lo fp16 */
__device__ __half g_atts[(size_t)M_ROWS * KSPLIT];   /* attn+conv split    */
__device__ __half g_wqkvs[(size_t)QKV_N * KTOT];     /* W_qkv^T fp16       */
__device__ __half g_wprojs[(size_t)CDIM * KTOT];     /* W_proj^T fp16      */

/* ---------------- helpers ------------------------------------------------- */
__device__ __forceinline__ uint32_t smem_u32(const void* p) {
    uint32_t a;
    asm("{ .reg .u64 t; cvta.to.shared.u64 t, %1; cvt.u32.u64 %0, t; }" : "=r"(a) : "l"(p));
    return a;
}
__device__ __forceinline__ uint32_t sw128(uint32_t o) { return o ^ ((o >> 3) & 0x70); }

__device__ __forceinline__ void cp16(uint32_t s, const void* g) {
    asm volatile("cp.async.cg.shared.global [%0], [%1], 16;" :: "r"(s), "l"(g));
}
__device__ __forceinline__ void ldm_x4(uint32_t* r, uint32_t a) {
    asm volatile("ldmatrix.sync.aligned.m8n8.x4.shared.b16 {%0,%1,%2,%3}, [%4];"
                 : "=r"(r[0]), "=r"(r[1]), "=r"(r[2]), "=r"(r[3]) : "r"(a));
}
__device__ __forceinline__ void ldm_x4t(uint32_t* r, uint32_t a) {
    asm volatile("ldmatrix.sync.aligned.m8n8.x4.trans.shared.b16 {%0,%1,%2,%3}, [%4];"
                 : "=r"(r[0]), "=r"(r[1]), "=r"(r[2]), "=r"(r[3]) : "r"(a));
}
__device__ __forceinline__ void mma16816(float* c, const uint32_t* a, const uint32_t* b) {
    asm volatile(
        "mma.sync.aligned.m16n8k16.row.col.f32.f16.f16.f32 "
        "{%0,%1,%2,%3}, {%4,%5,%6,%7}, {%8,%9}, {%0,%1,%2,%3};"
        : "+f"(c[0]), "+f"(c[1]), "+f"(c[2]), "+f"(c[3])
        : "r"(a[0]), "r"(a[1]), "r"(a[2]), "r"(a[3]), "r"(b[0]), "r"(b[1]));
}
__device__ __forceinline__ void fsplit2h(float x, float y, uint32_t& hi, uint32_t& lo) {
    __half hx = __float2half_rn(x), hy = __float2half_rn(y);
    __half lx = __float2half_rn(x - __half2float(hx));
    __half ly = __float2half_rn(y - __half2float(hy));
    __half2 th = __halves2half2(hx, hy);
    __half2 tl = __halves2half2(lx, ly);
    hi = *reinterpret_cast<uint32_t*>(&th);
    lo = *reinterpret_cast<uint32_t*>(&tl);
}

/* ---------------- prep kernels -------------------------------------------- */
__global__ __launch_bounds__(256) void split_rows(const float* __restrict__ in,
                                                  __half* __restrict__ out, int total)
{
    int idx = blockIdx.x * 256 + threadIdx.x;
    if (idx >= total) return;
    int r = idx / KTOT, k = idx % KTOT;
    float a = in[idx];
    __half hi = __float2half_rn(a);
    __half lo = __float2half_rn(a - __half2float(hi));
    size_t o = (size_t)r * KSPLIT + ((k >> 5) << 6) + (k & 31);
    out[o] = hi;
    out[o + 32] = lo;
}

__global__ __launch_bounds__(256) void wpack(const float* __restrict__ W,
                                             __half* __restrict__ out,
                                             int N, int total)
{
    int idx = blockIdx.x * 256 + threadIdx.x;
    if (idx >= total) return;
    int n = idx / KTOT, k = idx % KTOT;
    out[(size_t)n * KTOT + k] = __float2half_rn(W[(size_t)k * N + n]);
}

/* ---------------- fp16 2-term GEMM, 6-stage pipeline ----------------------- */
#define TM 128
#define TN 256
#define NSTG 24
#define RING 6
#define PF 5
#define STG_A 16384
#define STG_B 16384
#define STG (STG_A + STG_B)
#define GSMEM (RING * STG)        /* 196608 */

__device__ __forceinline__ void load_stage(uint32_t sb, int buf, int st,
                                           const char* Ag, const char* Bg, int tid)
{
    uint32_t ab = sb + buf * STG;
    const char* a0 = Ag + (size_t)st * 128;
#pragma unroll
    for (int c = tid; c < 1024; c += 256) {
        int r = c >> 3, j = c & 7;
        cp16(ab + sw128(r * 128 + j * 16), a0 + (size_t)r * ROWB + j * 16);
    }
    uint32_t bb = ab + STG_A;
    const char* b0 = Bg + (size_t)st * 64;
#pragma unroll
    for (int c = tid; c < 1024; c += 256) {
        int j = c >> 2, o = c & 3;
        cp16(bb + sw128((j >> 1) * 128 + (j & 1) * 64 + o * 16),
             b0 + (size_t)j * BROWB + o * 16);
    }
    asm volatile("cp.async.commit_group;" ::: "memory");
}

__global__ __launch_bounds__(256, 1) void gemm_mma(
    const __half* __restrict__ As, const __half* __restrict__ Bs,
    const float* __restrict__ bias, float* __restrict__ C, int Nd)
{
    extern __shared__ __align__(1024) char smc[];
    uint32_t sb = smem_u32(smc);
    const int tid = threadIdx.x;
    const size_t bm = (size_t)blockIdx.y * TM;
    const size_t bn = (size_t)blockIdx.x * TN;
    const char* Ag = (const char*)As + bm * ROWB;
    const char* Bg = (const char*)Bs + bn * BROWB;

#pragma unroll
    for (int st = 0; st < PF; st++) load_stage(sb, st, st, Ag, Bg, tid);

    const int warp = tid >> 5, lane = tid & 31;
    const int wm = (warp >> 2) * 64;
    const int wn = (warp & 3) * 64;

    float acc[4][8][4];
#pragma unroll
    for (int i = 0; i < 4; i++)
#pragma unroll
        for (int j = 0; j < 8; j++)
#pragma unroll
            for (int q = 0; q < 4; q++) acc[i][j][q] = 0.f;

    const int a_r = lane & 15;
    const int a_c = (lane >> 4) << 4;
    const int b_r = (lane & 7) + ((lane >> 4) << 3);
    const int b_c = ((lane >> 3) & 1) << 4;

    for (int s = 0; s < NSTG; s++) {
        const int buf = s % RING;
        if (s <= NSTG - PF)      asm volatile("cp.async.wait_group 4;" ::: "memory");
        else if (s == NSTG - 4)  asm volatile("cp.async.wait_group 3;" ::: "memory");
        else if (s == NSTG - 3)  asm volatile("cp.async.wait_group 2;" ::: "memory");
        else if (s == NSTG - 2)  asm volatile("cp.async.wait_group 1;" ::: "memory");
        else                     asm volatile("cp.async.wait_group 0;" ::: "memory");
        __syncthreads();
        if (s + PF < NSTG) load_stage(sb, (s + PF) % RING, s + PF, Ag, Bg, tid);

        uint32_t ab = sb + buf * STG;
        uint32_t bb = ab + STG_A;

#pragma unroll
        for (int t = 0; t < 2; t++) {
            /* hoist all loads of this k16 step ahead of the mma bursts */
            uint32_t br[4][4];
#pragma unroll
            for (int j = 0; j < 4; j++) {
                int row = wn + j * 16 + b_r;
                ldm_x4(br[j], bb + sw128((row >> 1) * 128 + (row & 1) * 64 + t * 32 + b_c));
            }
            uint32_t a0[4][4], a1[4][4];
#pragma unroll
            for (int i = 0; i < 4; i++) {
                int row = wm + i * 16 + a_r;
                ldm_x4(a0[i], ab + sw128(row * 128 + t * 32 + a_c));
            }
#pragma unroll
            for (int i = 0; i < 4; i++) {
                int row = wm + i * 16 + a_r;
                ldm_x4(a1[i], ab + sw128(row * 128 + 64 + t * 32 + a_c));
            }
#pragma unroll
            for (int i = 0; i < 4; i++)
#pragma unroll
                for (int j = 0; j < 4; j++) {
                    mma16816(acc[i][2 * j + 0], a0[i], &br[j][0]);
                    mma16816(acc[i][2 * j + 1], a0[i], &br[j][2]);
                }
#pragma unroll
            for (int i = 0; i < 4; i++)
#pragma unroll
                for (int j = 0; j < 4; j++) {
                    mma16816(acc[i][2 * j + 0], a1[i], &br[j][0]);
                    mma16816(acc[i][2 * j + 1], a1[i], &br[j][2]);
                }
        }
    }

    const int r0 = lane >> 2;
    const int c0 = (lane & 3) * 2;
    const size_t grow = bm + wm + r0;
    const int gcol = (int)bn + wn + c0;

    float2 bv[8];
#pragma unroll
    for (int j = 0; j < 8; j++)
        bv[j] = *(const float2*)(bias + gcol + j * 8);

#pragma unroll
    for (int i = 0; i < 4; i++) {
        float* cp0 = C + (grow + i * 16) * Nd + gcol;
        float* cp1 = cp0 + (size_t)8 * Nd;
#pragma unroll
        for (int j = 0; j < 8; j++) {
            *(float2*)(cp0 + j * 8) = make_float2(acc[i][j][0] + bv[j].x, acc[i][j][1] + bv[j].y);
            *(float2*)(cp1 + j * 8) = make_float2(acc[i][j][2] + bv[j].x, acc[i][j][3] + bv[j].y);
        }
    }
}

/* ---------------- tensor-core attention + fused depthwise conv ------------- */
/* One CTA per (b,h).  K single fp16, V hi/lo fp16, SW128 smem.              */
/* The conv on V (tokens 1..196, channels h*64..h*64+63) is computed from    */
/* the staged V smem and added to O before the split write.                  */
#define NPAD 208
#define ACHB (NPAD * 128)           /* 26624 */
#define WS_OFF (3 * ACHB)           /* conv weights: 288 float2 */
#define BS_OFF (WS_OFF + 2304)      /* conv bias: 32 float2 */
#define ASMEM (BS_OFF + 256)        /* 82432 */

__global__ __launch_bounds__(128) void attn_mma(const float* __restrict__ qkv,
                                                const float* __restrict__ dwc_w,
                                                const float* __restrict__ dwc_b,
                                                __half* __restrict__ atts)
{
    extern __shared__ __align__(1024) char smem[];
    uint32_t sbase = smem_u32(smem);
    const uint32_t Ksm = sbase, Vhi = sbase + ACHB, Vlo = sbase + 2 * ACHB;
    float2* ws2 = (float2*)(smem + WS_OFF);
    float2* bs2 = (float2*)(smem + BS_OFF);
    const int b = blockIdx.x / HEADS, h = blockIdx.x % HEADS;
    const int tid = threadIdx.x;
    const float* base = qkv + (size_t)b * NTOK * QKV_N + h * DH;

    /* stage conv weights/bias for this head */
    for (int i = tid; i < 288; i += 128) {
        int pair = i / 9, tap = i % 9;
        int c = h * 64 + pair * 2;
        ws2[i] = make_float2(dwc_w[(size_t)c * 9 + tap], dwc_w[(size_t)(c + 1) * 9 + tap]);
    }
    if (tid < 32) bs2[tid] = make_float2(dwc_b[h * 64 + tid * 2], dwc_b[h * 64 + tid * 2 + 1]);

    for (int idx = tid; idx < NPAD * 32; idx += 128) {
        int j = idx >> 5, dp = idx & 31;
        float2 kv = make_float2(0.f, 0.f), vv = make_float2(0.f, 0.f);
        if (j < NTOK) {
            const float* p = base + (size_t)j * QKV_N + dp * 2;
            kv = *(const float2*)(p + CDIM);
            vv = *(const float2*)(p + 2 * CDIM);
        }
        uint32_t off = sw128((uint32_t)(j * 128 + dp * 4));
        __half2 k2 = __floats2half2_rn(kv.x, kv.y);
        uint32_t ku = *reinterpret_cast<uint32_t*>(&k2);
        uint32_t vhu, vlu;
        fsplit2h(vv.x, vv.y, vhu, vlu);
        asm volatile("st.shared.b32 [%0], %1;" :: "r"(Ksm + off), "r"(ku) : "memory");
        asm volatile("st.shared.b32 [%0], %1;" :: "r"(Vhi + off), "r"(vhu) : "memory");
        asm volatile("st.shared.b32 [%0], %1;" :: "r"(Vlo + off), "r"(vlu) : "memory");
    }
    __syncthreads();

    const int lane = tid & 31, warp = tid >> 5;
    const int qr = lane >> 2;
    const int qc = (lane & 3) * 2;
    const int b_r = (lane & 7) + ((lane >> 4) << 3);
    const int b_c = ((lane >> 3) & 1) << 4;
    const int a_r = lane & 15;
    const int a_c = (lane >> 4) << 4;

    for (int s = warp; s < 13; s += 4) {
        const int m0 = s * 16 + qr;
        const int m1 = m0 + 8;
        const int rm0 = m0 < NTOK ? m0 : NTOK - 1;
        const int rm1 = m1 < NTOK ? m1 : NTOK - 1;

        uint32_t qh[4][4], ql[4][4];
        const float* q0 = base + (size_t)rm0 * QKV_N;
        const float* q1 = base + (size_t)rm1 * QKV_N;
#pragma unroll
        for (int kt = 0; kt < 4; kt++) {
            int c = kt * 16 + qc;
            float2 p00 = *(const float2*)(q0 + c);
            float2 p10 = *(const float2*)(q1 + c);
            float2 p01 = *(const float2*)(q0 + c + 8);
            float2 p11 = *(const float2*)(q1 + c + 8);
            fsplit2h(p00.x, p00.y, qh[kt][0], ql[kt][0]);
            fsplit2h(p10.x, p10.y, qh[kt][1], ql[kt][1]);
            fsplit2h(p01.x, p01.y, qh[kt][2], ql[kt][2]);
            fsplit2h(p11.x, p11.y, qh[kt][3], ql[kt][3]);
        }

        float S[26][4];
#pragma unroll
        for (int t = 0; t < 26; t++)
#pragma unroll
            for (int q = 0; q < 4; q++) S[t][q] = 0.f;

#pragma unroll
        for (int nc = 0; nc < 13; nc++) {
#pragma unroll
            for (int kt = 0; kt < 4; kt++) {
                uint32_t kb[4];
                ldm_x4(kb, Ksm + sw128((uint32_t)((nc * 16 + b_r) * 128 + kt * 32 + b_c)));
                mma16816(S[2 * nc],     qh[kt], &kb[0]);
                mma16816(S[2 * nc + 1], qh[kt], &kb[2]);
                mma16816(S[2 * nc],     ql[kt], &kb[0]);
                mma16816(S[2 * nc + 1], ql[kt], &kb[2]);
            }
        }

#pragma unroll
        for (int t = 24; t < 26; t++) {
            int j0 = t * 8 + qc;
            if (j0 >= NTOK)     S[t][0] = S[t][2] = -1e30f;
            if (j0 + 1 >= NTOK) S[t][1] = S[t][3] = -1e30f;
        }

        float mx0 = -1e30f, mx1 = -1e30f;
#pragma unroll
        for (int t = 0; t < 26; t++) {
            mx0 = fmaxf(mx0, fmaxf(S[t][0], S[t][1]));
            mx1 = fmaxf(mx1, fmaxf(S[t][2], S[t][3]));
        }
        mx0 = fmaxf(mx0, __shfl_xor_sync(0xffffffffu, mx0, 1));
        mx0 = fmaxf(mx0, __shfl_xor_sync(0xffffffffu, mx0, 2));
        mx1 = fmaxf(mx1, __shfl_xor_sync(0xffffffffu, mx1, 1));
        mx1 = fmaxf(mx1, __shfl_xor_sync(0xffffffffu, mx1, 2));
        float sum0 = 0.f, sum1 = 0.f;
#pragma unroll
        for (int t = 0; t < 26; t++) {
            S[t][0] = __expf((S[t][0] - mx0) * 0.125f);
            S[t][1] = __expf((S[t][1] - mx0) * 0.125f);
            S[t][2] = __expf((S[t][2] - mx1) * 0.125f);
            S[t][3] = __expf((S[t][3] - mx1) * 0.125f);
            sum0 += S[t][0] + S[t][1];
            sum1 += S[t][2] + S[t][3];
        }
        sum0 += __shfl_xor_sync(0xffffffffu, sum0, 1);
        sum0 += __shfl_xor_sync(0xffffffffu, sum0, 2);
        sum1 += __shfl_xor_sync(0xffffffffu, sum1, 1);
        sum1 += __shfl_xor_sync(0xffffffffu, sum1, 2);
        float inv0 = __frcp_rn(sum0), inv1 = __frcp_rn(sum1);

        float O[8][4];
#pragma unroll
        for (int t = 0; t < 8; t++)
#pragma unroll
            for (int q = 0; q < 4; q++) O[t][q] = 0.f;

#pragma unroll
        for (int jt = 0; jt < 13; jt++) {
            uint32_t ph[4], pl[4];
            fsplit2h(S[2 * jt][0],     S[2 * jt][1],     ph[0], pl[0]);
            fsplit2h(S[2 * jt][2],     S[2 * jt][3],     ph[1], pl[1]);
            fsplit2h(S[2 * jt + 1][0], S[2 * jt + 1][1], ph[2], pl[2]);
            fsplit2h(S[2 * jt + 1][2], S[2 * jt + 1][3], ph[3], pl[3]);
#pragma unroll
            for (int dc = 0; dc < 4; dc++) {
                uint32_t vbh[4], vbl[4];
                uint32_t rb = (uint32_t)((jt * 16 + a_r) * 128 + dc * 32 + a_c);
                ldm_x4t(vbh, Vhi + sw128(rb));
                ldm_x4t(vbl, Vlo + sw128(rb));
                mma16816(O[2 * dc],     ph, &vbh[0]);
                mma16816(O[2 * dc + 1], ph, &vbh[2]);
                mma16816(O[2 * dc],     ph, &vbl[0]);
                mma16816(O[2 * dc + 1], ph, &vbl[2]);
                mma16816(O[2 * dc],     pl, &vbh[0]);
                mma16816(O[2 * dc + 1], pl, &vbh[2]);
            }
        }

        /* write rows with fused conv */
#pragma unroll
        for (int rsel = 0; rsel < 2; rsel++) {
            const int m = rsel ? m1 : m0;
            if (m >= NTOK) continue;
            const float inv = rsel ? inv1 : inv0;
            const int qs = rsel * 2;
            const bool doconv = (m >= 1);
            int y = 0, x = 0;
            if (doconv) { y = (m - 1) / GRID14; x = (m - 1) % GRID14; }
            __half* rp = atts + (size_t)(b * NTOK + m) * KSPLIT + h * 128;
#pragma unroll
            for (int t = 0; t < 8; t++) {
                float v0 = O[t][qs] * inv;
                float v1 = O[t][qs + 1] * inv;
                if (doconv) {
                    const int d0 = (t >> 1) * 16 + (t & 1) * 8 + qc;
                    float2 cv = bs2[d0 >> 1];
                    const float2* wp = ws2 + (d0 >> 1) * 9;
#pragma unroll
                    for (int ky = 0; ky < 3; ky++) {
                        int yy = y + ky - 1;
                        if (yy < 0 || yy >= GRID14) continue;
#pragma unroll
                        for (int kx = 0; kx < 3; kx++) {
                            int xx = x + kx - 1;
                            if (xx < 0 || xx >= GRID14) continue;
                            int j = 1 + yy * GRID14 + xx;
                            uint32_t off = sw128((uint32_t)(j * 128 + d0 * 2));
                            uint32_t vh, vl;
                            asm("ld.shared.b32 %0,[%1];" : "=r"(vh) : "r"(Vhi + off));
                            asm("ld.shared.b32 %0,[%1];" : "=r"(vl) : "r"(Vlo + off));
                            __half2 h2 = *reinterpret_cast<__half2*>(&vh);
                            __half2 l2 = *reinterpret_cast<__half2*>(&vl);
                            float2 wv = wp[ky * 3 + kx];
                            cv.x = fmaf(__half2float(h2.x) + __half2float(l2.x), wv.x, cv.x);
                            cv.y = fmaf(__half2float(h2.y) + __half2float(l2.y), wv.y, cv.y);
                        }
                    }
                    v0 += cv.x;
                    v1 += cv.y;
                }
                int off = (t >> 2) * 64 + (t & 3) * 8 + qc;
                uint32_t hi, lo;
                fsplit2h(v0, v1, hi, lo);
                *(uint32_t*)(rp + off) = hi;
                *(uint32_t*)(rp + off + 32) = lo;
            }
        }
    }
}

/* ---------------- launch --------------------------------------------------- */
extern "C" void kernel_launch(void* const* d_in, const int* in_sizes, int n_in,
                              void* d_out, int out_size)
{
    const float* x      = (const float*)d_in[0];
    const float* W_qkv  = (const float*)d_in[1];
    const float* b_qkv  = (const float*)d_in[2];
    const float* W_proj = (const float*)d_in[3];
    const float* b_proj = (const float*)d_in[4];
    const float* dwc_w  = (const float*)d_in[5];
    const float* dwc_b  = (const float*)d_in[6];
    float* out = (float*)d_out;

    float* qkv = nullptr;
    __half *xs = nullptr, *atts = nullptr, *wqkvs = nullptr, *wprojs = nullptr;
    cudaGetSymbolAddress((void**)&qkv, g_qkv);
    cudaGetSymbolAddress((void**)&xs, g_xs);
    cudaGetSymbolAddress((void**)&atts, g_atts);
    cudaGetSymbolAddress((void**)&wqkvs, g_wqkvs);
    cudaGetSymbolAddress((void**)&wprojs, g_wprojs);

    cudaFuncSetAttribute(attn_mma, cudaFuncAttributeMaxDynamicSharedMemorySize, ASMEM);
    cudaFuncSetAttribute(gemm_mma, cudaFuncAttributeMaxDynamicSharedMemorySize, GSMEM);

    split_rows<<<(M_ROWS * KTOT) / 256, 256>>>(x, xs, M_ROWS * KTOT);
    wpack<<<(QKV_N * KTOT) / 256, 256>>>(W_qkv, wqkvs, QKV_N, QKV_N * KTOT);
    wpack<<<(CDIM * KTOT) / 256, 256>>>(W_proj, wprojs, CDIM, CDIM * KTOT);

    /* 1) qkv = x @ W_qkv + b_qkv */
    gemm_mma<<<dim3(QKV_N / TN, M_ROWS / TM), 256, GSMEM>>>(xs, wqkvs, b_qkv, qkv, QKV_N);

    /* 2) attention + fused depthwise conv -> atts (split fp16) */
    attn_mma<<<BATCH * HEADS, 128, ASMEM>>>(qkv, dwc_w, dwc_b, atts);

    /* 3) out = (attn+conv) @ W_proj + b_proj */
    gemm_mma<<<dim3(CDIM / TN, M_ROWS / TM), 256, GSMEM>>>(atts, wprojs, b_proj, out, CDIM);
}

// round 7
// speedup vs baseline: 4.9842x; 1.2585x over previous
#include <cuda_runtime.h>
#include <cuda_fp16.h>
#include <cstdint>
#include <math.h>

#define BATCH 256
#define NTOK 197
#define CDIM 768
#define HEADS 12
#define DH 64
#define GRID14 14
#define M_ROWS (BATCH * NTOK)   /* 50432 = 394*128 */
#define QKV_N (3 * CDIM)        /* 2304 */
#define KTOT 768
#define ROWB (KTOT * 2)         /* 1536 bytes per fp16 row */

/* ---------------- scratch (__device__ globals; no allocs allowed) -------- */
__device__ float g_qkv[(size_t)M_ROWS * QKV_N];
__device__ __half g_xs[(size_t)M_ROWS * KTOT];       /* x fp16            */
__device__ __half g_atts[(size_t)M_ROWS * KTOT];     /* attn+conv fp16    */
__device__ __half g_wqkvs[(size_t)QKV_N * KTOT];     /* W_qkv^T fp16      */
__device__ __half g_wprojs[(size_t)CDIM * KTOT];     /* W_proj^T fp16     */

/* ---------------- helpers ------------------------------------------------- */
__device__ __forceinline__ uint32_t smem_u32(const void* p) {
    uint32_t a;
    asm("{ .reg .u64 t; cvta.to.shared.u64 t, %1; cvt.u32.u64 %0, t; }" : "=r"(a) : "l"(p));
    return a;
}
__device__ __forceinline__ uint32_t sw128(uint32_t o) { return o ^ ((o >> 3) & 0x70); }

__device__ __forceinline__ void cp16(uint32_t s, const void* g) {
    asm volatile("cp.async.cg.shared.global [%0], [%1], 16;" :: "r"(s), "l"(g));
}
__device__ __forceinline__ void ldm_x4(uint32_t* r, uint32_t a) {
    asm volatile("ldmatrix.sync.aligned.m8n8.x4.shared.b16 {%0,%1,%2,%3}, [%4];"
                 : "=r"(r[0]), "=r"(r[1]), "=r"(r[2]), "=r"(r[3]) : "r"(a));
}
__device__ __forceinline__ void ldm_x4t(uint32_t* r, uint32_t a) {
    asm volatile("ldmatrix.sync.aligned.m8n8.x4.trans.shared.b16 {%0,%1,%2,%3}, [%4];"
                 : "=r"(r[0]), "=r"(r[1]), "=r"(r[2]), "=r"(r[3]) : "r"(a));
}
__device__ __forceinline__ void mma16816(float* c, const uint32_t* a, const uint32_t* b) {
    asm volatile(
        "mma.sync.aligned.m16n8k16.row.col.f32.f16.f16.f32 "
        "{%0,%1,%2,%3}, {%4,%5,%6,%7}, {%8,%9}, {%0,%1,%2,%3};"
        : "+f"(c[0]), "+f"(c[1]), "+f"(c[2]), "+f"(c[3])
        : "r"(a[0]), "r"(a[1]), "r"(a[2]), "r"(a[3]), "r"(b[0]), "r"(b[1]));
}
__device__ __forceinline__ void fsplit2h(float x, float y, uint32_t& hi, uint32_t& lo) {
    __half hx = __float2half_rn(x), hy = __float2half_rn(y);
    __half lx = __float2half_rn(x - __half2float(hx));
    __half ly = __float2half_rn(y - __half2float(hy));
    __half2 th = __halves2half2(hx, hy);
    __half2 tl = __halves2half2(lx, ly);
    hi = *reinterpret_cast<uint32_t*>(&th);
    lo = *reinterpret_cast<uint32_t*>(&tl);
}

/* ---------------- prep kernels -------------------------------------------- */
__global__ __launch_bounds__(256) void xpack(const float* __restrict__ in,
                                             __half* __restrict__ out, int total)
{
    int idx = blockIdx.x * 256 + threadIdx.x;
    if (idx >= total) return;
    out[idx] = __float2half_rn(in[idx]);
}

__global__ __launch_bounds__(256) void wpack(const float* __restrict__ W,
                                             __half* __restrict__ out,
                                             int N, int total)
{
    int idx = blockIdx.x * 256 + threadIdx.x;
    if (idx >= total) return;
    int n = idx / KTOT, k = idx % KTOT;
    out[(size_t)n * KTOT + k] = __float2half_rn(W[(size_t)k * N + n]);
}

/* ---------------- plain fp16 GEMM, 8-stage pipeline ------------------------ */
/* C[M,Nd] = A*B^T + bias.  A fp16 [M,768], B fp16 [Nd,768].                */
/* K-stage = 32.  A and B rows packed 2-per-128B smem row (64B each).       */
#define TM 128
#define TN 256
#define NSTG 24
#define RING 8
#define PF 7
#define STG_A 8192                /* 128 rows * 64B */
#define STG_B 16384               /* 256 rows * 64B */
#define STG (STG_A + STG_B)       /* 24576 */
#define GSMEM (RING * STG)        /* 196608 */

__device__ __forceinline__ void load_stage(uint32_t sb, int buf, int st,
                                           const char* Ag, const char* Bg, int tid)
{
    uint32_t ab = sb + buf * STG;
    const char* a0 = Ag + (size_t)st * 64;
#pragma unroll
    for (int c = tid; c < 512; c += 256) {
        int j = c >> 2, o = c & 3;
        cp16(ab + sw128((j >> 1) * 128 + (j & 1) * 64 + o * 16),
             a0 + (size_t)j * ROWB + o * 16);
    }
    uint32_t bb = ab + STG_A;
    const char* b0 = Bg + (size_t)st * 64;
#pragma unroll
    for (int c = tid; c < 1024; c += 256) {
        int j = c >> 2, o = c & 3;
        cp16(bb + sw128((j >> 1) * 128 + (j & 1) * 64 + o * 16),
             b0 + (size_t)j * ROWB + o * 16);
    }
    asm volatile("cp.async.commit_group;" ::: "memory");
}

__global__ __launch_bounds__(256, 1) void gemm_mma(
    const __half* __restrict__ As, const __half* __restrict__ Bs,
    const float* __restrict__ bias, float* __restrict__ C, int Nd)
{
    extern __shared__ __align__(1024) char smc[];
    uint32_t sb = smem_u32(smc);
    const int tid = threadIdx.x;
    const size_t bm = (size_t)blockIdx.y * TM;
    const size_t bn = (size_t)blockIdx.x * TN;
    const char* Ag = (const char*)As + bm * ROWB;
    const char* Bg = (const char*)Bs + bn * ROWB;

#pragma unroll
    for (int st = 0; st < PF; st++) load_stage(sb, st, st, Ag, Bg, tid);

    const int warp = tid >> 5, lane = tid & 31;
    const int wm = (warp >> 2) * 64;
    const int wn = (warp & 3) * 64;

    float acc[4][8][4];
#pragma unroll
    for (int i = 0; i < 4; i++)
#pragma unroll
        for (int j = 0; j < 8; j++)
#pragma unroll
            for (int q = 0; q < 4; q++) acc[i][j][q] = 0.f;

    const int a_r = lane & 15;
    const int a_c = (lane >> 4) << 4;
    const int b_r = (lane & 7) + ((lane >> 4) << 3);
    const int b_c = ((lane >> 3) & 1) << 4;

    for (int s = 0; s < NSTG; s++) {
        const int buf = s % RING;
        if (s <= NSTG - 7)       asm volatile("cp.async.wait_group 6;" ::: "memory");
        else if (s == NSTG - 6)  asm volatile("cp.async.wait_group 5;" ::: "memory");
        else if (s == NSTG - 5)  asm volatile("cp.async.wait_group 4;" ::: "memory");
        else if (s == NSTG - 4)  asm volatile("cp.async.wait_group 3;" ::: "memory");
        else if (s == NSTG - 3)  asm volatile("cp.async.wait_group 2;" ::: "memory");
        else if (s == NSTG - 2)  asm volatile("cp.async.wait_group 1;" ::: "memory");
        else                     asm volatile("cp.async.wait_group 0;" ::: "memory");
        __syncthreads();
        if (s + PF < NSTG) load_stage(sb, (s + PF) % RING, s + PF, Ag, Bg, tid);

        uint32_t ab = sb + buf * STG;
        uint32_t bb = ab + STG_A;

#pragma unroll
        for (int t = 0; t < 2; t++) {
            uint32_t br[4][4];
#pragma unroll
            for (int j = 0; j < 4; j++) {
                int row = wn + j * 16 + b_r;
                ldm_x4(br[j], bb + sw128((row >> 1) * 128 + (row & 1) * 64 + t * 32 + b_c));
            }
            uint32_t ar[4][4];
#pragma unroll
            for (int i = 0; i < 4; i++) {
                int row = wm + i * 16 + a_r;
                ldm_x4(ar[i], ab + sw128((row >> 1) * 128 + (row & 1) * 64 + t * 32 + a_c));
            }
#pragma unroll
            for (int i = 0; i < 4; i++)
#pragma unroll
                for (int j = 0; j < 4; j++) {
                    mma16816(acc[i][2 * j + 0], ar[i], &br[j][0]);
                    mma16816(acc[i][2 * j + 1], ar[i], &br[j][2]);
                }
        }
    }

    const int r0 = lane >> 2;
    const int c0 = (lane & 3) * 2;
    const size_t grow = bm + wm + r0;
    const int gcol = (int)bn + wn + c0;

    float2 bv[8];
#pragma unroll
    for (int j = 0; j < 8; j++)
        bv[j] = *(const float2*)(bias + gcol + j * 8);

#pragma unroll
    for (int i = 0; i < 4; i++) {
        float* cp0 = C + (grow + i * 16) * Nd + gcol;
        float* cp1 = cp0 + (size_t)8 * Nd;
#pragma unroll
        for (int j = 0; j < 8; j++) {
            *(float2*)(cp0 + j * 8) = make_float2(acc[i][j][0] + bv[j].x, acc[i][j][1] + bv[j].y);
            *(float2*)(cp1 + j * 8) = make_float2(acc[i][j][2] + bv[j].x, acc[i][j][3] + bv[j].y);
        }
    }
}

/* ---------------- tensor-core attention + fused depthwise conv ------------- */
/* One CTA per (b,h).  K single fp16, V hi/lo fp16, SW128 smem.              */
/* QK^T 2-term (Q split), PV 3-term.  Conv on V added before plain-fp16 store*/
#define NPAD 208
#define ACHB (NPAD * 128)           /* 26624 */
#define WS_OFF (3 * ACHB)           /* conv weights: 288 float2 */
#define BS_OFF (WS_OFF + 2304)      /* conv bias: 32 float2 */
#define ASMEM (BS_OFF + 256)        /* 82432 */

__global__ __launch_bounds__(128) void attn_mma(const float* __restrict__ qkv,
                                                const float* __restrict__ dwc_w,
                                                const float* __restrict__ dwc_b,
                                                __half* __restrict__ atts)
{
    extern __shared__ __align__(1024) char smem[];
    uint32_t sbase = smem_u32(smem);
    const uint32_t Ksm = sbase, Vhi = sbase + ACHB, Vlo = sbase + 2 * ACHB;
    float2* ws2 = (float2*)(smem + WS_OFF);
    float2* bs2 = (float2*)(smem + BS_OFF);
    const int b = blockIdx.x / HEADS, h = blockIdx.x % HEADS;
    const int tid = threadIdx.x;
    const float* base = qkv + (size_t)b * NTOK * QKV_N + h * DH;

    for (int i = tid; i < 288; i += 128) {
        int pair = i / 9, tap = i % 9;
        int c = h * 64 + pair * 2;
        ws2[i] = make_float2(dwc_w[(size_t)c * 9 + tap], dwc_w[(size_t)(c + 1) * 9 + tap]);
    }
    if (tid < 32) bs2[tid] = make_float2(dwc_b[h * 64 + tid * 2], dwc_b[h * 64 + tid * 2 + 1]);

    for (int idx = tid; idx < NPAD * 32; idx += 128) {
        int j = idx >> 5, dp = idx & 31;
        float2 kv = make_float2(0.f, 0.f), vv = make_float2(0.f, 0.f);
        if (j < NTOK) {
            const float* p = base + (size_t)j * QKV_N + dp * 2;
            kv = *(const float2*)(p + CDIM);
            vv = *(const float2*)(p + 2 * CDIM);
        }
        uint32_t off = sw128((uint32_t)(j * 128 + dp * 4));
        __half2 k2 = __floats2half2_rn(kv.x, kv.y);
        uint32_t ku = *reinterpret_cast<uint32_t*>(&k2);
        uint32_t vhu, vlu;
        fsplit2h(vv.x, vv.y, vhu, vlu);
        asm volatile("st.shared.b32 [%0], %1;" :: "r"(Ksm + off), "r"(ku) : "memory");
        asm volatile("st.shared.b32 [%0], %1;" :: "r"(Vhi + off), "r"(vhu) : "memory");
        asm volatile("st.shared.b32 [%0], %1;" :: "r"(Vlo + off), "r"(vlu) : "memory");
    }
    __syncthreads();

    const int lane = tid & 31, warp = tid >> 5;
    const int qr = lane >> 2;
    const int qc = (lane & 3) * 2;
    const int b_r = (lane & 7) + ((lane >> 4) << 3);
    const int b_c = ((lane >> 3) & 1) << 4;
    const int a_r = lane & 15;
    const int a_c = (lane >> 4) << 4;

    for (int s = warp; s < 13; s += 4) {
        const int m0 = s * 16 + qr;
        const int m1 = m0 + 8;
        const int rm0 = m0 < NTOK ? m0 : NTOK - 1;
        const int rm1 = m1 < NTOK ? m1 : NTOK - 1;

        uint32_t qh[4][4], ql[4][4];
        const float* q0 = base + (size_t)rm0 * QKV_N;
        const float* q1 = base + (size_t)rm1 * QKV_N;
#pragma unroll
        for (int kt = 0; kt < 4; kt++) {
            int c = kt * 16 + qc;
            float2 p00 = *(const float2*)(q0 + c);
            float2 p10 = *(const float2*)(q1 + c);
            float2 p01 = *(const float2*)(q0 + c + 8);
            float2 p11 = *(const float2*)(q1 + c + 8);
            fsplit2h(p00.x, p00.y, qh[kt][0], ql[kt][0]);
            fsplit2h(p10.x, p10.y, qh[kt][1], ql[kt][1]);
            fsplit2h(p01.x, p01.y, qh[kt][2], ql[kt][2]);
            fsplit2h(p11.x, p11.y, qh[kt][3], ql[kt][3]);
        }

        float S[26][4];
#pragma unroll
        for (int t = 0; t < 26; t++)
#pragma unroll
            for (int q = 0; q < 4; q++) S[t][q] = 0.f;

#pragma unroll
        for (int nc = 0; nc < 13; nc++) {
#pragma unroll
            for (int kt = 0; kt < 4; kt++) {
                uint32_t kb[4];
                ldm_x4(kb, Ksm + sw128((uint32_t)((nc * 16 + b_r) * 128 + kt * 32 + b_c)));
                mma16816(S[2 * nc],     qh[kt], &kb[0]);
                mma16816(S[2 * nc + 1], qh[kt], &kb[2]);
                mma16816(S[2 * nc],     ql[kt], &kb[0]);
                mma16816(S[2 * nc + 1], ql[kt], &kb[2]);
            }
        }

#pragma unroll
        for (int t = 24; t < 26; t++) {
            int j0 = t * 8 + qc;
            if (j0 >= NTOK)     S[t][0] = S[t][2] = -1e30f;
            if (j0 + 1 >= NTOK) S[t][1] = S[t][3] = -1e30f;
        }

        float mx0 = -1e30f, mx1 = -1e30f;
#pragma unroll
        for (int t = 0; t < 26; t++) {
            mx0 = fmaxf(mx0, fmaxf(S[t][0], S[t][1]));
            mx1 = fmaxf(mx1, fmaxf(S[t][2], S[t][3]));
        }
        mx0 = fmaxf(mx0, __shfl_xor_sync(0xffffffffu, mx0, 1));
        mx0 = fmaxf(mx0, __shfl_xor_sync(0xffffffffu, mx0, 2));
        mx1 = fmaxf(mx1, __shfl_xor_sync(0xffffffffu, mx1, 1));
        mx1 = fmaxf(mx1, __shfl_xor_sync(0xffffffffu, mx1, 2));
        float sum0 = 0.f, sum1 = 0.f;
#pragma unroll
        for (int t = 0; t < 26; t++) {
            S[t][0] = __expf((S[t][0] - mx0) * 0.125f);
            S[t][1] = __expf((S[t][1] - mx0) * 0.125f);
            S[t][2] = __expf((S[t][2] - mx1) * 0.125f);
            S[t][3] = __expf((S[t][3] - mx1) * 0.125f);
            sum0 += S[t][0] + S[t][1];
            sum1 += S[t][2] + S[t][3];
        }
        sum0 += __shfl_xor_sync(0xffffffffu, sum0, 1);
        sum0 += __shfl_xor_sync(0xffffffffu, sum0, 2);
        sum1 += __shfl_xor_sync(0xffffffffu, sum1, 1);
        sum1 += __shfl_xor_sync(0xffffffffu, sum1, 2);
        float inv0 = __frcp_rn(sum0), inv1 = __frcp_rn(sum1);

        float O[8][4];
#pragma unroll
        for (int t = 0; t < 8; t++)
#pragma unroll
            for (int q = 0; q < 4; q++) O[t][q] = 0.f;

#pragma unroll
        for (int jt = 0; jt < 13; jt++) {
            uint32_t ph[4], pl[4];
            fsplit2h(S[2 * jt][0],     S[2 * jt][1],     ph[0], pl[0]);
            fsplit2h(S[2 * jt][2],     S[2 * jt][3],     ph[1], pl[1]);
            fsplit2h(S[2 * jt + 1][0], S[2 * jt + 1][1], ph[2], pl[2]);
            fsplit2h(S[2 * jt + 1][2], S[2 * jt + 1][3], ph[3], pl[3]);
#pragma unroll
            for (int dc = 0; dc < 4; dc++) {
                uint32_t vbh[4], vbl[4];
                uint32_t rb = (uint32_t)((jt * 16 + a_r) * 128 + dc * 32 + a_c);
                ldm_x4t(vbh, Vhi + sw128(rb));
                ldm_x4t(vbl, Vlo + sw128(rb));
                mma16816(O[2 * dc],     ph, &vbh[0]);
                mma16816(O[2 * dc + 1], ph, &vbh[2]);
                mma16816(O[2 * dc],     ph, &vbl[0]);
                mma16816(O[2 * dc + 1], ph, &vbl[2]);
                mma16816(O[2 * dc],     pl, &vbh[0]);
                mma16816(O[2 * dc + 1], pl, &vbh[2]);
            }
        }

        /* write rows with fused conv (plain fp16 atts) */
#pragma unroll
        for (int rsel = 0; rsel < 2; rsel++) {
            const int m = rsel ? m1 : m0;
            if (m >= NTOK) continue;
            const float inv = rsel ? inv1 : inv0;
            const int qs = rsel * 2;
            const bool doconv = (m >= 1);
            int y = 0, x = 0;
            if (doconv) { y = (m - 1) / GRID14; x = (m - 1) % GRID14; }
            __half* rp = atts + (size_t)(b * NTOK + m) * KTOT + h * DH;
#pragma unroll
            for (int t = 0; t < 8; t++) {
                float v0 = O[t][qs] * inv;
                float v1 = O[t][qs + 1] * inv;
                const int d0 = (t >> 1) * 16 + (t & 1) * 8 + qc;
                if (doconv) {
                    float2 cv = bs2[d0 >> 1];
                    const float2* wp = ws2 + (d0 >> 1) * 9;
#pragma unroll
                    for (int ky = 0; ky < 3; ky++) {
                        int yy = y + ky - 1;
                        if (yy < 0 || yy >= GRID14) continue;
#pragma unroll
                        for (int kx = 0; kx < 3; kx++) {
                            int xx = x + kx - 1;
                            if (xx < 0 || xx >= GRID14) continue;
                            int j = 1 + yy * GRID14 + xx;
                            uint32_t off = sw128((uint32_t)(j * 128 + d0 * 2));
                            uint32_t vh, vl;
                            asm("ld.shared.b32 %0,[%1];" : "=r"(vh) : "r"(Vhi + off));
                            asm("ld.shared.b32 %0,[%1];" : "=r"(vl) : "r"(Vlo + off));
                            __half2 h2 = *reinterpret_cast<__half2*>(&vh);
                            __half2 l2 = *reinterpret_cast<__half2*>(&vl);
                            float2 wv = wp[ky * 3 + kx];
                            cv.x = fmaf(__half2float(h2.x) + __half2float(l2.x), wv.x, cv.x);
                            cv.y = fmaf(__half2float(h2.y) + __half2float(l2.y), wv.y, cv.y);
                        }
                    }
                    v0 += cv.x;
                    v1 += cv.y;
                }
                __half2 hv = __floats2half2_rn(v0, v1);
                *(uint32_t*)(rp + d0) = *reinterpret_cast<uint32_t*>(&hv);
            }
        }
    }
}

/* ---------------- launch --------------------------------------------------- */
extern "C" void kernel_launch(void* const* d_in, const int* in_sizes, int n_in,
                              void* d_out, int out_size)
{
    const float* x      = (const float*)d_in[0];
    const float* W_qkv  = (const float*)d_in[1];
    const float* b_qkv  = (const float*)d_in[2];
    const float* W_proj = (const float*)d_in[3];
    const float* b_proj = (const float*)d_in[4];
    const float* dwc_w  = (const float*)d_in[5];
    const float* dwc_b  = (const float*)d_in[6];
    float* out = (float*)d_out;

    float* qkv = nullptr;
    __half *xs = nullptr, *atts = nullptr, *wqkvs = nullptr, *wprojs = nullptr;
    cudaGetSymbolAddress((void**)&qkv, g_qkv);
    cudaGetSymbolAddress((void**)&xs, g_xs);
    cudaGetSymbolAddress((void**)&atts, g_atts);
    cudaGetSymbolAddress((void**)&wqkvs, g_wqkvs);
    cudaGetSymbolAddress((void**)&wprojs, g_wprojs);

    cudaFuncSetAttribute(attn_mma, cudaFuncAttributeMaxDynamicSharedMemorySize, ASMEM);
    cudaFuncSetAttribute(gemm_mma, cudaFuncAttributeMaxDynamicSharedMemorySize, GSMEM);

    xpack<<<(M_ROWS * KTOT) / 256, 256>>>(x, xs, M_ROWS * KTOT);
    wpack<<<(QKV_N * KTOT) / 256, 256>>>(W_qkv, wqkvs, QKV_N, QKV_N * KTOT);
    wpack<<<(CDIM * KTOT) / 256, 256>>>(W_proj, wprojs, CDIM, CDIM * KTOT);

    /* 1) qkv = x @ W_qkv + b_qkv */
    gemm_mma<<<dim3(QKV_N / TN, M_ROWS / TM), 256, GSMEM>>>(xs, wqkvs, b_qkv, qkv, QKV_N);

    /* 2) attention + fused depthwise conv -> atts (fp16) */
    attn_mma<<<BATCH * HEADS, 128, ASMEM>>>(qkv, dwc_w, dwc_b, atts);

    /* 3) out = (attn+conv) @ W_proj + b_proj */
    gemm_mma<<<dim3(CDIM / TN, M_ROWS / TM), 256, GSMEM>>>(atts, wprojs, b_proj, out, CDIM);
}

// round 8
// speedup vs baseline: 5.5798x; 1.1195x over previous
#include <cuda_runtime.h>
#include <cuda_fp16.h>
#include <cstdint>
#include <math.h>

#define BATCH 256
#define NTOK 197
#define CDIM 768
#define HEADS 12
#define DH 64
#define GRID14 14
#define M_ROWS (BATCH * NTOK)   /* 50432 = 394*128 */
#define QKV_N (3 * CDIM)        /* 2304 */
#define KTOT 768
#define ROWB (KTOT * 2)         /* 1536 bytes per fp16 row */

/* ---------------- scratch (__device__ globals; no allocs allowed) -------- */
__device__ float g_qkv[(size_t)M_ROWS * QKV_N];
__device__ __half g_xs[(size_t)M_ROWS * KTOT];       /* x fp16            */
__device__ __half g_atts[(size_t)M_ROWS * KTOT];     /* attn+conv fp16    */
__device__ __half g_wqkvs[(size_t)QKV_N * KTOT];     /* W_qkv^T fp16      */
__device__ __half g_wprojs[(size_t)CDIM * KTOT];     /* W_proj^T fp16     */

/* ---------------- helpers ------------------------------------------------- */
__device__ __forceinline__ uint32_t smem_u32(const void* p) {
    uint32_t a;
    asm("{ .reg .u64 t; cvta.to.shared.u64 t, %1; cvt.u32.u64 %0, t; }" : "=r"(a) : "l"(p));
    return a;
}
__device__ __forceinline__ uint32_t sw128(uint32_t o) { return o ^ ((o >> 3) & 0x70); }

__device__ __forceinline__ void cp16(uint32_t s, const void* g) {
    asm volatile("cp.async.cg.shared.global [%0], [%1], 16;" :: "r"(s), "l"(g));
}
__device__ __forceinline__ void ldm_x4(uint32_t* r, uint32_t a) {
    asm volatile("ldmatrix.sync.aligned.m8n8.x4.shared.b16 {%0,%1,%2,%3}, [%4];"
                 : "=r"(r[0]), "=r"(r[1]), "=r"(r[2]), "=r"(r[3]) : "r"(a));
}
__device__ __forceinline__ void ldm_x4t(uint32_t* r, uint32_t a) {
    asm volatile("ldmatrix.sync.aligned.m8n8.x4.trans.shared.b16 {%0,%1,%2,%3}, [%4];"
                 : "=r"(r[0]), "=r"(r[1]), "=r"(r[2]), "=r"(r[3]) : "r"(a));
}
__device__ __forceinline__ void mma16816(float* c, const uint32_t* a, const uint32_t* b) {
    asm volatile(
        "mma.sync.aligned.m16n8k16.row.col.f32.f16.f16.f32 "
        "{%0,%1,%2,%3}, {%4,%5,%6,%7}, {%8,%9}, {%0,%1,%2,%3};"
        : "+f"(c[0]), "+f"(c[1]), "+f"(c[2]), "+f"(c[3])
        : "r"(a[0]), "r"(a[1]), "r"(a[2]), "r"(a[3]), "r"(b[0]), "r"(b[1]));
}
__device__ __forceinline__ void fsplit2h(float x, float y, uint32_t& hi, uint32_t& lo) {
    __half hx = __float2half_rn(x), hy = __float2half_rn(y);
    __half lx = __float2half_rn(x - __half2float(hx));
    __half ly = __float2half_rn(y - __half2float(hy));
    __half2 th = __halves2half2(hx, hy);
    __half2 tl = __halves2half2(lx, ly);
    hi = *reinterpret_cast<uint32_t*>(&th);
    lo = *reinterpret_cast<uint32_t*>(&tl);
}

/* ---------------- prep kernels -------------------------------------------- */
__global__ __launch_bounds__(256) void xpack(const float* __restrict__ in,
                                             __half* __restrict__ out, int total)
{
    int idx = blockIdx.x * 256 + threadIdx.x;
    if (idx >= total) return;
    out[idx] = __float2half_rn(in[idx]);
}

__global__ __launch_bounds__(256) void wpack(const float* __restrict__ W,
                                             __half* __restrict__ out,
                                             int N, int total)
{
    int idx = blockIdx.x * 256 + threadIdx.x;
    if (idx >= total) return;
    int n = idx / KTOT, k = idx % KTOT;
    out[(size_t)n * KTOT + k] = __float2half_rn(W[(size_t)k * N + n]);
}

/* ---------------- plain fp16 GEMM, K-stage 64, 4-buffer ring --------------- */
/* C[M,Nd] = A*B^T + bias.  A fp16 [M,768], B fp16 [Nd,768].                */
#define TM 128
#define TN 256
#define NSTG 12                   /* 768 / 64 */
#define RING 4
#define PF 3
#define STG_A 16384               /* 128 rows * 128B (64 k-elems) */
#define STG_B 32768               /* 256 rows * 128B */
#define STG (STG_A + STG_B)       /* 49152 */
#define GSMEM (RING * STG)        /* 196608 */

__device__ __forceinline__ void load_stage(uint32_t sb, int buf, int st,
                                           const char* Ag, const char* Bg, int tid)
{
    uint32_t ab = sb + buf * STG;
    const char* a0 = Ag + (size_t)st * 128;
#pragma unroll
    for (int c = tid; c < 1024; c += 256) {
        int r = c >> 3, j = c & 7;
        cp16(ab + sw128(r * 128 + j * 16), a0 + (size_t)r * ROWB + j * 16);
    }
    uint32_t bb = ab + STG_A;
    const char* b0 = Bg + (size_t)st * 128;
#pragma unroll
    for (int c = tid; c < 2048; c += 256) {
        int r = c >> 3, j = c & 7;
        cp16(bb + sw128(r * 128 + j * 16), b0 + (size_t)r * ROWB + j * 16);
    }
    asm volatile("cp.async.commit_group;" ::: "memory");
}

__global__ __launch_bounds__(256, 1) void gemm_mma(
    const __half* __restrict__ As, const __half* __restrict__ Bs,
    const float* __restrict__ bias, float* __restrict__ C, int Nd)
{
    extern __shared__ __align__(1024) char smc[];
    uint32_t sb = smem_u32(smc);
    const int tid = threadIdx.x;
    const size_t bm = (size_t)blockIdx.y * TM;
    const size_t bn = (size_t)blockIdx.x * TN;
    const char* Ag = (const char*)As + bm * ROWB;
    const char* Bg = (const char*)Bs + bn * ROWB;

#pragma unroll
    for (int st = 0; st < PF; st++) load_stage(sb, st, st, Ag, Bg, tid);

    const int warp = tid >> 5, lane = tid & 31;
    const int wm = (warp >> 2) * 64;
    const int wn = (warp & 3) * 64;

    float acc[4][8][4];
#pragma unroll
    for (int i = 0; i < 4; i++)
#pragma unroll
        for (int j = 0; j < 8; j++)
#pragma unroll
            for (int q = 0; q < 4; q++) acc[i][j][q] = 0.f;

    const int a_r = lane & 15;
    const int a_c = (lane >> 4) << 4;
    const int b_r = (lane & 7) + ((lane >> 4) << 3);
    const int b_c = ((lane >> 3) & 1) << 4;

    for (int s = 0; s < NSTG; s++) {
        const int buf = s & (RING - 1);
        if (s < NSTG - 2)        asm volatile("cp.async.wait_group 2;" ::: "memory");
        else if (s == NSTG - 2)  asm volatile("cp.async.wait_group 1;" ::: "memory");
        else                     asm volatile("cp.async.wait_group 0;" ::: "memory");
        __syncthreads();
        if (s + PF < NSTG) load_stage(sb, (s + PF) & (RING - 1), s + PF, Ag, Bg, tid);

        uint32_t ab = sb + buf * STG;
        uint32_t bb = ab + STG_A;

#pragma unroll
        for (int t = 0; t < 4; t++) {
            uint32_t br[4][4];
#pragma unroll
            for (int j = 0; j < 4; j++) {
                int row = wn + j * 16 + b_r;
                ldm_x4(br[j], bb + sw128(row * 128 + t * 32 + b_c));
            }
            uint32_t ar[4][4];
#pragma unroll
            for (int i = 0; i < 4; i++) {
                int row = wm + i * 16 + a_r;
                ldm_x4(ar[i], ab + sw128(row * 128 + t * 32 + a_c));
            }
#pragma unroll
            for (int i = 0; i < 4; i++)
#pragma unroll
                for (int j = 0; j < 4; j++) {
                    mma16816(acc[i][2 * j + 0], ar[i], &br[j][0]);
                    mma16816(acc[i][2 * j + 1], ar[i], &br[j][2]);
                }
        }
    }

    const int r0 = lane >> 2;
    const int c0 = (lane & 3) * 2;
    const size_t grow = bm + wm + r0;
    const int gcol = (int)bn + wn + c0;

    float2 bv[8];
#pragma unroll
    for (int j = 0; j < 8; j++)
        bv[j] = *(const float2*)(bias + gcol + j * 8);

#pragma unroll
    for (int i = 0; i < 4; i++) {
        float* cp0 = C + (grow + i * 16) * Nd + gcol;
        float* cp1 = cp0 + (size_t)8 * Nd;
#pragma unroll
        for (int j = 0; j < 8; j++) {
            *(float2*)(cp0 + j * 8) = make_float2(acc[i][j][0] + bv[j].x, acc[i][j][1] + bv[j].y);
            *(float2*)(cp1 + j * 8) = make_float2(acc[i][j][2] + bv[j].x, acc[i][j][3] + bv[j].y);
        }
    }
}

/* ---------------- tensor-core attention + fused depthwise conv ------------- */
#define NPAD 208
#define ACHB (NPAD * 128)           /* 26624 */
#define WS_OFF (3 * ACHB)
#define BS_OFF (WS_OFF + 2304)
#define ASMEM (BS_OFF + 256)        /* 82432 */

__global__ __launch_bounds__(128) void attn_mma(const float* __restrict__ qkv,
                                                const float* __restrict__ dwc_w,
                                                const float* __restrict__ dwc_b,
                                                __half* __restrict__ atts)
{
    extern __shared__ __align__(1024) char smem[];
    uint32_t sbase = smem_u32(smem);
    const uint32_t Ksm = sbase, Vhi = sbase + ACHB, Vlo = sbase + 2 * ACHB;
    float2* ws2 = (float2*)(smem + WS_OFF);
    float2* bs2 = (float2*)(smem + BS_OFF);
    const int b = blockIdx.x / HEADS, h = blockIdx.x % HEADS;
    const int tid = threadIdx.x;
    const float* base = qkv + (size_t)b * NTOK * QKV_N + h * DH;

    for (int i = tid; i < 288; i += 128) {
        int pair = i / 9, tap = i % 9;
        int c = h * 64 + pair * 2;
        ws2[i] = make_float2(dwc_w[(size_t)c * 9 + tap], dwc_w[(size_t)(c + 1) * 9 + tap]);
    }
    if (tid < 32) bs2[tid] = make_float2(dwc_b[h * 64 + tid * 2], dwc_b[h * 64 + tid * 2 + 1]);

    for (int idx = tid; idx < NPAD * 32; idx += 128) {
        int j = idx >> 5, dp = idx & 31;
        float2 kv = make_float2(0.f, 0.f), vv = make_float2(0.f, 0.f);
        if (j < NTOK) {
            const float* p = base + (size_t)j * QKV_N + dp * 2;
            kv = *(const float2*)(p + CDIM);
            vv = *(const float2*)(p + 2 * CDIM);
        }
        uint32_t off = sw128((uint32_t)(j * 128 + dp * 4));
        __half2 k2 = __floats2half2_rn(kv.x, kv.y);
        uint32_t ku = *reinterpret_cast<uint32_t*>(&k2);
        uint32_t vhu, vlu;
        fsplit2h(vv.x, vv.y, vhu, vlu);
        asm volatile("st.shared.b32 [%0], %1;" :: "r"(Ksm + off), "r"(ku) : "memory");
        asm volatile("st.shared.b32 [%0], %1;" :: "r"(Vhi + off), "r"(vhu) : "memory");
        asm volatile("st.shared.b32 [%0], %1;" :: "r"(Vlo + off), "r"(vlu) : "memory");
    }
    __syncthreads();

    const int lane = tid & 31, warp = tid >> 5;
    const int qr = lane >> 2;
    const int qc = (lane & 3) * 2;
    const int b_r = (lane & 7) + ((lane >> 4) << 3);
    const int b_c = ((lane >> 3) & 1) << 4;
    const int a_r = lane & 15;
    const int a_c = (lane >> 4) << 4;

    for (int s = warp; s < 13; s += 4) {
        const int m0 = s * 16 + qr;
        const int m1 = m0 + 8;
        const int rm0 = m0 < NTOK ? m0 : NTOK - 1;
        const int rm1 = m1 < NTOK ? m1 : NTOK - 1;

        uint32_t qh[4][4], ql[4][4];
        const float* q0 = base + (size_t)rm0 * QKV_N;
        const float* q1 = base + (size_t)rm1 * QKV_N;
#pragma unroll
        for (int kt = 0; kt < 4; kt++) {
            int c = kt * 16 + qc;
            float2 p00 = *(const float2*)(q0 + c);
            float2 p10 = *(const float2*)(q1 + c);
            float2 p01 = *(const float2*)(q0 + c + 8);
            float2 p11 = *(const float2*)(q1 + c + 8);
            fsplit2h(p00.x, p00.y, qh[kt][0], ql[kt][0]);
            fsplit2h(p10.x, p10.y, qh[kt][1], ql[kt][1]);
            fsplit2h(p01.x, p01.y, qh[kt][2], ql[kt][2]);
            fsplit2h(p11.x, p11.y, qh[kt][3], ql[kt][3]);
        }

        float S[26][4];
#pragma unroll
        for (int t = 0; t < 26; t++)
#pragma unroll
            for (int q = 0; q < 4; q++) S[t][q] = 0.f;

#pragma unroll
        for (int nc = 0; nc < 13; nc++) {
#pragma unroll
            for (int kt = 0; kt < 4; kt++) {
                uint32_t kb[4];
                ldm_x4(kb, Ksm + sw128((uint32_t)((nc * 16 + b_r) * 128 + kt * 32 + b_c)));
                mma16816(S[2 * nc],     qh[kt], &kb[0]);
                mma16816(S[2 * nc + 1], qh[kt], &kb[2]);
                mma16816(S[2 * nc],     ql[kt], &kb[0]);
                mma16816(S[2 * nc + 1], ql[kt], &kb[2]);
            }
        }

#pragma unroll
        for (int t = 24; t < 26; t++) {
            int j0 = t * 8 + qc;
            if (j0 >= NTOK)     S[t][0] = S[t][2] = -1e30f;
            if (j0 + 1 >= NTOK) S[t][1] = S[t][3] = -1e30f;
        }

        float mx0 = -1e30f, mx1 = -1e30f;
#pragma unroll
        for (int t = 0; t < 26; t++) {
            mx0 = fmaxf(mx0, fmaxf(S[t][0], S[t][1]));
            mx1 = fmaxf(mx1, fmaxf(S[t][2], S[t][3]));
        }
        mx0 = fmaxf(mx0, __shfl_xor_sync(0xffffffffu, mx0, 1));
        mx0 = fmaxf(mx0, __shfl_xor_sync(0xffffffffu, mx0, 2));
        mx1 = fmaxf(mx1, __shfl_xor_sync(0xffffffffu, mx1, 1));
        mx1 = fmaxf(mx1, __shfl_xor_sync(0xffffffffu, mx1, 2));
        float sum0 = 0.f, sum1 = 0.f;
#pragma unroll
        for (int t = 0; t < 26; t++) {
            S[t][0] = __expf((S[t][0] - mx0) * 0.125f);
            S[t][1] = __expf((S[t][1] - mx0) * 0.125f);
            S[t][2] = __expf((S[t][2] - mx1) * 0.125f);
            S[t][3] = __expf((S[t][3] - mx1) * 0.125f);
            sum0 += S[t][0] + S[t][1];
            sum1 += S[t][2] + S[t][3];
        }
        sum0 += __shfl_xor_sync(0xffffffffu, sum0, 1);
        sum0 += __shfl_xor_sync(0xffffffffu, sum0, 2);
        sum1 += __shfl_xor_sync(0xffffffffu, sum1, 1);
        sum1 += __shfl_xor_sync(0xffffffffu, sum1, 2);
        float inv0 = __frcp_rn(sum0), inv1 = __frcp_rn(sum1);

        float O[8][4];
#pragma unroll
        for (int t = 0; t < 8; t++)
#pragma unroll
            for (int q = 0; q < 4; q++) O[t][q] = 0.f;

#pragma unroll
        for (int jt = 0; jt < 13; jt++) {
            uint32_t ph[4], pl[4];
            fsplit2h(S[2 * jt][0],     S[2 * jt][1],     ph[0], pl[0]);
            fsplit2h(S[2 * jt][2],     S[2 * jt][3],     ph[1], pl[1]);
            fsplit2h(S[2 * jt + 1][0], S[2 * jt + 1][1], ph[2], pl[2]);
            fsplit2h(S[2 * jt + 1][2], S[2 * jt + 1][3], ph[3], pl[3]);
#pragma unroll
            for (int dc = 0; dc < 4; dc++) {
                uint32_t vbh[4], vbl[4];
                uint32_t rb = (uint32_t)((jt * 16 + a_r) * 128 + dc * 32 + a_c);
                ldm_x4t(vbh, Vhi + sw128(rb));
                ldm_x4t(vbl, Vlo + sw128(rb));
                mma16816(O[2 * dc],     ph, &vbh[0]);
                mma16816(O[2 * dc + 1], ph, &vbh[2]);
                mma16816(O[2 * dc],     ph, &vbl[0]);
                mma16816(O[2 * dc + 1], ph, &vbl[2]);
                mma16816(O[2 * dc],     pl, &vbh[0]);
                mma16816(O[2 * dc + 1], pl, &vbh[2]);
            }
        }

        /* write rows with fused conv (plain fp16 atts) */
#pragma unroll
        for (int rsel = 0; rsel < 2; rsel++) {
            const int m = rsel ? m1 : m0;
            if (m >= NTOK) continue;
            const float inv = rsel ? inv1 : inv0;
            const int qs = rsel * 2;
            const bool doconv = (m >= 1);
            int y = 0, x = 0;
            if (doconv) { y = (m - 1) / GRID14; x = (m - 1) % GRID14; }
            __half* rp = atts + (size_t)(b * NTOK + m) * KTOT + h * DH;
#pragma unroll
            for (int t = 0; t < 8; t++) {
                float v0 = O[t][qs] * inv;
                float v1 = O[t][qs + 1] * inv;
                const int d0 = (t >> 1) * 16 + (t & 1) * 8 + qc;
                if (doconv) {
                    float2 cv = bs2[d0 >> 1];
                    const float2* wp = ws2 + (d0 >> 1) * 9;
#pragma unroll
                    for (int ky = 0; ky < 3; ky++) {
                        int yy = y + ky - 1;
                        if (yy < 0 || yy >= GRID14) continue;
#pragma unroll
                        for (int kx = 0; kx < 3; kx++) {
                            int xx = x + kx - 1;
                            if (xx < 0 || xx >= GRID14) continue;
                            int j = 1 + yy * GRID14 + xx;
                            uint32_t off = sw128((uint32_t)(j * 128 + d0 * 2));
                            uint32_t vh, vl;
                            asm("ld.shared.b32 %0,[%1];" : "=r"(vh) : "r"(Vhi + off));
                            asm("ld.shared.b32 %0,[%1];" : "=r"(vl) : "r"(Vlo + off));
                            __half2 h2 = *reinterpret_cast<__half2*>(&vh);
                            __half2 l2 = *reinterpret_cast<__half2*>(&vl);
                            float2 wv = wp[ky * 3 + kx];
                            cv.x = fmaf(__half2float(h2.x) + __half2float(l2.x), wv.x, cv.x);
                            cv.y = fmaf(__half2float(h2.y) + __half2float(l2.y), wv.y, cv.y);
                        }
                    }
                    v0 += cv.x;
                    v1 += cv.y;
                }
                __half2 hv = __floats2half2_rn(v0, v1);
                *(uint32_t*)(rp + d0) = *reinterpret_cast<uint32_t*>(&hv);
            }
        }
    }
}

/* ---------------- launch --------------------------------------------------- */
extern "C" void kernel_launch(void* const* d_in, const int* in_sizes, int n_in,
                              void* d_out, int out_size)
{
    const float* x      = (const float*)d_in[0];
    const float* W_qkv  = (const float*)d_in[1];
    const float* b_qkv  = (const float*)d_in[2];
    const float* W_proj = (const float*)d_in[3];
    const float* b_proj = (const float*)d_in[4];
    const float* dwc_w  = (const float*)d_in[5];
    const float* dwc_b  = (const float*)d_in[6];
    float* out = (float*)d_out;

    float* qkv = nullptr;
    __half *xs = nullptr, *atts = nullptr, *wqkvs = nullptr, *wprojs = nullptr;
    cudaGetSymbolAddress((void**)&qkv, g_qkv);
    cudaGetSymbolAddress((void**)&xs, g_xs);
    cudaGetSymbolAddress((void**)&atts, g_atts);
    cudaGetSymbolAddress((void**)&wqkvs, g_wqkvs);
    cudaGetSymbolAddress((void**)&wprojs, g_wprojs);

    cudaFuncSetAttribute(attn_mma, cudaFuncAttributeMaxDynamicSharedMemorySize, ASMEM);
    cudaFuncSetAttribute(gemm_mma, cudaFuncAttributeMaxDynamicSharedMemorySize, GSMEM);

    xpack<<<(M_ROWS * KTOT) / 256, 256>>>(x, xs, M_ROWS * KTOT);
    wpack<<<(QKV_N * KTOT) / 256, 256>>>(W_qkv, wqkvs, QKV_N, QKV_N * KTOT);
    wpack<<<(CDIM * KTOT) / 256, 256>>>(W_proj, wprojs, CDIM, CDIM * KTOT);

    /* 1) qkv = x @ W_qkv + b_qkv */
    gemm_mma<<<dim3(QKV_N / TN, M_ROWS / TM), 256, GSMEM>>>(xs, wqkvs, b_qkv, qkv, QKV_N);

    /* 2) attention + fused depthwise conv -> atts (fp16) */
    attn_mma<<<BATCH * HEADS, 128, ASMEM>>>(qkv, dwc_w, dwc_b, atts);

    /* 3) out = (attn+conv) @ W_proj + b_proj */
    gemm_mma<<<dim3(CDIM / TN, M_ROWS / TM), 256, GSMEM>>>(atts, wprojs, b_proj, out, CDIM);
}

// round 9
// speedup vs baseline: 5.8570x; 1.0497x over previous
#include <cuda_runtime.h>
#include <cuda_fp16.h>
#include <cstdint>
#include <math.h>

#define BATCH 256
#define NTOK 197
#define CDIM 768
#define HEADS 12
#define DH 64
#define GRID14 14
#define M_ROWS (BATCH * NTOK)   /* 50432 = 394*128 */
#define QKV_N (3 * CDIM)        /* 2304 */
#define KTOT 768
#define ROWB (KTOT * 2)         /* 1536 bytes per fp16 row */

/* ---------------- scratch (__device__ globals; no allocs allowed) -------- */
__device__ float g_qkv[(size_t)M_ROWS * QKV_N];
__device__ __half g_xs[(size_t)M_ROWS * KTOT];       /* x fp16            */
__device__ __half g_atts[(size_t)M_ROWS * KTOT];     /* attn+conv fp16    */
__device__ __half g_wqkvs[(size_t)QKV_N * KTOT];     /* W_qkv^T fp16      */
__device__ __half g_wprojs[(size_t)CDIM * KTOT];     /* W_proj^T fp16     */

/* ---------------- helpers ------------------------------------------------- */
__device__ __forceinline__ uint32_t smem_u32(const void* p) {
    uint32_t a;
    asm("{ .reg .u64 t; cvta.to.shared.u64 t, %1; cvt.u32.u64 %0, t; }" : "=r"(a) : "l"(p));
    return a;
}
__device__ __forceinline__ uint32_t sw128(uint32_t o) { return o ^ ((o >> 3) & 0x70); }

__device__ __forceinline__ void cp16(uint32_t s, const void* g) {
    asm volatile("cp.async.cg.shared.global [%0], [%1], 16;" :: "r"(s), "l"(g));
}
__device__ __forceinline__ void ldm_x4(uint32_t* r, uint32_t a) {
    asm volatile("ldmatrix.sync.aligned.m8n8.x4.shared.b16 {%0,%1,%2,%3}, [%4];"
                 : "=r"(r[0]), "=r"(r[1]), "=r"(r[2]), "=r"(r[3]) : "r"(a));
}
__device__ __forceinline__ void ldm_x4t(uint32_t* r, uint32_t a) {
    asm volatile("ldmatrix.sync.aligned.m8n8.x4.trans.shared.b16 {%0,%1,%2,%3}, [%4];"
                 : "=r"(r[0]), "=r"(r[1]), "=r"(r[2]), "=r"(r[3]) : "r"(a));
}
__device__ __forceinline__ void mma16816(float* c, const uint32_t* a, const uint32_t* b) {
    asm volatile(
        "mma.sync.aligned.m16n8k16.row.col.f32.f16.f16.f32 "
        "{%0,%1,%2,%3}, {%4,%5,%6,%7}, {%8,%9}, {%0,%1,%2,%3};"
        : "+f"(c[0]), "+f"(c[1]), "+f"(c[2]), "+f"(c[3])
        : "r"(a[0]), "r"(a[1]), "r"(a[2]), "r"(a[3]), "r"(b[0]), "r"(b[1]));
}
__device__ __forceinline__ void fsplit2h(float x, float y, uint32_t& hi, uint32_t& lo) {
    __half hx = __float2half_rn(x), hy = __float2half_rn(y);
    __half lx = __float2half_rn(x - __half2float(hx));
    __half ly = __float2half_rn(y - __half2float(hy));
    __half2 th = __halves2half2(hx, hy);
    __half2 tl = __halves2half2(lx, ly);
    hi = *reinterpret_cast<uint32_t*>(&th);
    lo = *reinterpret_cast<uint32_t*>(&tl);
}

/* ---------------- prep kernels -------------------------------------------- */
__global__ __launch_bounds__(256) void xpack(const float* __restrict__ in,
                                             __half* __restrict__ out, int total)
{
    int idx = blockIdx.x * 256 + threadIdx.x;
    if (idx >= total) return;
    out[idx] = __float2half_rn(in[idx]);
}

__global__ __launch_bounds__(256) void wpack(const float* __restrict__ W,
                                             __half* __restrict__ out,
                                             int N, int total)
{
    int idx = blockIdx.x * 256 + threadIdx.x;
    if (idx >= total) return;
    int n = idx / KTOT, k = idx % KTOT;
    out[(size_t)n * KTOT + k] = __float2half_rn(W[(size_t)k * N + n]);
}

/* ---------------- fp16 GEMM: 128x128 tile, 4 warps, 2 CTAs/SM ------------- */
/* C[M,Nd] = A*B^T + bias.  K-stage 64 (128B SW128 rows), RING=3, PF=2.     */
#define TM 128
#define TN 128
#define NSTG 12                   /* 768 / 64 */
#define RING 3
#define PF 2
#define STG_A 16384               /* 128 rows * 128B */
#define STG_B 16384               /* 128 rows * 128B */
#define STG (STG_A + STG_B)       /* 32768 */
#define GSMEM (RING * STG)        /* 98304 -> 2 CTAs/SM */

__device__ __forceinline__ void load_stage(uint32_t sb, int buf, int st,
                                           const char* Ag, const char* Bg, int tid)
{
    uint32_t ab = sb + buf * STG;
    const char* a0 = Ag + (size_t)st * 128;
#pragma unroll
    for (int c = tid; c < 1024; c += 128) {
        int r = c >> 3, j = c & 7;
        cp16(ab + sw128(r * 128 + j * 16), a0 + (size_t)r * ROWB + j * 16);
    }
    uint32_t bb = ab + STG_A;
    const char* b0 = Bg + (size_t)st * 128;
#pragma unroll
    for (int c = tid; c < 1024; c += 128) {
        int r = c >> 3, j = c & 7;
        cp16(bb + sw128(r * 128 + j * 16), b0 + (size_t)r * ROWB + j * 16);
    }
    asm volatile("cp.async.commit_group;" ::: "memory");
}

__global__ __launch_bounds__(128, 2) void gemm_mma(
    const __half* __restrict__ As, const __half* __restrict__ Bs,
    const float* __restrict__ bias, float* __restrict__ C, int Nd)
{
    extern __shared__ __align__(1024) char smc[];
    uint32_t sb = smem_u32(smc);
    const int tid = threadIdx.x;
    const size_t bm = (size_t)blockIdx.y * TM;
    const size_t bn = (size_t)blockIdx.x * TN;
    const char* Ag = (const char*)As + bm * ROWB;
    const char* Bg = (const char*)Bs + bn * ROWB;

#pragma unroll
    for (int st = 0; st < PF; st++) load_stage(sb, st, st, Ag, Bg, tid);

    const int warp = tid >> 5, lane = tid & 31;
    const int wm = (warp >> 1) * 64;
    const int wn = (warp & 1) * 64;

    float acc[4][8][4];
#pragma unroll
    for (int i = 0; i < 4; i++)
#pragma unroll
        for (int j = 0; j < 8; j++)
#pragma unroll
            for (int q = 0; q < 4; q++) acc[i][j][q] = 0.f;

    const int a_r = lane & 15;
    const int a_c = (lane >> 4) << 4;
    const int b_r = (lane & 7) + ((lane >> 4) << 3);
    const int b_c = ((lane >> 3) & 1) << 4;

    for (int s = 0; s < NSTG; s++) {
        const int buf = s % RING;
        if (s < NSTG - 1) asm volatile("cp.async.wait_group 1;" ::: "memory");
        else              asm volatile("cp.async.wait_group 0;" ::: "memory");
        __syncthreads();
        if (s + PF < NSTG) load_stage(sb, (s + PF) % RING, s + PF, Ag, Bg, tid);

        uint32_t ab = sb + buf * STG;
        uint32_t bb = ab + STG_A;

#pragma unroll
        for (int t = 0; t < 4; t++) {
            uint32_t br[4][4];
#pragma unroll
            for (int j = 0; j < 4; j++) {
                int row = wn + j * 16 + b_r;
                ldm_x4(br[j], bb + sw128(row * 128 + t * 32 + b_c));
            }
            uint32_t ar[4][4];
#pragma unroll
            for (int i = 0; i < 4; i++) {
                int row = wm + i * 16 + a_r;
                ldm_x4(ar[i], ab + sw128(row * 128 + t * 32 + a_c));
            }
#pragma unroll
            for (int i = 0; i < 4; i++)
#pragma unroll
                for (int j = 0; j < 4; j++) {
                    mma16816(acc[i][2 * j + 0], ar[i], &br[j][0]);
                    mma16816(acc[i][2 * j + 1], ar[i], &br[j][2]);
                }
        }
    }

    const int r0 = lane >> 2;
    const int c0 = (lane & 3) * 2;
    const size_t grow = bm + wm + r0;
    const int gcol = (int)bn + wn + c0;

    float2 bv[8];
#pragma unroll
    for (int j = 0; j < 8; j++)
        bv[j] = *(const float2*)(bias + gcol + j * 8);

#pragma unroll
    for (int i = 0; i < 4; i++) {
        float* cp0 = C + (grow + i * 16) * Nd + gcol;
        float* cp1 = cp0 + (size_t)8 * Nd;
#pragma unroll
        for (int j = 0; j < 8; j++) {
            *(float2*)(cp0 + j * 8) = make_float2(acc[i][j][0] + bv[j].x, acc[i][j][1] + bv[j].y);
            *(float2*)(cp1 + j * 8) = make_float2(acc[i][j][2] + bv[j].x, acc[i][j][3] + bv[j].y);
        }
    }
}

/* ---------------- tensor-core attention + fused depthwise conv ------------- */
#define NPAD 208
#define ACHB (NPAD * 128)           /* 26624 */
#define WS_OFF (3 * ACHB)
#define BS_OFF (WS_OFF + 2304)
#define ASMEM (BS_OFF + 256)        /* 82432 */

__global__ __launch_bounds__(128, 2) void attn_mma(const float* __restrict__ qkv,
                                                   const float* __restrict__ dwc_w,
                                                   const float* __restrict__ dwc_b,
                                                   __half* __restrict__ atts)
{
    extern __shared__ __align__(1024) char smem[];
    uint32_t sbase = smem_u32(smem);
    const uint32_t Ksm = sbase, Vhi = sbase + ACHB, Vlo = sbase + 2 * ACHB;
    float2* ws2 = (float2*)(smem + WS_OFF);
    float2* bs2 = (float2*)(smem + BS_OFF);
    const int b = blockIdx.x / HEADS, h = blockIdx.x % HEADS;
    const int tid = threadIdx.x;
    const float* base = qkv + (size_t)b * NTOK * QKV_N + h * DH;

    for (int i = tid; i < 288; i += 128) {
        int pair = i / 9, tap = i % 9;
        int c = h * 64 + pair * 2;
        ws2[i] = make_float2(dwc_w[(size_t)c * 9 + tap], dwc_w[(size_t)(c + 1) * 9 + tap]);
    }
    if (tid < 32) bs2[tid] = make_float2(dwc_b[h * 64 + tid * 2], dwc_b[h * 64 + tid * 2 + 1]);

    for (int idx = tid; idx < NPAD * 32; idx += 128) {
        int j = idx >> 5, dp = idx & 31;
        float2 kv = make_float2(0.f, 0.f), vv = make_float2(0.f, 0.f);
        if (j < NTOK) {
            const float* p = base + (size_t)j * QKV_N + dp * 2;
            kv = *(const float2*)(p + CDIM);
            vv = *(const float2*)(p + 2 * CDIM);
        }
        uint32_t off = sw128((uint32_t)(j * 128 + dp * 4));
        __half2 k2 = __floats2half2_rn(kv.x, kv.y);
        uint32_t ku = *reinterpret_cast<uint32_t*>(&k2);
        uint32_t vhu, vlu;
        fsplit2h(vv.x, vv.y, vhu, vlu);
        asm volatile("st.shared.b32 [%0], %1;" :: "r"(Ksm + off), "r"(ku) : "memory");
        asm volatile("st.shared.b32 [%0], %1;" :: "r"(Vhi + off), "r"(vhu) : "memory");
        asm volatile("st.shared.b32 [%0], %1;" :: "r"(Vlo + off), "r"(vlu) : "memory");
    }
    __syncthreads();

    const int lane = tid & 31, warp = tid >> 5;
    const int qr = lane >> 2;
    const int qc = (lane & 3) * 2;
    const int b_r = (lane & 7) + ((lane >> 4) << 3);
    const int b_c = ((lane >> 3) & 1) << 4;
    const int a_r = lane & 15;
    const int a_c = (lane >> 4) << 4;

    for (int s = warp; s < 13; s += 4) {
        const int m0 = s * 16 + qr;
        const int m1 = m0 + 8;
        const int rm0 = m0 < NTOK ? m0 : NTOK - 1;
        const int rm1 = m1 < NTOK ? m1 : NTOK - 1;

        uint32_t qh[4][4], ql[4][4];
        const float* q0 = base + (size_t)rm0 * QKV_N;
        const float* q1 = base + (size_t)rm1 * QKV_N;
#pragma unroll
        for (int kt = 0; kt < 4; kt++) {
            int c = kt * 16 + qc;
            float2 p00 = *(const float2*)(q0 + c);
            float2 p10 = *(const float2*)(q1 + c);
            float2 p01 = *(const float2*)(q0 + c + 8);
            float2 p11 = *(const float2*)(q1 + c + 8);
            fsplit2h(p00.x, p00.y, qh[kt][0], ql[kt][0]);
            fsplit2h(p10.x, p10.y, qh[kt][1], ql[kt][1]);
            fsplit2h(p01.x, p01.y, qh[kt][2], ql[kt][2]);
            fsplit2h(p11.x, p11.y, qh[kt][3], ql[kt][3]);
        }

        float S[26][4];
#pragma unroll
        for (int t = 0; t < 26; t++)
#pragma unroll
            for (int q = 0; q < 4; q++) S[t][q] = 0.f;

#pragma unroll
        for (int nc = 0; nc < 13; nc++) {
#pragma unroll
            for (int kt = 0; kt < 4; kt++) {
                uint32_t kb[4];
                ldm_x4(kb, Ksm + sw128((uint32_t)((nc * 16 + b_r) * 128 + kt * 32 + b_c)));
                mma16816(S[2 * nc],     qh[kt], &kb[0]);
                mma16816(S[2 * nc + 1], qh[kt], &kb[2]);
                mma16816(S[2 * nc],     ql[kt], &kb[0]);
                mma16816(S[2 * nc + 1], ql[kt], &kb[2]);
            }
        }

#pragma unroll
        for (int t = 24; t < 26; t++) {
            int j0 = t * 8 + qc;
            if (j0 >= NTOK)     S[t][0] = S[t][2] = -1e30f;
            if (j0 + 1 >= NTOK) S[t][1] = S[t][3] = -1e30f;
        }

        float mx0 = -1e30f, mx1 = -1e30f;
#pragma unroll
        for (int t = 0; t < 26; t++) {
            mx0 = fmaxf(mx0, fmaxf(S[t][0], S[t][1]));
            mx1 = fmaxf(mx1, fmaxf(S[t][2], S[t][3]));
        }
        mx0 = fmaxf(mx0, __shfl_xor_sync(0xffffffffu, mx0, 1));
        mx0 = fmaxf(mx0, __shfl_xor_sync(0xffffffffu, mx0, 2));
        mx1 = fmaxf(mx1, __shfl_xor_sync(0xffffffffu, mx1, 1));
        mx1 = fmaxf(mx1, __shfl_xor_sync(0xffffffffu, mx1, 2));
        float sum0 = 0.f, sum1 = 0.f;
#pragma unroll
        for (int t = 0; t < 26; t++) {
            S[t][0] = __expf((S[t][0] - mx0) * 0.125f);
            S[t][1] = __expf((S[t][1] - mx0) * 0.125f);
            S[t][2] = __expf((S[t][2] - mx1) * 0.125f);
            S[t][3] = __expf((S[t][3] - mx1) * 0.125f);
            sum0 += S[t][0] + S[t][1];
            sum1 += S[t][2] + S[t][3];
        }
        sum0 += __shfl_xor_sync(0xffffffffu, sum0, 1);
        sum0 += __shfl_xor_sync(0xffffffffu, sum0, 2);
        sum1 += __shfl_xor_sync(0xffffffffu, sum1, 1);
        sum1 += __shfl_xor_sync(0xffffffffu, sum1, 2);
        float inv0 = __frcp_rn(sum0), inv1 = __frcp_rn(sum1);

        float O[8][4];
#pragma unroll
        for (int t = 0; t < 8; t++)
#pragma unroll
            for (int q = 0; q < 4; q++) O[t][q] = 0.f;

#pragma unroll
        for (int jt = 0; jt < 13; jt++) {
            uint32_t ph[4], pl[4];
            fsplit2h(S[2 * jt][0],     S[2 * jt][1],     ph[0], pl[0]);
            fsplit2h(S[2 * jt][2],     S[2 * jt][3],     ph[1], pl[1]);
            fsplit2h(S[2 * jt + 1][0], S[2 * jt + 1][1], ph[2], pl[2]);
            fsplit2h(S[2 * jt + 1][2], S[2 * jt + 1][3], ph[3], pl[3]);
#pragma unroll
            for (int dc = 0; dc < 4; dc++) {
                uint32_t vbh[4], vbl[4];
                uint32_t rb = (uint32_t)((jt * 16 + a_r) * 128 + dc * 32 + a_c);
                ldm_x4t(vbh, Vhi + sw128(rb));
                ldm_x4t(vbl, Vlo + sw128(rb));
                mma16816(O[2 * dc],     ph, &vbh[0]);
                mma16816(O[2 * dc + 1], ph, &vbh[2]);
                mma16816(O[2 * dc],     ph, &vbl[0]);
                mma16816(O[2 * dc + 1], ph, &vbl[2]);
                mma16816(O[2 * dc],     pl, &vbh[0]);
                mma16816(O[2 * dc + 1], pl, &vbh[2]);
            }
        }

        /* write rows with fused conv (plain fp16 atts) */
#pragma unroll
        for (int rsel = 0; rsel < 2; rsel++) {
            const int m = rsel ? m1 : m0;
            if (m >= NTOK) continue;
            const float inv = rsel ? inv1 : inv0;
            const int qs = rsel * 2;
            const bool doconv = (m >= 1);
            int y = 0, x = 0;
            if (doconv) { y = (m - 1) / GRID14; x = (m - 1) % GRID14; }
            __half* rp = atts + (size_t)(b * NTOK + m) * KTOT + h * DH;
#pragma unroll
            for (int t = 0; t < 8; t++) {
                float v0 = O[t][qs] * inv;
                float v1 = O[t][qs + 1] * inv;
                const int d0 = (t >> 1) * 16 + (t & 1) * 8 + qc;
                if (doconv) {
                    float2 cv = bs2[d0 >> 1];
                    const float2* wp = ws2 + (d0 >> 1) * 9;
#pragma unroll
                    for (int ky = 0; ky < 3; ky++) {
                        int yy = y + ky - 1;
                        if (yy < 0 || yy >= GRID14) continue;
#pragma unroll
                        for (int kx = 0; kx < 3; kx++) {
                            int xx = x + kx - 1;
                            if (xx < 0 || xx >= GRID14) continue;
                            int j = 1 + yy * GRID14 + xx;
                            uint32_t off = sw128((uint32_t)(j * 128 + d0 * 2));
                            uint32_t vh, vl;
                            asm("ld.shared.b32 %0,[%1];" : "=r"(vh) : "r"(Vhi + off));
                            asm("ld.shared.b32 %0,[%1];" : "=r"(vl) : "r"(Vlo + off));
                            __half2 h2 = *reinterpret_cast<__half2*>(&vh);
                            __half2 l2 = *reinterpret_cast<__half2*>(&vl);
                            float2 wv = wp[ky * 3 + kx];
                            cv.x = fmaf(__half2float(h2.x) + __half2float(l2.x), wv.x, cv.x);
                            cv.y = fmaf(__half2float(h2.y) + __half2float(l2.y), wv.y, cv.y);
                        }
                    }
                    v0 += cv.x;
                    v1 += cv.y;
                }
                __half2 hv = __floats2half2_rn(v0, v1);
                *(uint32_t*)(rp + d0) = *reinterpret_cast<uint32_t*>(&hv);
            }
        }
    }
}

/* ---------------- launch --------------------------------------------------- */
extern "C" void kernel_launch(void* const* d_in, const int* in_sizes, int n_in,
                              void* d_out, int out_size)
{
    const float* x      = (const float*)d_in[0];
    const float* W_qkv  = (const float*)d_in[1];
    const float* b_qkv  = (const float*)d_in[2];
    const float* W_proj = (const float*)d_in[3];
    const float* b_proj = (const float*)d_in[4];
    const float* dwc_w  = (const float*)d_in[5];
    const float* dwc_b  = (const float*)d_in[6];
    float* out = (float*)d_out;

    float* qkv = nullptr;
    __half *xs = nullptr, *atts = nullptr, *wqkvs = nullptr, *wprojs = nullptr;
    cudaGetSymbolAddress((void**)&qkv, g_qkv);
    cudaGetSymbolAddress((void**)&xs, g_xs);
    cudaGetSymbolAddress((void**)&atts, g_atts);
    cudaGetSymbolAddress((void**)&wqkvs, g_wqkvs);
    cudaGetSymbolAddress((void**)&wprojs, g_wprojs);

    cudaFuncSetAttribute(attn_mma, cudaFuncAttributeMaxDynamicSharedMemorySize, ASMEM);
    cudaFuncSetAttribute(gemm_mma, cudaFuncAttributeMaxDynamicSharedMemorySize, GSMEM);

    xpack<<<(M_ROWS * KTOT) / 256, 256>>>(x, xs, M_ROWS * KTOT);
    wpack<<<(QKV_N * KTOT) / 256, 256>>>(W_qkv, wqkvs, QKV_N, QKV_N * KTOT);
    wpack<<<(CDIM * KTOT) / 256, 256>>>(W_proj, wprojs, CDIM, CDIM * KTOT);

    /* 1) qkv = x @ W_qkv + b_qkv */
    gemm_mma<<<dim3(QKV_N / TN, M_ROWS / TM), 128, GSMEM>>>(xs, wqkvs, b_qkv, qkv, QKV_N);

    /* 2) attention + fused depthwise conv -> atts (fp16) */
    attn_mma<<<BATCH * HEADS, 128, ASMEM>>>(qkv, dwc_w, dwc_b, atts);

    /* 3) out = (attn+conv) @ W_proj + b_proj */
    gemm_mma<<<dim3(CDIM / TN, M_ROWS / TM), 128, GSMEM>>>(atts, wprojs, b_proj, out, CDIM);
}

// round 10
// speedup vs baseline: 6.4192x; 1.0960x over previous
#include <cuda_runtime.h>
#include <cuda_fp16.h>
#include <cstdint>
#include <math.h>

#define BATCH 256
#define NTOK 197
#define CDIM 768
#define HEADS 12
#define DH 64
#define GRID14 14
#define M_ROWS (BATCH * NTOK)   /* 50432 = 394*128 */
#define QKV_N (3 * CDIM)        /* 2304 */
#define KTOT 768
#define ROWB (KTOT * 2)         /* 1536 bytes per fp16 row */

/* ---------------- scratch (__device__ globals; no allocs allowed) -------- */
__device__ __half g_qkv[(size_t)M_ROWS * QKV_N];     /* qkv fp16          */
__device__ __half g_xs[(size_t)M_ROWS * KTOT];       /* x fp16            */
__device__ __half g_atts[(size_t)M_ROWS * KTOT];     /* attn+conv fp16    */
__device__ __half g_wqkvs[(size_t)QKV_N * KTOT];     /* W_qkv^T fp16      */
__device__ __half g_wprojs[(size_t)CDIM * KTOT];     /* W_proj^T fp16     */

/* ---------------- helpers ------------------------------------------------- */
__device__ __forceinline__ uint32_t smem_u32(const void* p) {
    uint32_t a;
    asm("{ .reg .u64 t; cvta.to.shared.u64 t, %1; cvt.u32.u64 %0, t; }" : "=r"(a) : "l"(p));
    return a;
}
__device__ __forceinline__ uint32_t sw128(uint32_t o) { return o ^ ((o >> 3) & 0x70); }

__device__ __forceinline__ void cp16(uint32_t s, const void* g) {
    asm volatile("cp.async.cg.shared.global [%0], [%1], 16;" :: "r"(s), "l"(g));
}
__device__ __forceinline__ void ldm_x4(uint32_t* r, uint32_t a) {
    asm volatile("ldmatrix.sync.aligned.m8n8.x4.shared.b16 {%0,%1,%2,%3}, [%4];"
                 : "=r"(r[0]), "=r"(r[1]), "=r"(r[2]), "=r"(r[3]) : "r"(a));
}
__device__ __forceinline__ void ldm_x4t(uint32_t* r, uint32_t a) {
    asm volatile("ldmatrix.sync.aligned.m8n8.x4.trans.shared.b16 {%0,%1,%2,%3}, [%4];"
                 : "=r"(r[0]), "=r"(r[1]), "=r"(r[2]), "=r"(r[3]) : "r"(a));
}
__device__ __forceinline__ void mma16816(float* c, const uint32_t* a, const uint32_t* b) {
    asm volatile(
        "mma.sync.aligned.m16n8k16.row.col.f32.f16.f16.f32 "
        "{%0,%1,%2,%3}, {%4,%5,%6,%7}, {%8,%9}, {%0,%1,%2,%3};"
        : "+f"(c[0]), "+f"(c[1]), "+f"(c[2]), "+f"(c[3])
        : "r"(a[0]), "r"(a[1]), "r"(a[2]), "r"(a[3]), "r"(b[0]), "r"(b[1]));
}
__device__ __forceinline__ void fsplit2h(float x, float y, uint32_t& hi, uint32_t& lo) {
    __half hx = __float2half_rn(x), hy = __float2half_rn(y);
    __half lx = __float2half_rn(x - __half2float(hx));
    __half ly = __float2half_rn(y - __half2float(hy));
    __half2 th = __halves2half2(hx, hy);
    __half2 tl = __halves2half2(lx, ly);
    hi = *reinterpret_cast<uint32_t*>(&th);
    lo = *reinterpret_cast<uint32_t*>(&tl);
}
/* output-type-dispatched pair store */
__device__ __forceinline__ void store2(float* p, float a, float b) {
    *(float2*)p = make_float2(a, b);
}
__device__ __forceinline__ void store2(__half* p, float a, float b) {
    __half2 h = __floats2half2_rn(a, b);
    *(uint32_t*)p = *reinterpret_cast<uint32_t*>(&h);
}

/* ---------------- prep kernels -------------------------------------------- */
__global__ __launch_bounds__(256) void xpack(const float* __restrict__ in,
                                             __half* __restrict__ out, int total)
{
    int idx = blockIdx.x * 256 + threadIdx.x;
    if (idx >= total) return;
    out[idx] = __float2half_rn(in[idx]);
}

__global__ __launch_bounds__(256) void wpack(const float* __restrict__ W,
                                             __half* __restrict__ out,
                                             int N, int total)
{
    int idx = blockIdx.x * 256 + threadIdx.x;
    if (idx >= total) return;
    int n = idx / KTOT, k = idx % KTOT;
    out[(size_t)n * KTOT + k] = __float2half_rn(W[(size_t)k * N + n]);
}

/* ---------------- fp16 GEMM: 128x128 tile, 4 warps, 2 CTAs/SM ------------- */
#define TM 128
#define TN 128
#define NSTG 12                   /* 768 / 64 */
#define RING 3
#define PF 2
#define STG_A 16384
#define STG_B 16384
#define STG (STG_A + STG_B)       /* 32768 */
#define GSMEM (RING * STG)        /* 98304 -> 2 CTAs/SM */

__device__ __forceinline__ void load_stage(uint32_t sb, int buf, int st,
                                           const char* Ag, const char* Bg, int tid)
{
    uint32_t ab = sb + buf * STG;
    const char* a0 = Ag + (size_t)st * 128;
#pragma unroll
    for (int c = tid; c < 1024; c += 128) {
        int r = c >> 3, j = c & 7;
        cp16(ab + sw128(r * 128 + j * 16), a0 + (size_t)r * ROWB + j * 16);
    }
    uint32_t bb = ab + STG_A;
    const char* b0 = Bg + (size_t)st * 128;
#pragma unroll
    for (int c = tid; c < 1024; c += 128) {
        int r = c >> 3, j = c & 7;
        cp16(bb + sw128(r * 128 + j * 16), b0 + (size_t)r * ROWB + j * 16);
    }
    asm volatile("cp.async.commit_group;" ::: "memory");
}

template <typename OutT>
__global__ __launch_bounds__(128, 2) void gemm_mma(
    const __half* __restrict__ As, const __half* __restrict__ Bs,
    const float* __restrict__ bias, OutT* __restrict__ C, int Nd)
{
    extern __shared__ __align__(1024) char smc[];
    uint32_t sb = smem_u32(smc);
    const int tid = threadIdx.x;
    const size_t bm = (size_t)blockIdx.y * TM;
    const size_t bn = (size_t)blockIdx.x * TN;
    const char* Ag = (const char*)As + bm * ROWB;
    const char* Bg = (const char*)Bs + bn * ROWB;

#pragma unroll
    for (int st = 0; st < PF; st++) load_stage(sb, st, st, Ag, Bg, tid);

    const int warp = tid >> 5, lane = tid & 31;
    const int wm = (warp >> 1) * 64;
    const int wn = (warp & 1) * 64;

    float acc[4][8][4];
#pragma unroll
    for (int i = 0; i < 4; i++)
#pragma unroll
        for (int j = 0; j < 8; j++)
#pragma unroll
            for (int q = 0; q < 4; q++) acc[i][j][q] = 0.f;

    const int a_r = lane & 15;
    const int a_c = (lane >> 4) << 4;
    const int b_r = (lane & 7) + ((lane >> 4) << 3);
    const int b_c = ((lane >> 3) & 1) << 4;

    for (int s = 0; s < NSTG; s++) {
        const int buf = s % RING;
        if (s < NSTG - 1) asm volatile("cp.async.wait_group 1;" ::: "memory");
        else              asm volatile("cp.async.wait_group 0;" ::: "memory");
        __syncthreads();
        if (s + PF < NSTG) load_stage(sb, (s + PF) % RING, s + PF, Ag, Bg, tid);

        uint32_t ab = sb + buf * STG;
        uint32_t bb = ab + STG_A;

#pragma unroll
        for (int t = 0; t < 4; t++) {
            uint32_t br[4][4];
#pragma unroll
            for (int j = 0; j < 4; j++) {
                int row = wn + j * 16 + b_r;
                ldm_x4(br[j], bb + sw128(row * 128 + t * 32 + b_c));
            }
            uint32_t ar[4][4];
#pragma unroll
            for (int i = 0; i < 4; i++) {
                int row = wm + i * 16 + a_r;
                ldm_x4(ar[i], ab + sw128(row * 128 + t * 32 + a_c));
            }
#pragma unroll
            for (int i = 0; i < 4; i++)
#pragma unroll
                for (int j = 0; j < 4; j++) {
                    mma16816(acc[i][2 * j + 0], ar[i], &br[j][0]);
                    mma16816(acc[i][2 * j + 1], ar[i], &br[j][2]);
                }
        }
    }

    const int r0 = lane >> 2;
    const int c0 = (lane & 3) * 2;
    const size_t grow = bm + wm + r0;
    const int gcol = (int)bn + wn + c0;

    float2 bv[8];
#pragma unroll
    for (int j = 0; j < 8; j++)
        bv[j] = *(const float2*)(bias + gcol + j * 8);

#pragma unroll
    for (int i = 0; i < 4; i++) {
        OutT* cp0 = C + (grow + i * 16) * Nd + gcol;
        OutT* cp1 = cp0 + (size_t)8 * Nd;
#pragma unroll
        for (int j = 0; j < 8; j++) {
            store2(cp0 + j * 8, acc[i][j][0] + bv[j].x, acc[i][j][1] + bv[j].y);
            store2(cp1 + j * 8, acc[i][j][2] + bv[j].x, acc[i][j][3] + bv[j].y);
        }
    }
}

/* ---------------- tensor-core attention + fused depthwise conv ------------- */
/* One CTA per (b,h).  qkv already fp16: K,V copy-through to SW128 smem.     */
/* QK^T 1-term (fp16 Q), PV 2-term (P split x single-fp16 V).               */
#define NPAD 208
#define ACHB (NPAD * 128)           /* 26624 */
#define WS_OFF (2 * ACHB)
#define BS_OFF (WS_OFF + 2304)
#define ASMEM (BS_OFF + 256)        /* 55812 -> plenty for 2 CTAs/SM */

__global__ __launch_bounds__(128, 2) void attn_mma(const __half* __restrict__ qkv,
                                                   const float* __restrict__ dwc_w,
                                                   const float* __restrict__ dwc_b,
                                                   __half* __restrict__ atts)
{
    extern __shared__ __align__(1024) char smem[];
    uint32_t sbase = smem_u32(smem);
    const uint32_t Ksm = sbase, Vsm = sbase + ACHB;
    float2* ws2 = (float2*)(smem + WS_OFF);
    float2* bs2 = (float2*)(smem + BS_OFF);
    const int b = blockIdx.x / HEADS, h = blockIdx.x % HEADS;
    const int tid = threadIdx.x;
    const __half* base = qkv + (size_t)b * NTOK * QKV_N + h * DH;

    for (int i = tid; i < 288; i += 128) {
        int pair = i / 9, tap = i % 9;
        int c = h * 64 + pair * 2;
        ws2[i] = make_float2(dwc_w[(size_t)c * 9 + tap], dwc_w[(size_t)(c + 1) * 9 + tap]);
    }
    if (tid < 32) bs2[tid] = make_float2(dwc_b[h * 64 + tid * 2], dwc_b[h * 64 + tid * 2 + 1]);

    /* stage K,V (copy-through fp16; rows >= NTOK zeroed) */
    for (int idx = tid; idx < NPAD * 32; idx += 128) {
        int j = idx >> 5, dp = idx & 31;
        uint32_t kw = 0u, vw = 0u;
        if (j < NTOK) {
            const __half* p = base + (size_t)j * QKV_N + dp * 2;
            kw = *(const uint32_t*)(p + CDIM);
            vw = *(const uint32_t*)(p + 2 * CDIM);
        }
        uint32_t off = sw128((uint32_t)(j * 128 + dp * 4));
        asm volatile("st.shared.b32 [%0], %1;" :: "r"(Ksm + off), "r"(kw) : "memory");
        asm volatile("st.shared.b32 [%0], %1;" :: "r"(Vsm + off), "r"(vw) : "memory");
    }
    __syncthreads();

    const int lane = tid & 31, warp = tid >> 5;
    const int qr = lane >> 2;
    const int qc = (lane & 3) * 2;
    const int b_r = (lane & 7) + ((lane >> 4) << 3);
    const int b_c = ((lane >> 3) & 1) << 4;
    const int a_r = lane & 15;
    const int a_c = (lane >> 4) << 4;

    for (int s = warp; s < 13; s += 4) {
        const int m0 = s * 16 + qr;
        const int m1 = m0 + 8;
        const int rm0 = m0 < NTOK ? m0 : NTOK - 1;
        const int rm1 = m1 < NTOK ? m1 : NTOK - 1;

        /* Q fragments straight from fp16 global */
        uint32_t qh[4][4];
        const __half* q0 = base + (size_t)rm0 * QKV_N;
        const __half* q1 = base + (size_t)rm1 * QKV_N;
#pragma unroll
        for (int kt = 0; kt < 4; kt++) {
            int c = kt * 16 + qc;
            qh[kt][0] = *(const uint32_t*)(q0 + c);
            qh[kt][1] = *(const uint32_t*)(q1 + c);
            qh[kt][2] = *(const uint32_t*)(q0 + c + 8);
            qh[kt][3] = *(const uint32_t*)(q1 + c + 8);
        }

        float S[26][4];
#pragma unroll
        for (int t = 0; t < 26; t++)
#pragma unroll
            for (int q = 0; q < 4; q++) S[t][q] = 0.f;

#pragma unroll
        for (int nc = 0; nc < 13; nc++) {
#pragma unroll
            for (int kt = 0; kt < 4; kt++) {
                uint32_t kb[4];
                ldm_x4(kb, Ksm + sw128((uint32_t)((nc * 16 + b_r) * 128 + kt * 32 + b_c)));
                mma16816(S[2 * nc],     qh[kt], &kb[0]);
                mma16816(S[2 * nc + 1], qh[kt], &kb[2]);
            }
        }

#pragma unroll
        for (int t = 24; t < 26; t++) {
            int j0 = t * 8 + qc;
            if (j0 >= NTOK)     S[t][0] = S[t][2] = -1e30f;
            if (j0 + 1 >= NTOK) S[t][1] = S[t][3] = -1e30f;
        }

        float mx0 = -1e30f, mx1 = -1e30f;
#pragma unroll
        for (int t = 0; t < 26; t++) {
            mx0 = fmaxf(mx0, fmaxf(S[t][0], S[t][1]));
            mx1 = fmaxf(mx1, fmaxf(S[t][2], S[t][3]));
        }
        mx0 = fmaxf(mx0, __shfl_xor_sync(0xffffffffu, mx0, 1));
        mx0 = fmaxf(mx0, __shfl_xor_sync(0xffffffffu, mx0, 2));
        mx1 = fmaxf(mx1, __shfl_xor_sync(0xffffffffu, mx1, 1));
        mx1 = fmaxf(mx1, __shfl_xor_sync(0xffffffffu, mx1, 2));
        float sum0 = 0.f, sum1 = 0.f;
#pragma unroll
        for (int t = 0; t < 26; t++) {
            S[t][0] = __expf((S[t][0] - mx0) * 0.125f);
            S[t][1] = __expf((S[t][1] - mx0) * 0.125f);
            S[t][2] = __expf((S[t][2] - mx1) * 0.125f);
            S[t][3] = __expf((S[t][3] - mx1) * 0.125f);
            sum0 += S[t][0] + S[t][1];
            sum1 += S[t][2] + S[t][3];
        }
        sum0 += __shfl_xor_sync(0xffffffffu, sum0, 1);
        sum0 += __shfl_xor_sync(0xffffffffu, sum0, 2);
        sum1 += __shfl_xor_sync(0xffffffffu, sum1, 1);
        sum1 += __shfl_xor_sync(0xffffffffu, sum1, 2);
        float inv0 = __frcp_rn(sum0), inv1 = __frcp_rn(sum1);

        float O[8][4];
#pragma unroll
        for (int t = 0; t < 8; t++)
#pragma unroll
            for (int q = 0; q < 4; q++) O[t][q] = 0.f;

#pragma unroll
        for (int jt = 0; jt < 13; jt++) {
            uint32_t ph[4], pl[4];
            fsplit2h(S[2 * jt][0],     S[2 * jt][1],     ph[0], pl[0]);
            fsplit2h(S[2 * jt][2],     S[2 * jt][3],     ph[1], pl[1]);
            fsplit2h(S[2 * jt + 1][0], S[2 * jt + 1][1], ph[2], pl[2]);
            fsplit2h(S[2 * jt + 1][2], S[2 * jt + 1][3], ph[3], pl[3]);
#pragma unroll
            for (int dc = 0; dc < 4; dc++) {
                uint32_t vb[4];
                uint32_t rb = (uint32_t)((jt * 16 + a_r) * 128 + dc * 32 + a_c);
                ldm_x4t(vb, Vsm + sw128(rb));
                mma16816(O[2 * dc],     ph, &vb[0]);
                mma16816(O[2 * dc + 1], ph, &vb[2]);
                mma16816(O[2 * dc],     pl, &vb[0]);
                mma16816(O[2 * dc + 1], pl, &vb[2]);
            }
        }

        /* write rows with fused conv (plain fp16 atts) */
#pragma unroll
        for (int rsel = 0; rsel < 2; rsel++) {
            const int m = rsel ? m1 : m0;
            if (m >= NTOK) continue;
            const float inv = rsel ? inv1 : inv0;
            const int qs = rsel * 2;
            const bool doconv = (m >= 1);
            int y = 0, x = 0;
            if (doconv) { y = (m - 1) / GRID14; x = (m - 1) % GRID14; }
            __half* rp = atts + (size_t)(b * NTOK + m) * KTOT + h * DH;
#pragma unroll
            for (int t = 0; t < 8; t++) {
                float v0 = O[t][qs] * inv;
                float v1 = O[t][qs + 1] * inv;
                const int d0 = (t >> 1) * 16 + (t & 1) * 8 + qc;
                if (doconv) {
                    float2 cv = bs2[d0 >> 1];
                    const float2* wp = ws2 + (d0 >> 1) * 9;
#pragma unroll
                    for (int ky = 0; ky < 3; ky++) {
                        int yy = y + ky - 1;
                        if (yy < 0 || yy >= GRID14) continue;
#pragma unroll
                        for (int kx = 0; kx < 3; kx++) {
                            int xx = x + kx - 1;
                            if (xx < 0 || xx >= GRID14) continue;
                            int j = 1 + yy * GRID14 + xx;
                            uint32_t off = sw128((uint32_t)(j * 128 + d0 * 2));
                            uint32_t vh;
                            asm("ld.shared.b32 %0,[%1];" : "=r"(vh) : "r"(Vsm + off));
                            __half2 h2 = *reinterpret_cast<__half2*>(&vh);
                            float2 wv = wp[ky * 3 + kx];
                            cv.x = fmaf(__half2float(h2.x), wv.x, cv.x);
                            cv.y = fmaf(__half2float(h2.y), wv.y, cv.y);
                        }
                    }
                    v0 += cv.x;
                    v1 += cv.y;
                }
                __half2 hv = __floats2half2_rn(v0, v1);
                *(uint32_t*)(rp + d0) = *reinterpret_cast<uint32_t*>(&hv);
            }
        }
    }
}

/* ---------------- launch --------------------------------------------------- */
extern "C" void kernel_launch(void* const* d_in, const int* in_sizes, int n_in,
                              void* d_out, int out_size)
{
    const float* x      = (const float*)d_in[0];
    const float* W_qkv  = (const float*)d_in[1];
    const float* b_qkv  = (const float*)d_in[2];
    const float* W_proj = (const float*)d_in[3];
    const float* b_proj = (const float*)d_in[4];
    const float* dwc_w  = (const float*)d_in[5];
    const float* dwc_b  = (const float*)d_in[6];
    float* out = (float*)d_out;

    __half *qkv = nullptr, *xs = nullptr, *atts = nullptr, *wqkvs = nullptr, *wprojs = nullptr;
    cudaGetSymbolAddress((void**)&qkv, g_qkv);
    cudaGetSymbolAddress((void**)&xs, g_xs);
    cudaGetSymbolAddress((void**)&atts, g_atts);
    cudaGetSymbolAddress((void**)&wqkvs, g_wqkvs);
    cudaGetSymbolAddress((void**)&wprojs, g_wprojs);

    cudaFuncSetAttribute(attn_mma, cudaFuncAttributeMaxDynamicSharedMemorySize, ASMEM);
    cudaFuncSetAttribute(gemm_mma<__half>, cudaFuncAttributeMaxDynamicSharedMemorySize, GSMEM);
    cudaFuncSetAttribute(gemm_mma<float>, cudaFuncAttributeMaxDynamicSharedMemorySize, GSMEM);

    xpack<<<(M_ROWS * KTOT) / 256, 256>>>(x, xs, M_ROWS * KTOT);
    wpack<<<(QKV_N * KTOT) / 256, 256>>>(W_qkv, wqkvs, QKV_N, QKV_N * KTOT);
    wpack<<<(CDIM * KTOT) / 256, 256>>>(W_proj, wprojs, CDIM, CDIM * KTOT);

    /* 1) qkv = x @ W_qkv + b_qkv  (fp16 output) */
    gemm_mma<__half><<<dim3(QKV_N / TN, M_ROWS / TM), 128, GSMEM>>>(xs, wqkvs, b_qkv, qkv, QKV_N);

    /* 2) attention + fused depthwise conv -> atts (fp16) */
    attn_mma<<<BATCH * HEADS, 128, ASMEM>>>(qkv, dwc_w, dwc_b, atts);

    /* 3) out = (attn+conv) @ W_proj + b_proj  (fp32 output) */
    gemm_mma<float><<<dim3(CDIM / TN, M_ROWS / TM), 128, GSMEM>>>(atts, wprojs, b_proj, out, CDIM);
}

// round 11
// speedup vs baseline: 6.5688x; 1.0233x over previous
#include <cuda_runtime.h>
#include <cuda_fp16.h>
#include <cstdint>
#include <math.h>

#define BATCH 256
#define NTOK 197
#define CDIM 768
#define HEADS 12
#define DH 64
#define GRID14 14
#define M_ROWS (BATCH * NTOK)   /* 50432 = 394*128 */
#define QKV_N (3 * CDIM)        /* 2304 */
#define KTOT 768
#define ROWB (KTOT * 2)         /* 1536 bytes per fp16 row */

/* ---------------- scratch (__device__ globals; no allocs allowed) -------- */
__device__ __half g_qkv[(size_t)M_ROWS * QKV_N];     /* qkv fp16          */
__device__ __half g_xs[(size_t)M_ROWS * KTOT];       /* x fp16            */
__device__ __half g_atts[(size_t)M_ROWS * KTOT];     /* attn+conv fp16    */
__device__ __half g_wqkvs[(size_t)QKV_N * KTOT];     /* W_qkv^T fp16      */
__device__ __half g_wprojs[(size_t)CDIM * KTOT];     /* W_proj^T fp16     */

/* ---------------- helpers ------------------------------------------------- */
__device__ __forceinline__ uint32_t smem_u32(const void* p) {
    uint32_t a;
    asm("{ .reg .u64 t; cvta.to.shared.u64 t, %1; cvt.u32.u64 %0, t; }" : "=r"(a) : "l"(p));
    return a;
}
__device__ __forceinline__ uint32_t sw128(uint32_t o) { return o ^ ((o >> 3) & 0x70); }

__device__ __forceinline__ void cp16(uint32_t s, const void* g) {
    asm volatile("cp.async.cg.shared.global [%0], [%1], 16;" :: "r"(s), "l"(g));
}
__device__ __forceinline__ void ldm_x4(uint32_t* r, uint32_t a) {
    asm volatile("ldmatrix.sync.aligned.m8n8.x4.shared.b16 {%0,%1,%2,%3}, [%4];"
                 : "=r"(r[0]), "=r"(r[1]), "=r"(r[2]), "=r"(r[3]) : "r"(a));
}
__device__ __forceinline__ void ldm_x4t(uint32_t* r, uint32_t a) {
    asm volatile("ldmatrix.sync.aligned.m8n8.x4.trans.shared.b16 {%0,%1,%2,%3}, [%4];"
                 : "=r"(r[0]), "=r"(r[1]), "=r"(r[2]), "=r"(r[3]) : "r"(a));
}
__device__ __forceinline__ void mma16816(float* c, const uint32_t* a, const uint32_t* b) {
    asm volatile(
        "mma.sync.aligned.m16n8k16.row.col.f32.f16.f16.f32 "
        "{%0,%1,%2,%3}, {%4,%5,%6,%7}, {%8,%9}, {%0,%1,%2,%3};"
        : "+f"(c[0]), "+f"(c[1]), "+f"(c[2]), "+f"(c[3])
        : "r"(a[0]), "r"(a[1]), "r"(a[2]), "r"(a[3]), "r"(b[0]), "r"(b[1]));
}
__device__ __forceinline__ uint32_t pack2h(float x, float y) {
    __half2 h = __floats2half2_rn(x, y);
    return *reinterpret_cast<uint32_t*>(&h);
}
/* output-type-dispatched pair store */
__device__ __forceinline__ void store2(float* p, float a, float b) {
    *(float2*)p = make_float2(a, b);
}
__device__ __forceinline__ void store2(__half* p, float a, float b) {
    *(uint32_t*)p = pack2h(a, b);
}

/* ---------------- prep kernels -------------------------------------------- */
__global__ __launch_bounds__(256) void xpack(const float* __restrict__ in,
                                             __half* __restrict__ out, int total)
{
    int idx = blockIdx.x * 256 + threadIdx.x;
    if (idx >= total) return;
    out[idx] = __float2half_rn(in[idx]);
}

__global__ __launch_bounds__(256) void wpack(const float* __restrict__ W,
                                             __half* __restrict__ out,
                                             int N, int total)
{
    int idx = blockIdx.x * 256 + threadIdx.x;
    if (idx >= total) return;
    int n = idx / KTOT, k = idx % KTOT;
    out[(size_t)n * KTOT + k] = __float2half_rn(W[(size_t)k * N + n]);
}

/* ---------------- fp16 GEMM: 128x128 tile, 4 warps, 2 CTAs/SM ------------- */
#define TM 128
#define TN 128
#define NSTG 12                   /* 768 / 64 */
#define RING 3
#define PF 2
#define STG_A 16384
#define STG_B 16384
#define STG (STG_A + STG_B)       /* 32768 */
#define GSMEM (RING * STG)        /* 98304 -> 2 CTAs/SM */

__device__ __forceinline__ void load_stage(uint32_t sb, int buf, int st,
                                           const char* Ag, const char* Bg, int tid)
{
    uint32_t ab = sb + buf * STG;
    const char* a0 = Ag + (size_t)st * 128;
#pragma unroll
    for (int c = tid; c < 1024; c += 128) {
        int r = c >> 3, j = c & 7;
        cp16(ab + sw128(r * 128 + j * 16), a0 + (size_t)r * ROWB + j * 16);
    }
    uint32_t bb = ab + STG_A;
    const char* b0 = Bg + (size_t)st * 128;
#pragma unroll
    for (int c = tid; c < 1024; c += 128) {
        int r = c >> 3, j = c & 7;
        cp16(bb + sw128(r * 128 + j * 16), b0 + (size_t)r * ROWB + j * 16);
    }
    asm volatile("cp.async.commit_group;" ::: "memory");
}

template <typename OutT>
__global__ __launch_bounds__(128, 2) void gemm_mma(
    const __half* __restrict__ As, const __half* __restrict__ Bs,
    const float* __restrict__ bias, OutT* __restrict__ C, int Nd)
{
    extern __shared__ __align__(1024) char smc[];
    uint32_t sb = smem_u32(smc);
    const int tid = threadIdx.x;
    const size_t bm = (size_t)blockIdx.y * TM;
    const size_t bn = (size_t)blockIdx.x * TN;
    const char* Ag = (const char*)As + bm * ROWB;
    const char* Bg = (const char*)Bs + bn * ROWB;

#pragma unroll
    for (int st = 0; st < PF; st++) load_stage(sb, st, st, Ag, Bg, tid);

    const int warp = tid >> 5, lane = tid & 31;
    const int wm = (warp >> 1) * 64;
    const int wn = (warp & 1) * 64;

    float acc[4][8][4];
#pragma unroll
    for (int i = 0; i < 4; i++)
#pragma unroll
        for (int j = 0; j < 8; j++)
#pragma unroll
            for (int q = 0; q < 4; q++) acc[i][j][q] = 0.f;

    const int a_r = lane & 15;
    const int a_c = (lane >> 4) << 4;
    const int b_r = (lane & 7) + ((lane >> 4) << 3);
    const int b_c = ((lane >> 3) & 1) << 4;

    for (int s = 0; s < NSTG; s++) {
        const int buf = s % RING;
        if (s < NSTG - 1) asm volatile("cp.async.wait_group 1;" ::: "memory");
        else              asm volatile("cp.async.wait_group 0;" ::: "memory");
        __syncthreads();
        if (s + PF < NSTG) load_stage(sb, (s + PF) % RING, s + PF, Ag, Bg, tid);

        uint32_t ab = sb + buf * STG;
        uint32_t bb = ab + STG_A;

#pragma unroll
        for (int t = 0; t < 4; t++) {
            uint32_t br[4][4];
#pragma unroll
            for (int j = 0; j < 4; j++) {
                int row = wn + j * 16 + b_r;
                ldm_x4(br[j], bb + sw128(row * 128 + t * 32 + b_c));
            }
            uint32_t ar[4][4];
#pragma unroll
            for (int i = 0; i < 4; i++) {
                int row = wm + i * 16 + a_r;
                ldm_x4(ar[i], ab + sw128(row * 128 + t * 32 + a_c));
            }
#pragma unroll
            for (int i = 0; i < 4; i++)
#pragma unroll
                for (int j = 0; j < 4; j++) {
                    mma16816(acc[i][2 * j + 0], ar[i], &br[j][0]);
                    mma16816(acc[i][2 * j + 1], ar[i], &br[j][2]);
                }
        }
    }

    const int r0 = lane >> 2;
    const int c0 = (lane & 3) * 2;
    const size_t grow = bm + wm + r0;
    const int gcol = (int)bn + wn + c0;

    float2 bv[8];
#pragma unroll
    for (int j = 0; j < 8; j++)
        bv[j] = *(const float2*)(bias + gcol + j * 8);

#pragma unroll
    for (int i = 0; i < 4; i++) {
        OutT* cp0 = C + (grow + i * 16) * Nd + gcol;
        OutT* cp1 = cp0 + (size_t)8 * Nd;
#pragma unroll
        for (int j = 0; j < 8; j++) {
            store2(cp0 + j * 8, acc[i][j][0] + bv[j].x, acc[i][j][1] + bv[j].y);
            store2(cp1 + j * 8, acc[i][j][2] + bv[j].x, acc[i][j][3] + bv[j].y);
        }
    }
}

/* ---------------- tensor-core attention + fused depthwise conv ------------- */
/* One CTA per (b,h).  qkv fp16: K,V copy-through to SW128 smem.             */
/* QK^T 1-term, PV 1-term (fp16 P).                                          */
#define NPAD 208
#define ACHB (NPAD * 128)           /* 26624 */
#define WS_OFF (2 * ACHB)
#define BS_OFF (WS_OFF + 2304)
#define ASMEM (BS_OFF + 256)        /* 55812 */

__global__ __launch_bounds__(128, 2) void attn_mma(const __half* __restrict__ qkv,
                                                   const float* __restrict__ dwc_w,
                                                   const float* __restrict__ dwc_b,
                                                   __half* __restrict__ atts)
{
    extern __shared__ __align__(1024) char smem[];
    uint32_t sbase = smem_u32(smem);
    const uint32_t Ksm = sbase, Vsm = sbase + ACHB;
    float2* ws2 = (float2*)(smem + WS_OFF);
    float2* bs2 = (float2*)(smem + BS_OFF);
    const int b = blockIdx.x / HEADS, h = blockIdx.x % HEADS;
    const int tid = threadIdx.x;
    const __half* base = qkv + (size_t)b * NTOK * QKV_N + h * DH;

    for (int i = tid; i < 288; i += 128) {
        int pair = i / 9, tap = i % 9;
        int c = h * 64 + pair * 2;
        ws2[i] = make_float2(dwc_w[(size_t)c * 9 + tap], dwc_w[(size_t)(c + 1) * 9 + tap]);
    }
    if (tid < 32) bs2[tid] = make_float2(dwc_b[h * 64 + tid * 2], dwc_b[h * 64 + tid * 2 + 1]);

    /* stage K,V (copy-through fp16; rows >= NTOK zeroed) */
    for (int idx = tid; idx < NPAD * 32; idx += 128) {
        int j = idx >> 5, dp = idx & 31;
        uint32_t kw = 0u, vw = 0u;
        if (j < NTOK) {
            const __half* p = base + (size_t)j * QKV_N + dp * 2;
            kw = *(const uint32_t*)(p + CDIM);
            vw = *(const uint32_t*)(p + 2 * CDIM);
        }
        uint32_t off = sw128((uint32_t)(j * 128 + dp * 4));
        asm volatile("st.shared.b32 [%0], %1;" :: "r"(Ksm + off), "r"(kw) : "memory");
        asm volatile("st.shared.b32 [%0], %1;" :: "r"(Vsm + off), "r"(vw) : "memory");
    }
    __syncthreads();

    const int lane = tid & 31, warp = tid >> 5;
    const int qr = lane >> 2;
    const int qc = (lane & 3) * 2;
    const int b_r = (lane & 7) + ((lane >> 4) << 3);
    const int b_c = ((lane >> 3) & 1) << 4;
    const int a_r = lane & 15;
    const int a_c = (lane >> 4) << 4;

    for (int s = warp; s < 13; s += 4) {
        const int m0 = s * 16 + qr;
        const int m1 = m0 + 8;
        const int rm0 = m0 < NTOK ? m0 : NTOK - 1;
        const int rm1 = m1 < NTOK ? m1 : NTOK - 1;

        /* Q fragments straight from fp16 global */
        uint32_t qh[4][4];
        const __half* q0 = base + (size_t)rm0 * QKV_N;
        const __half* q1 = base + (size_t)rm1 * QKV_N;
#pragma unroll
        for (int kt = 0; kt < 4; kt++) {
            int c = kt * 16 + qc;
            qh[kt][0] = *(const uint32_t*)(q0 + c);
            qh[kt][1] = *(const uint32_t*)(q1 + c);
            qh[kt][2] = *(const uint32_t*)(q0 + c + 8);
            qh[kt][3] = *(const uint32_t*)(q1 + c + 8);
        }

        float S[26][4];
#pragma unroll
        for (int t = 0; t < 26; t++)
#pragma unroll
            for (int q = 0; q < 4; q++) S[t][q] = 0.f;

#pragma unroll
        for (int nc = 0; nc < 13; nc++) {
#pragma unroll
            for (int kt = 0; kt < 4; kt++) {
                uint32_t kb[4];
                ldm_x4(kb, Ksm + sw128((uint32_t)((nc * 16 + b_r) * 128 + kt * 32 + b_c)));
                mma16816(S[2 * nc],     qh[kt], &kb[0]);
                mma16816(S[2 * nc + 1], qh[kt], &kb[2]);
            }
        }

#pragma unroll
        for (int t = 24; t < 26; t++) {
            int j0 = t * 8 + qc;
            if (j0 >= NTOK)     S[t][0] = S[t][2] = -1e30f;
            if (j0 + 1 >= NTOK) S[t][1] = S[t][3] = -1e30f;
        }

        float mx0 = -1e30f, mx1 = -1e30f;
#pragma unroll
        for (int t = 0; t < 26; t++) {
            mx0 = fmaxf(mx0, fmaxf(S[t][0], S[t][1]));
            mx1 = fmaxf(mx1, fmaxf(S[t][2], S[t][3]));
        }
        mx0 = fmaxf(mx0, __shfl_xor_sync(0xffffffffu, mx0, 1));
        mx0 = fmaxf(mx0, __shfl_xor_sync(0xffffffffu, mx0, 2));
        mx1 = fmaxf(mx1, __shfl_xor_sync(0xffffffffu, mx1, 1));
        mx1 = fmaxf(mx1, __shfl_xor_sync(0xffffffffu, mx1, 2));
        float sum0 = 0.f, sum1 = 0.f;
#pragma unroll
        for (int t = 0; t < 26; t++) {
            S[t][0] = __expf((S[t][0] - mx0) * 0.125f);
            S[t][1] = __expf((S[t][1] - mx0) * 0.125f);
            S[t][2] = __expf((S[t][2] - mx1) * 0.125f);
            S[t][3] = __expf((S[t][3] - mx1) * 0.125f);
            sum0 += S[t][0] + S[t][1];
            sum1 += S[t][2] + S[t][3];
        }
        sum0 += __shfl_xor_sync(0xffffffffu, sum0, 1);
        sum0 += __shfl_xor_sync(0xffffffffu, sum0, 2);
        sum1 += __shfl_xor_sync(0xffffffffu, sum1, 1);
        sum1 += __shfl_xor_sync(0xffffffffu, sum1, 2);
        float inv0 = __frcp_rn(sum0), inv1 = __frcp_rn(sum1);

        float O[8][4];
#pragma unroll
        for (int t = 0; t < 8; t++)
#pragma unroll
            for (int q = 0; q < 4; q++) O[t][q] = 0.f;

#pragma unroll
        for (int jt = 0; jt < 13; jt++) {
            uint32_t ph[4];
            ph[0] = pack2h(S[2 * jt][0],     S[2 * jt][1]);
            ph[1] = pack2h(S[2 * jt][2],     S[2 * jt][3]);
            ph[2] = pack2h(S[2 * jt + 1][0], S[2 * jt + 1][1]);
            ph[3] = pack2h(S[2 * jt + 1][2], S[2 * jt + 1][3]);
#pragma unroll
            for (int dc = 0; dc < 4; dc++) {
                uint32_t vb[4];
                uint32_t rb = (uint32_t)((jt * 16 + a_r) * 128 + dc * 32 + a_c);
                ldm_x4t(vb, Vsm + sw128(rb));
                mma16816(O[2 * dc],     ph, &vb[0]);
                mma16816(O[2 * dc + 1], ph, &vb[2]);
            }
        }

        /* write rows with fused conv (plain fp16 atts) */
#pragma unroll
        for (int rsel = 0; rsel < 2; rsel++) {
            const int m = rsel ? m1 : m0;
            if (m >= NTOK) continue;
            const float inv = rsel ? inv1 : inv0;
            const int qs = rsel * 2;
            const bool doconv = (m >= 1);
            int y = 0, x = 0;
            if (doconv) { y = (m - 1) / GRID14; x = (m - 1) % GRID14; }
            __half* rp = atts + (size_t)(b * NTOK + m) * KTOT + h * DH;
#pragma unroll
            for (int t = 0; t < 8; t++) {
                float v0 = O[t][qs] * inv;
                float v1 = O[t][qs + 1] * inv;
                const int d0 = (t >> 1) * 16 + (t & 1) * 8 + qc;
                if (doconv) {
                    float2 cv = bs2[d0 >> 1];
                    const float2* wp = ws2 + (d0 >> 1) * 9;
#pragma unroll
                    for (int ky = 0; ky < 3; ky++) {
                        int yy = y + ky - 1;
                        if (yy < 0 || yy >= GRID14) continue;
#pragma unroll
                        for (int kx = 0; kx < 3; kx++) {
                            int xx = x + kx - 1;
                            if (xx < 0 || xx >= GRID14) continue;
                            int j = 1 + yy * GRID14 + xx;
                            uint32_t off = sw128((uint32_t)(j * 128 + d0 * 2));
                            uint32_t vh;
                            asm("ld.shared.b32 %0,[%1];" : "=r"(vh) : "r"(Vsm + off));
                            __half2 h2 = *reinterpret_cast<__half2*>(&vh);
                            float2 wv = wp[ky * 3 + kx];
                            cv.x = fmaf(__half2float(h2.x), wv.x, cv.x);
                            cv.y = fmaf(__half2float(h2.y), wv.y, cv.y);
                        }
                    }
                    v0 += cv.x;
                    v1 += cv.y;
                }
                *(uint32_t*)(rp + d0) = pack2h(v0, v1);
            }
        }
    }
}

/* ---------------- launch --------------------------------------------------- */
extern "C" void kernel_launch(void* const* d_in, const int* in_sizes, int n_in,
                              void* d_out, int out_size)
{
    const float* x      = (const float*)d_in[0];
    const float* W_qkv  = (const float*)d_in[1];
    const float* b_qkv  = (const float*)d_in[2];
    const float* W_proj = (const float*)d_in[3];
    const float* b_proj = (const float*)d_in[4];
    const float* dwc_w  = (const float*)d_in[5];
    const float* dwc_b  = (const float*)d_in[6];
    float* out = (float*)d_out;

    __half *qkv = nullptr, *xs = nullptr, *atts = nullptr, *wqkvs = nullptr, *wprojs = nullptr;
    cudaGetSymbolAddress((void**)&qkv, g_qkv);
    cudaGetSymbolAddress((void**)&xs, g_xs);
    cudaGetSymbolAddress((void**)&atts, g_atts);
    cudaGetSymbolAddress((void**)&wqkvs, g_wqkvs);
    cudaGetSymbolAddress((void**)&wprojs, g_wprojs);

    cudaFuncSetAttribute(attn_mma, cudaFuncAttributeMaxDynamicSharedMemorySize, ASMEM);
    cudaFuncSetAttribute(gemm_mma<__half>, cudaFuncAttributeMaxDynamicSharedMemorySize, GSMEM);
    cudaFuncSetAttribute(gemm_mma<float>, cudaFuncAttributeMaxDynamicSharedMemorySize, GSMEM);

    xpack<<<(M_ROWS * KTOT) / 256, 256>>>(x, xs, M_ROWS * KTOT);
    wpack<<<(QKV_N * KTOT) / 256, 256>>>(W_qkv, wqkvs, QKV_N, QKV_N * KTOT);
    wpack<<<(CDIM * KTOT) / 256, 256>>>(W_proj, wprojs, CDIM, CDIM * KTOT);

    /* 1) qkv = x @ W_qkv + b_qkv  (fp16 output) */
    gemm_mma<__half><<<dim3(QKV_N / TN, M_ROWS / TM), 128, GSMEM>>>(xs, wqkvs, b_qkv, qkv, QKV_N);

    /* 2) attention + fused depthwise conv -> atts (fp16) */
    attn_mma<<<BATCH * HEADS, 128, ASMEM>>>(qkv, dwc_w, dwc_b, atts);

    /* 3) out = (attn+conv) @ W_proj + b_proj  (fp32 output) */
    gemm_mma<float><<<dim3(CDIM / TN, M_ROWS / TM), 128, GSMEM>>>(atts, wprojs, b_proj, out, CDIM);
}

// round 12
// speedup vs baseline: 6.7553x; 1.0284x over previous
#include <cuda_runtime.h>
#include <cuda_fp16.h>
#include <cstdint>
#include <math.h>

#define BATCH 256
#define NTOK 197
#define CDIM 768
#define HEADS 12
#define DH 64
#define GRID14 14
#define M_ROWS (BATCH * NTOK)   /* 50432 = 394*128 */
#define QKV_N (3 * CDIM)        /* 2304 */
#define KTOT 768
#define ROWB (KTOT * 2)         /* 1536 bytes per fp16 row */

/* ---------------- scratch (__device__ globals; no allocs allowed) -------- */
__device__ __half g_qkv[(size_t)M_ROWS * QKV_N];     /* qkv fp16          */
__device__ __half g_xs[(size_t)M_ROWS * KTOT];       /* x fp16            */
__device__ __half g_atts[(size_t)M_ROWS * KTOT];     /* attn+conv fp16    */
__device__ __half g_wqkvs[(size_t)QKV_N * KTOT];     /* W_qkv^T fp16      */
__device__ __half g_wprojs[(size_t)CDIM * KTOT];     /* W_proj^T fp16     */

/* ---------------- helpers ------------------------------------------------- */
__device__ __forceinline__ uint32_t smem_u32(const void* p) {
    uint32_t a;
    asm("{ .reg .u64 t; cvta.to.shared.u64 t, %1; cvt.u32.u64 %0, t; }" : "=r"(a) : "l"(p));
    return a;
}
__device__ __forceinline__ uint32_t sw128(uint32_t o) { return o ^ ((o >> 3) & 0x70); }

__device__ __forceinline__ void cp16(uint32_t s, const void* g) {
    asm volatile("cp.async.cg.shared.global [%0], [%1], 16;" :: "r"(s), "l"(g));
}
__device__ __forceinline__ void ldm_x4(uint32_t* r, uint32_t a) {
    asm volatile("ldmatrix.sync.aligned.m8n8.x4.shared.b16 {%0,%1,%2,%3}, [%4];"
                 : "=r"(r[0]), "=r"(r[1]), "=r"(r[2]), "=r"(r[3]) : "r"(a));
}
__device__ __forceinline__ void ldm_x4t(uint32_t* r, uint32_t a) {
    asm volatile("ldmatrix.sync.aligned.m8n8.x4.trans.shared.b16 {%0,%1,%2,%3}, [%4];"
                 : "=r"(r[0]), "=r"(r[1]), "=r"(r[2]), "=r"(r[3]) : "r"(a));
}
__device__ __forceinline__ void mma16816(float* c, const uint32_t* a, const uint32_t* b) {
    asm volatile(
        "mma.sync.aligned.m16n8k16.row.col.f32.f16.f16.f32 "
        "{%0,%1,%2,%3}, {%4,%5,%6,%7}, {%8,%9}, {%0,%1,%2,%3};"
        : "+f"(c[0]), "+f"(c[1]), "+f"(c[2]), "+f"(c[3])
        : "r"(a[0]), "r"(a[1]), "r"(a[2]), "r"(a[3]), "r"(b[0]), "r"(b[1]));
}
__device__ __forceinline__ uint32_t pack2h(float x, float y) {
    __half2 h = __floats2half2_rn(x, y);
    return *reinterpret_cast<uint32_t*>(&h);
}
/* output-type-dispatched pair store */
__device__ __forceinline__ void store2(float* p, float a, float b) {
    *(float2*)p = make_float2(a, b);
}
__device__ __forceinline__ void store2(__half* p, float a, float b) {
    *(uint32_t*)p = pack2h(a, b);
}

/* ---------------- prep kernels -------------------------------------------- */
__global__ __launch_bounds__(256) void xpack(const float* __restrict__ in,
                                             __half* __restrict__ out, int total)
{
    int idx = blockIdx.x * 256 + threadIdx.x;
    if (idx >= total) return;
    out[idx] = __float2half_rn(in[idx]);
}

__global__ __launch_bounds__(256) void wpack(const float* __restrict__ W,
                                             __half* __restrict__ out,
                                             int N, int total)
{
    int idx = blockIdx.x * 256 + threadIdx.x;
    if (idx >= total) return;
    int n = idx / KTOT, k = idx % KTOT;
    out[(size_t)n * KTOT + k] = __float2half_rn(W[(size_t)k * N + n]);
}

/* ---------------- fp16 GEMM: 128x64 tile, 2 warps, 4 CTAs/SM -------------- */
#define TM 128
#define TN 64
#define NSTG 12                   /* 768 / 64 */
#define RING 2
#define STG_A 16384               /* 128 rows * 128B */
#define STG_B 8192                /* 64 rows * 128B  */
#define STG (STG_A + STG_B)       /* 24576 */
#define GSMEM (RING * STG)        /* 49152 -> 4 CTAs/SM */

__device__ __forceinline__ void load_stage(uint32_t sb, int buf, int st,
                                           const char* Ag, const char* Bg, int tid)
{
    uint32_t ab = sb + buf * STG;
    const char* a0 = Ag + (size_t)st * 128;
#pragma unroll
    for (int c = tid; c < 1024; c += 64) {
        int r = c >> 3, j = c & 7;
        cp16(ab + sw128(r * 128 + j * 16), a0 + (size_t)r * ROWB + j * 16);
    }
    uint32_t bb = ab + STG_A;
    const char* b0 = Bg + (size_t)st * 128;
#pragma unroll
    for (int c = tid; c < 512; c += 64) {
        int r = c >> 3, j = c & 7;
        cp16(bb + sw128(r * 128 + j * 16), b0 + (size_t)r * ROWB + j * 16);
    }
    asm volatile("cp.async.commit_group;" ::: "memory");
}

template <typename OutT>
__global__ __launch_bounds__(64, 4) void gemm_mma(
    const __half* __restrict__ As, const __half* __restrict__ Bs,
    const float* __restrict__ bias, OutT* __restrict__ C, int Nd)
{
    extern __shared__ __align__(1024) char smc[];
    uint32_t sb = smem_u32(smc);
    const int tid = threadIdx.x;
    const size_t bm = (size_t)blockIdx.y * TM;
    const size_t bn = (size_t)blockIdx.x * TN;
    const char* Ag = (const char*)As + bm * ROWB;
    const char* Bg = (const char*)Bs + bn * ROWB;

    load_stage(sb, 0, 0, Ag, Bg, tid);

    const int warp = tid >> 5, lane = tid & 31;
    const int wm = warp * 64;            /* warp rows; both warps take full n=64 */

    float acc[4][8][4];
#pragma unroll
    for (int i = 0; i < 4; i++)
#pragma unroll
        for (int j = 0; j < 8; j++)
#pragma unroll
            for (int q = 0; q < 4; q++) acc[i][j][q] = 0.f;

    const int a_r = lane & 15;
    const int a_c = (lane >> 4) << 4;
    const int b_r = (lane & 7) + ((lane >> 4) << 3);
    const int b_c = ((lane >> 3) & 1) << 4;

    for (int s = 0; s < NSTG; s++) {
        const int buf = s & 1;
        asm volatile("cp.async.wait_group 0;" ::: "memory");
        __syncthreads();
        if (s + 1 < NSTG) load_stage(sb, buf ^ 1, s + 1, Ag, Bg, tid);

        uint32_t ab = sb + buf * STG;
        uint32_t bb = ab + STG_A;

#pragma unroll
        for (int t = 0; t < 4; t++) {
            uint32_t br[4][4];
#pragma unroll
            for (int j = 0; j < 4; j++) {
                int row = j * 16 + b_r;
                ldm_x4(br[j], bb + sw128(row * 128 + t * 32 + b_c));
            }
            uint32_t ar[4][4];
#pragma unroll
            for (int i = 0; i < 4; i++) {
                int row = wm + i * 16 + a_r;
                ldm_x4(ar[i], ab + sw128(row * 128 + t * 32 + a_c));
            }
#pragma unroll
            for (int i = 0; i < 4; i++)
#pragma unroll
                for (int j = 0; j < 4; j++) {
                    mma16816(acc[i][2 * j + 0], ar[i], &br[j][0]);
                    mma16816(acc[i][2 * j + 1], ar[i], &br[j][2]);
                }
        }
    }

    const int r0 = lane >> 2;
    const int c0 = (lane & 3) * 2;
    const size_t grow = bm + wm + r0;
    const int gcol = (int)bn + c0;

    float2 bv[8];
#pragma unroll
    for (int j = 0; j < 8; j++)
        bv[j] = *(const float2*)(bias + gcol + j * 8);

#pragma unroll
    for (int i = 0; i < 4; i++) {
        OutT* cp0 = C + (grow + i * 16) * Nd + gcol;
        OutT* cp1 = cp0 + (size_t)8 * Nd;
#pragma unroll
        for (int j = 0; j < 8; j++) {
            store2(cp0 + j * 8, acc[i][j][0] + bv[j].x, acc[i][j][1] + bv[j].y);
            store2(cp1 + j * 8, acc[i][j][2] + bv[j].x, acc[i][j][3] + bv[j].y);
        }
    }
}

/* ---------------- tensor-core attention + fused depthwise conv ------------- */
/* One CTA per (b,h).  qkv fp16: K,V copy-through to SW128 smem.             */
/* QK^T 1-term, PV 1-term (fp16 P).                                          */
#define NPAD 208
#define ACHB (NPAD * 128)           /* 26624 */
#define WS_OFF (2 * ACHB)
#define BS_OFF (WS_OFF + 2304)
#define ASMEM (BS_OFF + 256)        /* 55812 */

__global__ __launch_bounds__(128, 2) void attn_mma(const __half* __restrict__ qkv,
                                                   const float* __restrict__ dwc_w,
                                                   const float* __restrict__ dwc_b,
                                                   __half* __restrict__ atts)
{
    extern __shared__ __align__(1024) char smem[];
    uint32_t sbase = smem_u32(smem);
    const uint32_t Ksm = sbase, Vsm = sbase + ACHB;
    float2* ws2 = (float2*)(smem + WS_OFF);
    float2* bs2 = (float2*)(smem + BS_OFF);
    const int b = blockIdx.x / HEADS, h = blockIdx.x % HEADS;
    const int tid = threadIdx.x;
    const __half* base = qkv + (size_t)b * NTOK * QKV_N + h * DH;

    for (int i = tid; i < 288; i += 128) {
        int pair = i / 9, tap = i % 9;
        int c = h * 64 + pair * 2;
        ws2[i] = make_float2(dwc_w[(size_t)c * 9 + tap], dwc_w[(size_t)(c + 1) * 9 + tap]);
    }
    if (tid < 32) bs2[tid] = make_float2(dwc_b[h * 64 + tid * 2], dwc_b[h * 64 + tid * 2 + 1]);

    /* stage K,V (copy-through fp16; rows >= NTOK zeroed) */
    for (int idx = tid; idx < NPAD * 32; idx += 128) {
        int j = idx >> 5, dp = idx & 31;
        uint32_t kw = 0u, vw = 0u;
        if (j < NTOK) {
            const __half* p = base + (size_t)j * QKV_N + dp * 2;
            kw = *(const uint32_t*)(p + CDIM);
            vw = *(const uint32_t*)(p + 2 * CDIM);
        }
        uint32_t off = sw128((uint32_t)(j * 128 + dp * 4));
        asm volatile("st.shared.b32 [%0], %1;" :: "r"(Ksm + off), "r"(kw) : "memory");
        asm volatile("st.shared.b32 [%0], %1;" :: "r"(Vsm + off), "r"(vw) : "memory");
    }
    __syncthreads();

    const int lane = tid & 31, warp = tid >> 5;
    const int qr = lane >> 2;
    const int qc = (lane & 3) * 2;
    const int b_r = (lane & 7) + ((lane >> 4) << 3);
    const int b_c = ((lane >> 3) & 1) << 4;
    const int a_r = lane & 15;
    const int a_c = (lane >> 4) << 4;

    for (int s = warp; s < 13; s += 4) {
        const int m0 = s * 16 + qr;
        const int m1 = m0 + 8;
        const int rm0 = m0 < NTOK ? m0 : NTOK - 1;
        const int rm1 = m1 < NTOK ? m1 : NTOK - 1;

        /* Q fragments straight from fp16 global */
        uint32_t qh[4][4];
        const __half* q0 = base + (size_t)rm0 * QKV_N;
        const __half* q1 = base + (size_t)rm1 * QKV_N;
#pragma unroll
        for (int kt = 0; kt < 4; kt++) {
            int c = kt * 16 + qc;
            qh[kt][0] = *(const uint32_t*)(q0 + c);
            qh[kt][1] = *(const uint32_t*)(q1 + c);
            qh[kt][2] = *(const uint32_t*)(q0 + c + 8);
            qh[kt][3] = *(const uint32_t*)(q1 + c + 8);
        }

        float S[26][4];
#pragma unroll
        for (int t = 0; t < 26; t++)
#pragma unroll
            for (int q = 0; q < 4; q++) S[t][q] = 0.f;

#pragma unroll
        for (int nc = 0; nc < 13; nc++) {
#pragma unroll
            for (int kt = 0; kt < 4; kt++) {
                uint32_t kb[4];
                ldm_x4(kb, Ksm + sw128((uint32_t)((nc * 16 + b_r) * 128 + kt * 32 + b_c)));
                mma16816(S[2 * nc],     qh[kt], &kb[0]);
                mma16816(S[2 * nc + 1], qh[kt], &kb[2]);
            }
        }

#pragma unroll
        for (int t = 24; t < 26; t++) {
            int j0 = t * 8 + qc;
            if (j0 >= NTOK)     S[t][0] = S[t][2] = -1e30f;
            if (j0 + 1 >= NTOK) S[t][1] = S[t][3] = -1e30f;
        }

        float mx0 = -1e30f, mx1 = -1e30f;
#pragma unroll
        for (int t = 0; t < 26; t++) {
            mx0 = fmaxf(mx0, fmaxf(S[t][0], S[t][1]));
            mx1 = fmaxf(mx1, fmaxf(S[t][2], S[t][3]));
        }
        mx0 = fmaxf(mx0, __shfl_xor_sync(0xffffffffu, mx0, 1));
        mx0 = fmaxf(mx0, __shfl_xor_sync(0xffffffffu, mx0, 2));
        mx1 = fmaxf(mx1, __shfl_xor_sync(0xffffffffu, mx1, 1));
        mx1 = fmaxf(mx1, __shfl_xor_sync(0xffffffffu, mx1, 2));
        float sum0 = 0.f, sum1 = 0.f;
#pragma unroll
        for (int t = 0; t < 26; t++) {
            S[t][0] = __expf((S[t][0] - mx0) * 0.125f);
            S[t][1] = __expf((S[t][1] - mx0) * 0.125f);
            S[t][2] = __expf((S[t][2] - mx1) * 0.125f);
            S[t][3] = __expf((S[t][3] - mx1) * 0.125f);
            sum0 += S[t][0] + S[t][1];
            sum1 += S[t][2] + S[t][3];
        }
        sum0 += __shfl_xor_sync(0xffffffffu, sum0, 1);
        sum0 += __shfl_xor_sync(0xffffffffu, sum0, 2);
        sum1 += __shfl_xor_sync(0xffffffffu, sum1, 1);
        sum1 += __shfl_xor_sync(0xffffffffu, sum1, 2);
        float inv0 = __frcp_rn(sum0), inv1 = __frcp_rn(sum1);

        float O[8][4];
#pragma unroll
        for (int t = 0; t < 8; t++)
#pragma unroll
            for (int q = 0; q < 4; q++) O[t][q] = 0.f;

#pragma unroll
        for (int jt = 0; jt < 13; jt++) {
            uint32_t ph[4];
            ph[0] = pack2h(S[2 * jt][0],     S[2 * jt][1]);
            ph[1] = pack2h(S[2 * jt][2],     S[2 * jt][3]);
            ph[2] = pack2h(S[2 * jt + 1][0], S[2 * jt + 1][1]);
            ph[3] = pack2h(S[2 * jt + 1][2], S[2 * jt + 1][3]);
#pragma unroll
            for (int dc = 0; dc < 4; dc++) {
                uint32_t vb[4];
                uint32_t rb = (uint32_t)((jt * 16 + a_r) * 128 + dc * 32 + a_c);
                ldm_x4t(vb, Vsm + sw128(rb));
                mma16816(O[2 * dc],     ph, &vb[0]);
                mma16816(O[2 * dc + 1], ph, &vb[2]);
            }
        }

        /* write rows with fused conv (plain fp16 atts) */
#pragma unroll
        for (int rsel = 0; rsel < 2; rsel++) {
            const int m = rsel ? m1 : m0;
            if (m >= NTOK) continue;
            const float inv = rsel ? inv1 : inv0;
            const int qs = rsel * 2;
            const bool doconv = (m >= 1);
            int y = 0, x = 0;
            if (doconv) { y = (m - 1) / GRID14; x = (m - 1) % GRID14; }
            __half* rp = atts + (size_t)(b * NTOK + m) * KTOT + h * DH;
#pragma unroll
            for (int t = 0; t < 8; t++) {
                float v0 = O[t][qs] * inv;
                float v1 = O[t][qs + 1] * inv;
                const int d0 = (t >> 1) * 16 + (t & 1) * 8 + qc;
                if (doconv) {
                    float2 cv = bs2[d0 >> 1];
                    const float2* wp = ws2 + (d0 >> 1) * 9;
#pragma unroll
                    for (int ky = 0; ky < 3; ky++) {
                        int yy = y + ky - 1;
                        if (yy < 0 || yy >= GRID14) continue;
#pragma unroll
                        for (int kx = 0; kx < 3; kx++) {
                            int xx = x + kx - 1;
                            if (xx < 0 || xx >= GRID14) continue;
                            int j = 1 + yy * GRID14 + xx;
                            uint32_t off = sw128((uint32_t)(j * 128 + d0 * 2));
                            uint32_t vh;
                            asm("ld.shared.b32 %0,[%1];" : "=r"(vh) : "r"(Vsm + off));
                            __half2 h2 = *reinterpret_cast<__half2*>(&vh);
                            float2 wv = wp[ky * 3 + kx];
                            cv.x = fmaf(__half2float(h2.x), wv.x, cv.x);
                            cv.y = fmaf(__half2float(h2.y), wv.y, cv.y);
                        }
                    }
                    v0 += cv.x;
                    v1 += cv.y;
                }
                *(uint32_t*)(rp + d0) = pack2h(v0, v1);
            }
        }
    }
}

/* ---------------- launch --------------------------------------------------- */
extern "C" void kernel_launch(void* const* d_in, const int* in_sizes, int n_in,
                              void* d_out, int out_size)
{
    const float* x      = (const float*)d_in[0];
    const float* W_qkv  = (const float*)d_in[1];
    const float* b_qkv  = (const float*)d_in[2];
    const float* W_proj = (const float*)d_in[3];
    const float* b_proj = (const float*)d_in[4];
    const float* dwc_w  = (const float*)d_in[5];
    const float* dwc_b  = (const float*)d_in[6];
    float* out = (float*)d_out;

    __half *qkv = nullptr, *xs = nullptr, *atts = nullptr, *wqkvs = nullptr, *wprojs = nullptr;
    cudaGetSymbolAddress((void**)&qkv, g_qkv);
    cudaGetSymbolAddress((void**)&xs, g_xs);
    cudaGetSymbolAddress((void**)&atts, g_atts);
    cudaGetSymbolAddress((void**)&wqkvs, g_wqkvs);
    cudaGetSymbolAddress((void**)&wprojs, g_wprojs);

    cudaFuncSetAttribute(attn_mma, cudaFuncAttributeMaxDynamicSharedMemorySize, ASMEM);
    cudaFuncSetAttribute(gemm_mma<__half>, cudaFuncAttributeMaxDynamicSharedMemorySize, GSMEM);
    cudaFuncSetAttribute(gemm_mma<float>, cudaFuncAttributeMaxDynamicSharedMemorySize, GSMEM);

    xpack<<<(M_ROWS * KTOT) / 256, 256>>>(x, xs, M_ROWS * KTOT);
    wpack<<<(QKV_N * KTOT) / 256, 256>>>(W_qkv, wqkvs, QKV_N, QKV_N * KTOT);
    wpack<<<(CDIM * KTOT) / 256, 256>>>(W_proj, wprojs, CDIM, CDIM * KTOT);

    /* 1) qkv = x @ W_qkv + b_qkv  (fp16 output) */
    gemm_mma<__half><<<dim3(QKV_N / TN, M_ROWS / TM), 64, GSMEM>>>(xs, wqkvs, b_qkv, qkv, QKV_N);

    /* 2) attention + fused depthwise conv -> atts (fp16) */
    attn_mma<<<BATCH * HEADS, 128, ASMEM>>>(qkv, dwc_w, dwc_b, atts);

    /* 3) out = (attn+conv) @ W_proj + b_proj  (fp32 output) */
    gemm_mma<float><<<dim3(CDIM / TN, M_ROWS / TM), 64, GSMEM>>>(atts, wprojs, b_proj, out, CDIM);
}

// round 13
// speedup vs baseline: 6.8050x; 1.0074x over previous
#include <cuda_runtime.h>
#include <cuda_fp16.h>
#include <cstdint>
#include <math.h>

#define BATCH 256
#define NTOK 197
#define CDIM 768
#define HEADS 12
#define DH 64
#define GRID14 14
#define M_ROWS (BATCH * NTOK)   /* 50432 = 394*128 */
#define QKV_N (3 * CDIM)        /* 2304 */
#define KTOT 768
#define ROWB (KTOT * 2)         /* 1536 bytes per fp16 row */

/* ---------------- scratch (__device__ globals; no allocs allowed) -------- */
__device__ __half g_qkv[(size_t)M_ROWS * QKV_N];     /* qkv fp16          */
__device__ __half g_xs[(size_t)M_ROWS * KTOT];       /* x fp16            */
__device__ __half g_atts[(size_t)M_ROWS * KTOT];     /* attn+conv fp16    */
__device__ __half g_wqkvs[(size_t)QKV_N * KTOT];     /* W_qkv^T fp16      */
__device__ __half g_wprojs[(size_t)CDIM * KTOT];     /* W_proj^T fp16     */

/* ---------------- helpers ------------------------------------------------- */
__device__ __forceinline__ uint32_t smem_u32(const void* p) {
    uint32_t a;
    asm("{ .reg .u64 t; cvta.to.shared.u64 t, %1; cvt.u32.u64 %0, t; }" : "=r"(a) : "l"(p));
    return a;
}
__device__ __forceinline__ uint32_t sw128(uint32_t o) { return o ^ ((o >> 3) & 0x70); }

__device__ __forceinline__ void cp16(uint32_t s, const void* g) {
    asm volatile("cp.async.cg.shared.global [%0], [%1], 16;" :: "r"(s), "l"(g));
}
__device__ __forceinline__ void ldm_x4(uint32_t* r, uint32_t a) {
    asm volatile("ldmatrix.sync.aligned.m8n8.x4.shared.b16 {%0,%1,%2,%3}, [%4];"
                 : "=r"(r[0]), "=r"(r[1]), "=r"(r[2]), "=r"(r[3]) : "r"(a));
}
__device__ __forceinline__ void ldm_x4t(uint32_t* r, uint32_t a) {
    asm volatile("ldmatrix.sync.aligned.m8n8.x4.trans.shared.b16 {%0,%1,%2,%3}, [%4];"
                 : "=r"(r[0]), "=r"(r[1]), "=r"(r[2]), "=r"(r[3]) : "r"(a));
}
__device__ __forceinline__ void mma16816(float* c, const uint32_t* a, const uint32_t* b) {
    asm volatile(
        "mma.sync.aligned.m16n8k16.row.col.f32.f16.f16.f32 "
        "{%0,%1,%2,%3}, {%4,%5,%6,%7}, {%8,%9}, {%0,%1,%2,%3};"
        : "+f"(c[0]), "+f"(c[1]), "+f"(c[2]), "+f"(c[3])
        : "r"(a[0]), "r"(a[1]), "r"(a[2]), "r"(a[3]), "r"(b[0]), "r"(b[1]));
}
__device__ __forceinline__ uint32_t pack2h(float x, float y) {
    __half2 h = __floats2half2_rn(x, y);
    return *reinterpret_cast<uint32_t*>(&h);
}
/* output-type-dispatched pair store */
__device__ __forceinline__ void store2(float* p, float a, float b) {
    *(float2*)p = make_float2(a, b);
}
__device__ __forceinline__ void store2(__half* p, float a, float b) {
    *(uint32_t*)p = pack2h(a, b);
}

/* ---------------- prep kernels -------------------------------------------- */
__global__ __launch_bounds__(256) void xpack(const float* __restrict__ in,
                                             __half* __restrict__ out, int total)
{
    int idx = blockIdx.x * 256 + threadIdx.x;
    if (idx >= total) return;
    out[idx] = __float2half_rn(in[idx]);
}

/* W [768, N] fp32 -> out [N, 768] fp16: 32x32 tiled transpose, coalesced */
__global__ __launch_bounds__(256) void wpack(const float* __restrict__ W,
                                             __half* __restrict__ out, int N)
{
    __shared__ __half tile[32][33];
    const int n0 = blockIdx.x * 32;
    const int k0 = blockIdx.y * 32;
    const int tx = threadIdx.x & 31;
    const int ty = threadIdx.x >> 5;   /* 0..7 */
#pragma unroll
    for (int i = ty; i < 32; i += 8)
        tile[tx][i] = __float2half_rn(W[(size_t)(k0 + i) * N + n0 + tx]);
    __syncthreads();
#pragma unroll
    for (int i = ty; i < 32; i += 8)
        out[(size_t)(n0 + i) * KTOT + k0 + tx] = tile[i][tx];
}

/* ---------------- fp16 GEMM: 128x64 tile, 2 warps, 4 CTAs/SM -------------- */
#define TM 128
#define TN 64
#define NSTG 12                   /* 768 / 64 */
#define RING 2
#define STG_A 16384               /* 128 rows * 128B */
#define STG_B 8192                /* 64 rows * 128B  */
#define STG (STG_A + STG_B)       /* 24576 */
#define GSMEM (RING * STG)        /* 49152 -> 4 CTAs/SM */

__device__ __forceinline__ void load_stage(uint32_t sb, int buf, int st,
                                           const char* Ag, const char* Bg, int tid)
{
    uint32_t ab = sb + buf * STG;
    const char* a0 = Ag + (size_t)st * 128;
#pragma unroll
    for (int c = tid; c < 1024; c += 64) {
        int r = c >> 3, j = c & 7;
        cp16(ab + sw128(r * 128 + j * 16), a0 + (size_t)r * ROWB + j * 16);
    }
    uint32_t bb = ab + STG_A;
    const char* b0 = Bg + (size_t)st * 128;
#pragma unroll
    for (int c = tid; c < 512; c += 64) {
        int r = c >> 3, j = c & 7;
        cp16(bb + sw128(r * 128 + j * 16), b0 + (size_t)r * ROWB + j * 16);
    }
    asm volatile("cp.async.commit_group;" ::: "memory");
}

template <typename OutT>
__global__ __launch_bounds__(64, 4) void gemm_mma(
    const __half* __restrict__ As, const __half* __restrict__ Bs,
    const float* __restrict__ bias, OutT* __restrict__ C, int Nd)
{
    extern __shared__ __align__(1024) char smc[];
    uint32_t sb = smem_u32(smc);
    const int tid = threadIdx.x;
    const size_t bm = (size_t)blockIdx.y * TM;
    const size_t bn = (size_t)blockIdx.x * TN;
    const char* Ag = (const char*)As + bm * ROWB;
    const char* Bg = (const char*)Bs + bn * ROWB;

    load_stage(sb, 0, 0, Ag, Bg, tid);

    const int warp = tid >> 5, lane = tid & 31;
    const int wm = warp * 64;

    float acc[4][8][4];
#pragma unroll
    for (int i = 0; i < 4; i++)
#pragma unroll
        for (int j = 0; j < 8; j++)
#pragma unroll
            for (int q = 0; q < 4; q++) acc[i][j][q] = 0.f;

    const int a_r = lane & 15;
    const int a_c = (lane >> 4) << 4;
    const int b_r = (lane & 7) + ((lane >> 4) << 3);
    const int b_c = ((lane >> 3) & 1) << 4;

    for (int s = 0; s < NSTG; s++) {
        const int buf = s & 1;
        asm volatile("cp.async.wait_group 0;" ::: "memory");
        __syncthreads();
        if (s + 1 < NSTG) load_stage(sb, buf ^ 1, s + 1, Ag, Bg, tid);

        uint32_t ab = sb + buf * STG;
        uint32_t bb = ab + STG_A;

#pragma unroll
        for (int t = 0; t < 4; t++) {
            uint32_t br[4][4];
#pragma unroll
            for (int j = 0; j < 4; j++) {
                int row = j * 16 + b_r;
                ldm_x4(br[j], bb + sw128(row * 128 + t * 32 + b_c));
            }
            uint32_t ar[4][4];
#pragma unroll
            for (int i = 0; i < 4; i++) {
                int row = wm + i * 16 + a_r;
                ldm_x4(ar[i], ab + sw128(row * 128 + t * 32 + a_c));
            }
#pragma unroll
            for (int i = 0; i < 4; i++)
#pragma unroll
                for (int j = 0; j < 4; j++) {
                    mma16816(acc[i][2 * j + 0], ar[i], &br[j][0]);
                    mma16816(acc[i][2 * j + 1], ar[i], &br[j][2]);
                }
        }
    }

    const int r0 = lane >> 2;
    const int c0 = (lane & 3) * 2;
    const size_t grow = bm + wm + r0;
    const int gcol = (int)bn + c0;

    float2 bv[8];
#pragma unroll
    for (int j = 0; j < 8; j++)
        bv[j] = *(const float2*)(bias + gcol + j * 8);

#pragma unroll
    for (int i = 0; i < 4; i++) {
        OutT* cp0 = C + (grow + i * 16) * Nd + gcol;
        OutT* cp1 = cp0 + (size_t)8 * Nd;
#pragma unroll
        for (int j = 0; j < 8; j++) {
            store2(cp0 + j * 8, acc[i][j][0] + bv[j].x, acc[i][j][1] + bv[j].y);
            store2(cp1 + j * 8, acc[i][j][2] + bv[j].x, acc[i][j][3] + bv[j].y);
        }
    }
}

/* ---------------- tensor-core attention + fused depthwise conv ------------- */
/* One CTA per (b,h).  qkv fp16: K,V copy-through to SW128 smem.             */
/* QK^T 1-term, PV 1-term (fp16 P).  Odd CTAs reverse the warp->strip map    */
/* so the {4,3,3,3} strip counts balance across SMSPs of co-resident CTAs.   */
#define NPAD 208
#define ACHB (NPAD * 128)           /* 26624 */
#define WS_OFF (2 * ACHB)
#define BS_OFF (WS_OFF + 2304)
#define ASMEM (BS_OFF + 256)        /* 55812 */

__global__ __launch_bounds__(128, 2) void attn_mma(const __half* __restrict__ qkv,
                                                   const float* __restrict__ dwc_w,
                                                   const float* __restrict__ dwc_b,
                                                   __half* __restrict__ atts)
{
    extern __shared__ __align__(1024) char smem[];
    uint32_t sbase = smem_u32(smem);
    const uint32_t Ksm = sbase, Vsm = sbase + ACHB;
    float2* ws2 = (float2*)(smem + WS_OFF);
    float2* bs2 = (float2*)(smem + BS_OFF);
    const int b = blockIdx.x / HEADS, h = blockIdx.x % HEADS;
    const int tid = threadIdx.x;
    const __half* base = qkv + (size_t)b * NTOK * QKV_N + h * DH;

    for (int i = tid; i < 288; i += 128) {
        int pair = i / 9, tap = i % 9;
        int c = h * 64 + pair * 2;
        ws2[i] = make_float2(dwc_w[(size_t)c * 9 + tap], dwc_w[(size_t)(c + 1) * 9 + tap]);
    }
    if (tid < 32) bs2[tid] = make_float2(dwc_b[h * 64 + tid * 2], dwc_b[h * 64 + tid * 2 + 1]);

    /* stage K,V (copy-through fp16; rows >= NTOK zeroed) */
    for (int idx = tid; idx < NPAD * 32; idx += 128) {
        int j = idx >> 5, dp = idx & 31;
        uint32_t kw = 0u, vw = 0u;
        if (j < NTOK) {
            const __half* p = base + (size_t)j * QKV_N + dp * 2;
            kw = *(const uint32_t*)(p + CDIM);
            vw = *(const uint32_t*)(p + 2 * CDIM);
        }
        uint32_t off = sw128((uint32_t)(j * 128 + dp * 4));
        asm volatile("st.shared.b32 [%0], %1;" :: "r"(Ksm + off), "r"(kw) : "memory");
        asm volatile("st.shared.b32 [%0], %1;" :: "r"(Vsm + off), "r"(vw) : "memory");
    }
    __syncthreads();

    const int lane = tid & 31, warp = tid >> 5;
    const int wst = (blockIdx.x & 1) ? (3 - warp) : warp;   /* SMSP balance */
    const int qr = lane >> 2;
    const int qc = (lane & 3) * 2;
    const int b_r = (lane & 7) + ((lane >> 4) << 3);
    const int b_c = ((lane >> 3) & 1) << 4;
    const int a_r = lane & 15;
    const int a_c = (lane >> 4) << 4;

    for (int s = wst; s < 13; s += 4) {
        const int m0 = s * 16 + qr;
        const int m1 = m0 + 8;
        const int rm0 = m0 < NTOK ? m0 : NTOK - 1;
        const int rm1 = m1 < NTOK ? m1 : NTOK - 1;

        /* Q fragments straight from fp16 global */
        uint32_t qh[4][4];
        const __half* q0 = base + (size_t)rm0 * QKV_N;
        const __half* q1 = base + (size_t)rm1 * QKV_N;
#pragma unroll
        for (int kt = 0; kt < 4; kt++) {
            int c = kt * 16 + qc;
            qh[kt][0] = *(const uint32_t*)(q0 + c);
            qh[kt][1] = *(const uint32_t*)(q1 + c);
            qh[kt][2] = *(const uint32_t*)(q0 + c + 8);
            qh[kt][3] = *(const uint32_t*)(q1 + c + 8);
        }

        float S[26][4];
#pragma unroll
        for (int t = 0; t < 26; t++)
#pragma unroll
            for (int q = 0; q < 4; q++) S[t][q] = 0.f;

#pragma unroll
        for (int nc = 0; nc < 13; nc++) {
#pragma unroll
            for (int kt = 0; kt < 4; kt++) {
                uint32_t kb[4];
                ldm_x4(kb, Ksm + sw128((uint32_t)((nc * 16 + b_r) * 128 + kt * 32 + b_c)));
                mma16816(S[2 * nc],     qh[kt], &kb[0]);
                mma16816(S[2 * nc + 1], qh[kt], &kb[2]);
            }
        }

#pragma unroll
        for (int t = 24; t < 26; t++) {
            int j0 = t * 8 + qc;
            if (j0 >= NTOK)     S[t][0] = S[t][2] = -1e30f;
            if (j0 + 1 >= NTOK) S[t][1] = S[t][3] = -1e30f;
        }

        float mx0 = -1e30f, mx1 = -1e30f;
#pragma unroll
        for (int t = 0; t < 26; t++) {
            mx0 = fmaxf(mx0, fmaxf(S[t][0], S[t][1]));
            mx1 = fmaxf(mx1, fmaxf(S[t][2], S[t][3]));
        }
        mx0 = fmaxf(mx0, __shfl_xor_sync(0xffffffffu, mx0, 1));
        mx0 = fmaxf(mx0, __shfl_xor_sync(0xffffffffu, mx0, 2));
        mx1 = fmaxf(mx1, __shfl_xor_sync(0xffffffffu, mx1, 1));
        mx1 = fmaxf(mx1, __shfl_xor_sync(0xffffffffu, mx1, 2));
        float sum0 = 0.f, sum1 = 0.f;
#pragma unroll
        for (int t = 0; t < 26; t++) {
            S[t][0] = __expf((S[t][0] - mx0) * 0.125f);
            S[t][1] = __expf((S[t][1] - mx0) * 0.125f);
            S[t][2] = __expf((S[t][2] - mx1) * 0.125f);
            S[t][3] = __expf((S[t][3] - mx1) * 0.125f);
            sum0 += S[t][0] + S[t][1];
            sum1 += S[t][2] + S[t][3];
        }
        sum0 += __shfl_xor_sync(0xffffffffu, sum0, 1);
        sum0 += __shfl_xor_sync(0xffffffffu, sum0, 2);
        sum1 += __shfl_xor_sync(0xffffffffu, sum1, 1);
        sum1 += __shfl_xor_sync(0xffffffffu, sum1, 2);
        float inv0 = __frcp_rn(sum0), inv1 = __frcp_rn(sum1);

        float O[8][4];
#pragma unroll
        for (int t = 0; t < 8; t++)
#pragma unroll
            for (int q = 0; q < 4; q++) O[t][q] = 0.f;

#pragma unroll
        for (int jt = 0; jt < 13; jt++) {
            uint32_t ph[4];
            ph[0] = pack2h(S[2 * jt][0],     S[2 * jt][1]);
            ph[1] = pack2h(S[2 * jt][2],     S[2 * jt][3]);
            ph[2] = pack2h(S[2 * jt + 1][0], S[2 * jt + 1][1]);
            ph[3] = pack2h(S[2 * jt + 1][2], S[2 * jt + 1][3]);
#pragma unroll
            for (int dc = 0; dc < 4; dc++) {
                uint32_t vb[4];
                uint32_t rb = (uint32_t)((jt * 16 + a_r) * 128 + dc * 32 + a_c);
                ldm_x4t(vb, Vsm + sw128(rb));
                mma16816(O[2 * dc],     ph, &vb[0]);
                mma16816(O[2 * dc + 1], ph, &vb[2]);
            }
        }

        /* write rows with fused conv (plain fp16 atts) */
#pragma unroll
        for (int rsel = 0; rsel < 2; rsel++) {
            const int m = rsel ? m1 : m0;
            if (m >= NTOK) continue;
            const float inv = rsel ? inv1 : inv0;
            const int qs = rsel * 2;
            const bool doconv = (m >= 1);
            int y = 0, x = 0;
            if (doconv) { y = (m - 1) / GRID14; x = (m - 1) % GRID14; }
            __half* rp = atts + (size_t)(b * NTOK + m) * KTOT + h * DH;
#pragma unroll
            for (int t = 0; t < 8; t++) {
                float v0 = O[t][qs] * inv;
                float v1 = O[t][qs + 1] * inv;
                const int d0 = (t >> 1) * 16 + (t & 1) * 8 + qc;
                if (doconv) {
                    float2 cv = bs2[d0 >> 1];
                    const float2* wp = ws2 + (d0 >> 1) * 9;
#pragma unroll
                    for (int ky = 0; ky < 3; ky++) {
                        int yy = y + ky - 1;
                        if (yy < 0 || yy >= GRID14) continue;
#pragma unroll
                        for (int kx = 0; kx < 3; kx++) {
                            int xx = x + kx - 1;
                            if (xx < 0 || xx >= GRID14) continue;
                            int j = 1 + yy * GRID14 + xx;
                            uint32_t off = sw128((uint32_t)(j * 128 + d0 * 2));
                            uint32_t vh;
                            asm("ld.shared.b32 %0,[%1];" : "=r"(vh) : "r"(Vsm + off));
                            __half2 h2 = *reinterpret_cast<__half2*>(&vh);
                            float2 wv = wp[ky * 3 + kx];
                            cv.x = fmaf(__half2float(h2.x), wv.x, cv.x);
                            cv.y = fmaf(__half2float(h2.y), wv.y, cv.y);
                        }
                    }
                    v0 += cv.x;
                    v1 += cv.y;
                }
                *(uint32_t*)(rp + d0) = pack2h(v0, v1);
            }
        }
    }
}

/* ---------------- launch --------------------------------------------------- */
extern "C" void kernel_launch(void* const* d_in, const int* in_sizes, int n_in,
                              void* d_out, int out_size)
{
    const float* x      = (const float*)d_in[0];
    const float* W_qkv  = (const float*)d_in[1];
    const float* b_qkv  = (const float*)d_in[2];
    const float* W_proj = (const float*)d_in[3];
    const float* b_proj = (const float*)d_in[4];
    const float* dwc_w  = (const float*)d_in[5];
    const float* dwc_b  = (const float*)d_in[6];
    float* out = (float*)d_out;

    __half *qkv = nullptr, *xs = nullptr, *atts = nullptr, *wqkvs = nullptr, *wprojs = nullptr;
    cudaGetSymbolAddress((void**)&qkv, g_qkv);
    cudaGetSymbolAddress((void**)&xs, g_xs);
    cudaGetSymbolAddress((void**)&atts, g_atts);
    cudaGetSymbolAddress((void**)&wqkvs, g_wqkvs);
    cudaGetSymbolAddress((void**)&wprojs, g_wprojs);

    cudaFuncSetAttribute(attn_mma, cudaFuncAttributeMaxDynamicSharedMemorySize, ASMEM);
    cudaFuncSetAttribute(gemm_mma<__half>, cudaFuncAttributeMaxDynamicSharedMemorySize, GSMEM);
    cudaFuncSetAttribute(gemm_mma<float>, cudaFuncAttributeMaxDynamicSharedMemorySize, GSMEM);

    xpack<<<(M_ROWS * KTOT) / 256, 256>>>(x, xs, M_ROWS * KTOT);
    wpack<<<dim3(QKV_N / 32, KTOT / 32), 256>>>(W_qkv, wqkvs, QKV_N);
    wpack<<<dim3(CDIM / 32, KTOT / 32), 256>>>(W_proj, wprojs, CDIM);

    /* 1) qkv = x @ W_qkv + b_qkv  (fp16 output) */
    gemm_mma<__half><<<dim3(QKV_N / TN, M_ROWS / TM), 64, GSMEM>>>(xs, wqkvs, b_qkv, qkv, QKV_N);

    /* 2) attention + fused depthwise conv -> atts (fp16) */
    attn_mma<<<BATCH * HEADS, 128, ASMEM>>>(qkv, dwc_w, dwc_b, atts);

    /* 3) out = (attn+conv) @ W_proj + b_proj  (fp32 output) */
    gemm_mma<float><<<dim3(CDIM / TN, M_ROWS / TM), 64, GSMEM>>>(atts, wprojs, b_proj, out, CDIM);
}

// round 14
// speedup vs baseline: 6.9033x; 1.0144x over previous
#include <cuda_runtime.h>
#include <cuda_fp16.h>
#include <cstdint>
#include <math.h>

#define BATCH 256
#define NTOK 197
#define CDIM 768
#define HEADS 12
#define DH 64
#define GRID14 14
#define M_ROWS (BATCH * NTOK)   /* 50432 = 394*128 */
#define QKV_N (3 * CDIM)        /* 2304 */
#define KTOT 768
#define ROWB (KTOT * 2)         /* 1536 bytes per fp16 row */

/* ---------------- scratch (__device__ globals; no allocs allowed) -------- */
__device__ __half g_qkv[(size_t)M_ROWS * QKV_N];     /* qkv fp16          */
__device__ __half g_xs[(size_t)M_ROWS * KTOT];       /* x fp16            */
__device__ __half g_atts[(size_t)M_ROWS * KTOT];     /* attn+conv fp16    */
__device__ __half g_wqkvs[(size_t)QKV_N * KTOT];     /* W_qkv^T fp16      */
__device__ __half g_wprojs[(size_t)CDIM * KTOT];     /* W_proj^T fp16     */

/* ---------------- helpers ------------------------------------------------- */
__device__ __forceinline__ uint32_t smem_u32(const void* p) {
    uint32_t a;
    asm("{ .reg .u64 t; cvta.to.shared.u64 t, %1; cvt.u32.u64 %0, t; }" : "=r"(a) : "l"(p));
    return a;
}
__device__ __forceinline__ uint32_t sw128(uint32_t o) { return o ^ ((o >> 3) & 0x70); }

__device__ __forceinline__ void cp16(uint32_t s, const void* g) {
    asm volatile("cp.async.cg.shared.global [%0], [%1], 16;" :: "r"(s), "l"(g));
}
__device__ __forceinline__ void ldm_x4(uint32_t* r, uint32_t a) {
    asm volatile("ldmatrix.sync.aligned.m8n8.x4.shared.b16 {%0,%1,%2,%3}, [%4];"
                 : "=r"(r[0]), "=r"(r[1]), "=r"(r[2]), "=r"(r[3]) : "r"(a));
}
__device__ __forceinline__ void ldm_x4t(uint32_t* r, uint32_t a) {
    asm volatile("ldmatrix.sync.aligned.m8n8.x4.trans.shared.b16 {%0,%1,%2,%3}, [%4];"
                 : "=r"(r[0]), "=r"(r[1]), "=r"(r[2]), "=r"(r[3]) : "r"(a));
}
__device__ __forceinline__ void mma16816(float* c, const uint32_t* a, const uint32_t* b) {
    asm volatile(
        "mma.sync.aligned.m16n8k16.row.col.f32.f16.f16.f32 "
        "{%0,%1,%2,%3}, {%4,%5,%6,%7}, {%8,%9}, {%0,%1,%2,%3};"
        : "+f"(c[0]), "+f"(c[1]), "+f"(c[2]), "+f"(c[3])
        : "r"(a[0]), "r"(a[1]), "r"(a[2]), "r"(a[3]), "r"(b[0]), "r"(b[1]));
}
__device__ __forceinline__ uint32_t pack2h(float x, float y) {
    __half2 h = __floats2half2_rn(x, y);
    return *reinterpret_cast<uint32_t*>(&h);
}
/* output-type-dispatched pair store */
__device__ __forceinline__ void store2(float* p, float a, float b) {
    *(float2*)p = make_float2(a, b);
}
__device__ __forceinline__ void store2(__half* p, float a, float b) {
    *(uint32_t*)p = pack2h(a, b);
}

/* ---------------- prep kernels -------------------------------------------- */
__global__ __launch_bounds__(256) void xpack(const float* __restrict__ in,
                                             __half* __restrict__ out, int total)
{
    int idx = blockIdx.x * 256 + threadIdx.x;
    if (idx >= total) return;
    out[idx] = __float2half_rn(in[idx]);
}

/* W [768, N] fp32 -> out [N, 768] fp16: 32x32 tiled transpose, coalesced */
__global__ __launch_bounds__(256) void wpack(const float* __restrict__ W,
                                             __half* __restrict__ out, int N)
{
    __shared__ __half tile[32][33];
    const int n0 = blockIdx.x * 32;
    const int k0 = blockIdx.y * 32;
    const int tx = threadIdx.x & 31;
    const int ty = threadIdx.x >> 5;   /* 0..7 */
#pragma unroll
    for (int i = ty; i < 32; i += 8)
        tile[tx][i] = __float2half_rn(W[(size_t)(k0 + i) * N + n0 + tx]);
    __syncthreads();
#pragma unroll
    for (int i = ty; i < 32; i += 8)
        out[(size_t)(n0 + i) * KTOT + k0 + tx] = tile[i][tx];
}

/* ---------------- fp16 GEMM: 128x64 tile, 2 warps, 4 CTAs/SM -------------- */
#define TM 128
#define TN 64
#define NSTG 12                   /* 768 / 64 */
#define RING 2
#define STG_A 16384               /* 128 rows * 128B */
#define STG_B 8192                /* 64 rows * 128B  */
#define STG (STG_A + STG_B)       /* 24576 */
#define GSMEM (RING * STG)        /* 49152 -> 4 CTAs/SM */

__device__ __forceinline__ void load_stage(uint32_t sb, int buf, int st,
                                           const char* Ag, const char* Bg, int tid)
{
    uint32_t ab = sb + buf * STG;
    const char* a0 = Ag + (size_t)st * 128;
#pragma unroll
    for (int c = tid; c < 1024; c += 64) {
        int r = c >> 3, j = c & 7;
        cp16(ab + sw128(r * 128 + j * 16), a0 + (size_t)r * ROWB + j * 16);
    }
    uint32_t bb = ab + STG_A;
    const char* b0 = Bg + (size_t)st * 128;
#pragma unroll
    for (int c = tid; c < 512; c += 64) {
        int r = c >> 3, j = c & 7;
        cp16(bb + sw128(r * 128 + j * 16), b0 + (size_t)r * ROWB + j * 16);
    }
    asm volatile("cp.async.commit_group;" ::: "memory");
}

template <typename OutT>
__global__ __launch_bounds__(64, 4) void gemm_mma(
    const __half* __restrict__ As, const __half* __restrict__ Bs,
    const float* __restrict__ bias, OutT* __restrict__ C, int Nd)
{
    extern __shared__ __align__(1024) char smc[];
    uint32_t sb = smem_u32(smc);
    const int tid = threadIdx.x;
    const size_t bm = (size_t)blockIdx.y * TM;
    const size_t bn = (size_t)blockIdx.x * TN;
    const char* Ag = (const char*)As + bm * ROWB;
    const char* Bg = (const char*)Bs + bn * ROWB;

    load_stage(sb, 0, 0, Ag, Bg, tid);

    const int warp = tid >> 5, lane = tid & 31;
    const int wm = warp * 64;

    float acc[4][8][4];
#pragma unroll
    for (int i = 0; i < 4; i++)
#pragma unroll
        for (int j = 0; j < 8; j++)
#pragma unroll
            for (int q = 0; q < 4; q++) acc[i][j][q] = 0.f;

    const int a_r = lane & 15;
    const int a_c = (lane >> 4) << 4;
    const int b_r = (lane & 7) + ((lane >> 4) << 3);
    const int b_c = ((lane >> 3) & 1) << 4;

    for (int s = 0; s < NSTG; s++) {
        const int buf = s & 1;
        asm volatile("cp.async.wait_group 0;" ::: "memory");
        __syncthreads();
        if (s + 1 < NSTG) load_stage(sb, buf ^ 1, s + 1, Ag, Bg, tid);

        uint32_t ab = sb + buf * STG;
        uint32_t bb = ab + STG_A;

#pragma unroll
        for (int t = 0; t < 4; t++) {
            uint32_t br[4][4];
#pragma unroll
            for (int j = 0; j < 4; j++) {
                int row = j * 16 + b_r;
                ldm_x4(br[j], bb + sw128(row * 128 + t * 32 + b_c));
            }
            uint32_t ar[4][4];
#pragma unroll
            for (int i = 0; i < 4; i++) {
                int row = wm + i * 16 + a_r;
                ldm_x4(ar[i], ab + sw128(row * 128 + t * 32 + a_c));
            }
#pragma unroll
            for (int i = 0; i < 4; i++)
#pragma unroll
                for (int j = 0; j < 4; j++) {
                    mma16816(acc[i][2 * j + 0], ar[i], &br[j][0]);
                    mma16816(acc[i][2 * j + 1], ar[i], &br[j][2]);
                }
        }
    }

    const int r0 = lane >> 2;
    const int c0 = (lane & 3) * 2;
    const size_t grow = bm + wm + r0;
    const int gcol = (int)bn + c0;

    float2 bv[8];
#pragma unroll
    for (int j = 0; j < 8; j++)
        bv[j] = *(const float2*)(bias + gcol + j * 8);

#pragma unroll
    for (int i = 0; i < 4; i++) {
        OutT* cp0 = C + (grow + i * 16) * Nd + gcol;
        OutT* cp1 = cp0 + (size_t)8 * Nd;
#pragma unroll
        for (int j = 0; j < 8; j++) {
            store2(cp0 + j * 8, acc[i][j][0] + bv[j].x, acc[i][j][1] + bv[j].y);
            store2(cp1 + j * 8, acc[i][j][2] + bv[j].x, acc[i][j][3] + bv[j].y);
        }
    }
}

/* ---------------- tensor-core attention + precomputed depthwise conv ------- */
/* One CTA per (b,h).  qkv fp16: K,V copy-through to SW128 smem.             */
/* QK^T 1-term, PV 1-term.  Conv computed ONCE per CTA (conflict-free pass)  */
/* into Csm[197 rows x 136B]; epilogue just adds one LDS per 8-col group.    */
#define NPAD 208
#define ACHB (NPAD * 128)           /* 26624 */
#define WS_OFF (2 * ACHB)           /* 53248: 288 float2 conv weights */
#define BS_OFF (WS_OFF + 2304)      /* 55552: 32 float2 conv bias     */
#define CV_OFF (BS_OFF + 256)       /* 55808: conv results            */
#define CVSTRIDE 136                /* bytes per conv row (64 halves + pad) */
#define ASMEM (CV_OFF + NTOK * CVSTRIDE)  /* 82600 -> 2 CTAs/SM */

__global__ __launch_bounds__(128, 2) void attn_mma(const __half* __restrict__ qkv,
                                                   const float* __restrict__ dwc_w,
                                                   const float* __restrict__ dwc_b,
                                                   __half* __restrict__ atts)
{
    extern __shared__ __align__(1024) char smem[];
    uint32_t sbase = smem_u32(smem);
    const uint32_t Ksm = sbase, Vsm = sbase + ACHB, Cv = sbase + CV_OFF;
    float2* ws2 = (float2*)(smem + WS_OFF);
    float2* bs2 = (float2*)(smem + BS_OFF);
    const int b = blockIdx.x / HEADS, h = blockIdx.x % HEADS;
    const int tid = threadIdx.x;
    const __half* base = qkv + (size_t)b * NTOK * QKV_N + h * DH;

    for (int i = tid; i < 288; i += 128) {
        int pair = i / 9, tap = i % 9;
        int c = h * 64 + pair * 2;
        ws2[i] = make_float2(dwc_w[(size_t)c * 9 + tap], dwc_w[(size_t)(c + 1) * 9 + tap]);
    }
    if (tid < 32) bs2[tid] = make_float2(dwc_b[h * 64 + tid * 2], dwc_b[h * 64 + tid * 2 + 1]);

    /* stage K,V (copy-through fp16; rows >= NTOK zeroed) */
    for (int idx = tid; idx < NPAD * 32; idx += 128) {
        int j = idx >> 5, dp = idx & 31;
        uint32_t kw = 0u, vw = 0u;
        if (j < NTOK) {
            const __half* p = base + (size_t)j * QKV_N + dp * 2;
            kw = *(const uint32_t*)(p + CDIM);
            vw = *(const uint32_t*)(p + 2 * CDIM);
        }
        uint32_t off = sw128((uint32_t)(j * 128 + dp * 4));
        asm volatile("st.shared.b32 [%0], %1;" :: "r"(Ksm + off), "r"(kw) : "memory");
        asm volatile("st.shared.b32 [%0], %1;" :: "r"(Vsm + off), "r"(vw) : "memory");
    }
    __syncthreads();

    /* cooperative conv pass: conflict-free (consecutive lanes -> consecutive
       channel pairs within one V row), one result row per token m=1..196 */
    for (int idx = tid; idx < 196 * 32; idx += 128) {
        int m = 1 + (idx >> 5);
        int dp = idx & 31;
        int y = (m - 1) / GRID14, x = (m - 1) % GRID14;
        float2 cv = bs2[dp];
        const float2* wp = ws2 + dp * 9;
#pragma unroll
        for (int ky = 0; ky < 3; ky++) {
            int yy = y + ky - 1;
            if (yy < 0 || yy >= GRID14) continue;
#pragma unroll
            for (int kx = 0; kx < 3; kx++) {
                int xx = x + kx - 1;
                if (xx < 0 || xx >= GRID14) continue;
                int j = 1 + yy * GRID14 + xx;
                uint32_t vh;
                asm("ld.shared.b32 %0,[%1];" : "=r"(vh)
                    : "r"(Vsm + sw128((uint32_t)(j * 128 + dp * 4))));
                __half2 h2 = *reinterpret_cast<__half2*>(&vh);
                float2 wv = wp[ky * 3 + kx];
                cv.x = fmaf(__half2float(h2.x), wv.x, cv.x);
                cv.y = fmaf(__half2float(h2.y), wv.y, cv.y);
            }
        }
        uint32_t cw = pack2h(cv.x, cv.y);
        asm volatile("st.shared.b32 [%0], %1;"
                     :: "r"(Cv + (uint32_t)(m * CVSTRIDE + dp * 4)), "r"(cw) : "memory");
    }
    __syncthreads();

    const int lane = tid & 31, warp = tid >> 5;
    const int wst = (blockIdx.x & 1) ? (3 - warp) : warp;   /* SMSP balance */
    const int qr = lane >> 2;
    const int qc = (lane & 3) * 2;
    const int b_r = (lane & 7) + ((lane >> 4) << 3);
    const int b_c = ((lane >> 3) & 1) << 4;
    const int a_r = lane & 15;
    const int a_c = (lane >> 4) << 4;

    for (int s = wst; s < 13; s += 4) {
        const int m0 = s * 16 + qr;
        const int m1 = m0 + 8;
        const int rm0 = m0 < NTOK ? m0 : NTOK - 1;
        const int rm1 = m1 < NTOK ? m1 : NTOK - 1;

        /* Q fragments straight from fp16 global */
        uint32_t qh[4][4];
        const __half* q0 = base + (size_t)rm0 * QKV_N;
        const __half* q1 = base + (size_t)rm1 * QKV_N;
#pragma unroll
        for (int kt = 0; kt < 4; kt++) {
            int c = kt * 16 + qc;
            qh[kt][0] = *(const uint32_t*)(q0 + c);
            qh[kt][1] = *(const uint32_t*)(q1 + c);
            qh[kt][2] = *(const uint32_t*)(q0 + c + 8);
            qh[kt][3] = *(const uint32_t*)(q1 + c + 8);
        }

        float S[26][4];
#pragma unroll
        for (int t = 0; t < 26; t++)
#pragma unroll
            for (int q = 0; q < 4; q++) S[t][q] = 0.f;

#pragma unroll
        for (int nc = 0; nc < 13; nc++) {
#pragma unroll
            for (int kt = 0; kt < 4; kt++) {
                uint32_t kb[4];
                ldm_x4(kb, Ksm + sw128((uint32_t)((nc * 16 + b_r) * 128 + kt * 32 + b_c)));
                mma16816(S[2 * nc],     qh[kt], &kb[0]);
                mma16816(S[2 * nc + 1], qh[kt], &kb[2]);
            }
        }

#pragma unroll
        for (int t = 24; t < 26; t++) {
            int j0 = t * 8 + qc;
            if (j0 >= NTOK)     S[t][0] = S[t][2] = -1e30f;
            if (j0 + 1 >= NTOK) S[t][1] = S[t][3] = -1e30f;
        }

        float mx0 = -1e30f, mx1 = -1e30f;
#pragma unroll
        for (int t = 0; t < 26; t++) {
            mx0 = fmaxf(mx0, fmaxf(S[t][0], S[t][1]));
            mx1 = fmaxf(mx1, fmaxf(S[t][2], S[t][3]));
        }
        mx0 = fmaxf(mx0, __shfl_xor_sync(0xffffffffu, mx0, 1));
        mx0 = fmaxf(mx0, __shfl_xor_sync(0xffffffffu, mx0, 2));
        mx1 = fmaxf(mx1, __shfl_xor_sync(0xffffffffu, mx1, 1));
        mx1 = fmaxf(mx1, __shfl_xor_sync(0xffffffffu, mx1, 2));
        float sum0 = 0.f, sum1 = 0.f;
#pragma unroll
        for (int t = 0; t < 26; t++) {
            S[t][0] = __expf((S[t][0] - mx0) * 0.125f);
            S[t][1] = __expf((S[t][1] - mx0) * 0.125f);
            S[t][2] = __expf((S[t][2] - mx1) * 0.125f);
            S[t][3] = __expf((S[t][3] - mx1) * 0.125f);
            sum0 += S[t][0] + S[t][1];
            sum1 += S[t][2] + S[t][3];
        }
        sum0 += __shfl_xor_sync(0xffffffffu, sum0, 1);
        sum0 += __shfl_xor_sync(0xffffffffu, sum0, 2);
        sum1 += __shfl_xor_sync(0xffffffffu, sum1, 1);
        sum1 += __shfl_xor_sync(0xffffffffu, sum1, 2);
        float inv0 = __frcp_rn(sum0), inv1 = __frcp_rn(sum1);

        float O[8][4];
#pragma unroll
        for (int t = 0; t < 8; t++)
#pragma unroll
            for (int q = 0; q < 4; q++) O[t][q] = 0.f;

#pragma unroll
        for (int jt = 0; jt < 13; jt++) {
            uint32_t ph[4];
            ph[0] = pack2h(S[2 * jt][0],     S[2 * jt][1]);
            ph[1] = pack2h(S[2 * jt][2],     S[2 * jt][3]);
            ph[2] = pack2h(S[2 * jt + 1][0], S[2 * jt + 1][1]);
            ph[3] = pack2h(S[2 * jt + 1][2], S[2 * jt + 1][3]);
#pragma unroll
            for (int dc = 0; dc < 4; dc++) {
                uint32_t vb[4];
                uint32_t rb = (uint32_t)((jt * 16 + a_r) * 128 + dc * 32 + a_c);
                ldm_x4t(vb, Vsm + sw128(rb));
                mma16816(O[2 * dc],     ph, &vb[0]);
                mma16816(O[2 * dc + 1], ph, &vb[2]);
            }
        }

        /* write rows; conv term is one smem load per 8-col group */
#pragma unroll
        for (int rsel = 0; rsel < 2; rsel++) {
            const int m = rsel ? m1 : m0;
            if (m >= NTOK) continue;
            const float inv = rsel ? inv1 : inv0;
            const int qs = rsel * 2;
            const bool doconv = (m >= 1);
            __half* rp = atts + (size_t)(b * NTOK + m) * KTOT + h * DH;
#pragma unroll
            for (int t = 0; t < 8; t++) {
                float v0 = O[t][qs] * inv;
                float v1 = O[t][qs + 1] * inv;
                const int d0 = (t >> 1) * 16 + (t & 1) * 8 + qc;
                if (doconv) {
                    uint32_t cw;
                    asm("ld.shared.b32 %0,[%1];" : "=r"(cw)
                        : "r"(Cv + (uint32_t)(m * CVSTRIDE + d0 * 2)));
                    __half2 c2 = *reinterpret_cast<__half2*>(&cw);
                    v0 += __half2float(c2.x);
                    v1 += __half2float(c2.y);
                }
                *(uint32_t*)(rp + d0) = pack2h(v0, v1);
            }
        }
    }
}

/* ---------------- launch --------------------------------------------------- */
extern "C" void kernel_launch(void* const* d_in, const int* in_sizes, int n_in,
                              void* d_out, int out_size)
{
    const float* x      = (const float*)d_in[0];
    const float* W_qkv  = (const float*)d_in[1];
    const float* b_qkv  = (const float*)d_in[2];
    const float* W_proj = (const float*)d_in[3];
    const float* b_proj = (const float*)d_in[4];
    const float* dwc_w  = (const float*)d_in[5];
    const float* dwc_b  = (const float*)d_in[6];
    float* out = (float*)d_out;

    __half *qkv = nullptr, *xs = nullptr, *atts = nullptr, *wqkvs = nullptr, *wprojs = nullptr;
    cudaGetSymbolAddress((void**)&qkv, g_qkv);
    cudaGetSymbolAddress((void**)&xs, g_xs);
    cudaGetSymbolAddress((void**)&atts, g_atts);
    cudaGetSymbolAddress((void**)&wqkvs, g_wqkvs);
    cudaGetSymbolAddress((void**)&wprojs, g_wprojs);

    cudaFuncSetAttribute(attn_mma, cudaFuncAttributeMaxDynamicSharedMemorySize, ASMEM);
    cudaFuncSetAttribute(gemm_mma<__half>, cudaFuncAttributeMaxDynamicSharedMemorySize, GSMEM);
    cudaFuncSetAttribute(gemm_mma<float>, cudaFuncAttributeMaxDynamicSharedMemorySize, GSMEM);

    xpack<<<(M_ROWS * KTOT) / 256, 256>>>(x, xs, M_ROWS * KTOT);
    wpack<<<dim3(QKV_N / 32, KTOT / 32), 256>>>(W_qkv, wqkvs, QKV_N);
    wpack<<<dim3(CDIM / 32, KTOT / 32), 256>>>(W_proj, wprojs, CDIM);

    /* 1) qkv = x @ W_qkv + b_qkv  (fp16 output) */
    gemm_mma<__half><<<dim3(QKV_N / TN, M_ROWS / TM), 64, GSMEM>>>(xs, wqkvs, b_qkv, qkv, QKV_N);

    /* 2) attention + precomputed depthwise conv -> atts (fp16) */
    attn_mma<<<BATCH * HEADS, 128, ASMEM>>>(qkv, dwc_w, dwc_b, atts);

    /* 3) out = (attn+conv) @ W_proj + b_proj  (fp32 output) */
    gemm_mma<float><<<dim3(CDIM / TN, M_ROWS / TM), 64, GSMEM>>>(atts, wprojs, b_proj, out, CDIM);
}